// round 1
// baseline (speedup 1.0000x reference)
#include <cuda_runtime.h>

#define BATCH 2
#define SEQ   1024
#define HID   1024
#define NHEAD 16
#define HDIM  64
#define BH    (BATCH*NHEAD)      // 32
#define VOCAB 129                // 2*64+1

// ---------------- scratch (device globals; no allocation allowed) ----------------
__device__ __align__(16) float g_qkv[3 * BH * SEQ * HDIM];       // Q,K,V in [bh][s][d]
__device__ __align__(16) float g_scores[(size_t)BH * SEQ * SEQ]; // 128 MB, probs in-place
__device__ __align__(16) float g_qrel[(size_t)BH * SEQ * VOCAB]; // q . tab[r]
__device__ __align__(16) float g_ps[(size_t)BH * SEQ * VOCAB];   // bucketed probs
__device__ __align__(16) float g_tab[VOCAB * HDIM];              // sinusoid table

// ---------------- sinusoid table ----------------
__global__ void init_tab_kernel() {
    int idx = blockIdx.x * blockDim.x + threadIdx.x;   // pair index
    if (idx >= VOCAB * 32) return;
    int p = idx >> 5, i = idx & 31;
    float div = expf((float)(2 * i) * (-9.210340371976184f / 64.0f)); // -ln(10000)/64
    float ang = (float)p * div;
    g_tab[p * 64 + 2 * i]     = sinf(ang);
    g_tab[p * 64 + 2 * i + 1] = cosf(ang);
}

// ---------------- phase 1: QKV projection  C = hs @ W^T + b ----------------
// 128x128 tile, BK=8, 256 threads, 8x8 per-thread
__global__ __launch_bounds__(256) void qkv_kernel(
    const float* __restrict__ hs,
    const float* __restrict__ Wq, const float* __restrict__ bq,
    const float* __restrict__ Wk, const float* __restrict__ bk,
    const float* __restrict__ Wv, const float* __restrict__ bv)
{
    int z = blockIdx.z;
    const float* W    = (z == 0) ? Wq : (z == 1 ? Wk : Wv);
    const float* bias = (z == 0) ? bq : (z == 1 ? bk : bv);
    float* outp = g_qkv + (size_t)z * BH * SEQ * HDIM;

    int m0 = blockIdx.y * 128, n0 = blockIdx.x * 128;
    __shared__ __align__(16) float As[8][128];
    __shared__ __align__(16) float Bs[8][128];

    int tid = threadIdx.x;
    int lr = tid >> 1, lc = (tid & 1) * 4;
    int tx = tid & 15, ty = tid >> 4;
    float acc[8][8] = {};

    for (int k0 = 0; k0 < HID; k0 += 8) {
        float4 a  = *(const float4*)(hs + (size_t)(m0 + lr) * HID + k0 + lc);
        float4 bb = *(const float4*)(W  + (size_t)(n0 + lr) * HID + k0 + lc);
        As[lc + 0][lr] = a.x;  As[lc + 1][lr] = a.y;  As[lc + 2][lr] = a.z;  As[lc + 3][lr] = a.w;
        Bs[lc + 0][lr] = bb.x; Bs[lc + 1][lr] = bb.y; Bs[lc + 2][lr] = bb.z; Bs[lc + 3][lr] = bb.w;
        __syncthreads();
        #pragma unroll
        for (int kk = 0; kk < 8; kk++) {
            float4 a0 = *(float4*)&As[kk][ty * 8];
            float4 a1 = *(float4*)&As[kk][ty * 8 + 4];
            float4 b0 = *(float4*)&Bs[kk][tx * 8];
            float4 b1 = *(float4*)&Bs[kk][tx * 8 + 4];
            float ra[8] = {a0.x, a0.y, a0.z, a0.w, a1.x, a1.y, a1.z, a1.w};
            float rb[8] = {b0.x, b0.y, b0.z, b0.w, b1.x, b1.y, b1.z, b1.w};
            #pragma unroll
            for (int i = 0; i < 8; i++)
                #pragma unroll
                for (int j = 0; j < 8; j++)
                    acc[i][j] += ra[i] * rb[j];
        }
        __syncthreads();
    }

    // epilogue: scatter to [b][h][s][d] head layout, bias added
    #pragma unroll
    for (int i = 0; i < 8; i++) {
        int m = m0 + ty * 8 + i;
        int b = m >> 10, s = m & 1023;
        int n = n0 + tx * 8;            // 8 consecutive n, never crosses a 64 boundary
        int h = n >> 6, d = n & 63;
        float v[8];
        #pragma unroll
        for (int j = 0; j < 8; j++) v[j] = acc[i][j] + bias[n + j];
        float* dst = outp + (((size_t)(b * NHEAD + h)) * SEQ + s) * HDIM + d;
        *(float4*)(dst)     = make_float4(v[0], v[1], v[2], v[3]);
        *(float4*)(dst + 4) = make_float4(v[4], v[5], v[6], v[7]);
    }
}

// ---------------- phase 1.5: qrel[row, r] = Q[row,:] . tab[r,:] ----------------
__global__ __launch_bounds__(128) void qrel_kernel() {
    int row = blockIdx.x;                           // bh*SEQ + q
    __shared__ float qrow[64];
    const float* Q = g_qkv + (size_t)row * HDIM;
    if (threadIdx.x < 64) qrow[threadIdx.x] = Q[threadIdx.x];
    __syncthreads();
    for (int r = threadIdx.x; r < VOCAB; r += 128) {
        float s = 0.0f;
        #pragma unroll
        for (int d = 0; d < 64; d++) s += qrow[d] * g_tab[r * 64 + d];
        g_qrel[(size_t)row * VOCAB + r] = s;
    }
}

// ---------------- phase 2: scores = (Q K^T + qrel)/8 + mask ----------------
__global__ __launch_bounds__(256) void scores_kernel(const float* __restrict__ mask) {
    int bh = blockIdx.z;
    const float* Q = g_qkv + (size_t)bh * SEQ * HDIM;
    const float* K = g_qkv + (size_t)BH * SEQ * HDIM + (size_t)bh * SEQ * HDIM;
    int m0 = blockIdx.y * 128, n0 = blockIdx.x * 128;

    __shared__ __align__(16) float As[8][128];
    __shared__ __align__(16) float Bs[8][128];
    int tid = threadIdx.x;
    int lr = tid >> 1, lc = (tid & 1) * 4;
    int tx = tid & 15, ty = tid >> 4;
    float acc[8][8] = {};

    for (int k0 = 0; k0 < HDIM; k0 += 8) {
        float4 a  = *(const float4*)(Q + (size_t)(m0 + lr) * HDIM + k0 + lc);
        float4 bb = *(const float4*)(K + (size_t)(n0 + lr) * HDIM + k0 + lc);
        As[lc + 0][lr] = a.x;  As[lc + 1][lr] = a.y;  As[lc + 2][lr] = a.z;  As[lc + 3][lr] = a.w;
        Bs[lc + 0][lr] = bb.x; Bs[lc + 1][lr] = bb.y; Bs[lc + 2][lr] = bb.z; Bs[lc + 3][lr] = bb.w;
        __syncthreads();
        #pragma unroll
        for (int kk = 0; kk < 8; kk++) {
            float4 a0 = *(float4*)&As[kk][ty * 8];
            float4 a1 = *(float4*)&As[kk][ty * 8 + 4];
            float4 b0 = *(float4*)&Bs[kk][tx * 8];
            float4 b1 = *(float4*)&Bs[kk][tx * 8 + 4];
            float ra[8] = {a0.x, a0.y, a0.z, a0.w, a1.x, a1.y, a1.z, a1.w};
            float rb[8] = {b0.x, b0.y, b0.z, b0.w, b1.x, b1.y, b1.z, b1.w};
            #pragma unroll
            for (int i = 0; i < 8; i++)
                #pragma unroll
                for (int j = 0; j < 8; j++)
                    acc[i][j] += ra[i] * rb[j];
        }
        __syncthreads();
    }

    int b = bh >> 4;
    #pragma unroll
    for (int i = 0; i < 8; i++) {
        int q = m0 + ty * 8 + i;
        const float* qr = g_qrel + ((size_t)bh * SEQ + q) * VOCAB;
        float v[8];
        #pragma unroll
        for (int j = 0; j < 8; j++) {
            int k = n0 + tx * 8 + j;
            int dist = k - q;
            dist = dist < -64 ? -64 : (dist > 64 ? 64 : dist);
            v[j] = (acc[i][j] + qr[dist + 64]) * 0.125f + mask[b * SEQ + k];
        }
        float* dst = g_scores + ((size_t)bh * SEQ + q) * SEQ + n0 + tx * 8;
        *(float4*)(dst)     = make_float4(v[0], v[1], v[2], v[3]);
        *(float4*)(dst + 4) = make_float4(v[4], v[5], v[6], v[7]);
    }
}

// ---------------- phase 3: row softmax (in place) + ps buckets ----------------
__global__ __launch_bounds__(256) void softmax_kernel() {
    int row = blockIdx.x;           // bh*SEQ + q
    int q = row & (SEQ - 1);
    float* x = g_scores + (size_t)row * SEQ;
    __shared__ float sm[SEQ];
    __shared__ float red[16];
    __shared__ float bc[4];
    int t = threadIdx.x;
    int lane = t & 31, warp = t >> 5;

    float v[4];
    float mx = -3.4e38f;
    #pragma unroll
    for (int u = 0; u < 4; u++) { v[u] = x[t + 256 * u]; mx = fmaxf(mx, v[u]); }
    #pragma unroll
    for (int o = 16; o > 0; o >>= 1) mx = fmaxf(mx, __shfl_xor_sync(0xffffffffu, mx, o));
    if (lane == 0) red[warp] = mx;
    __syncthreads();
    if (t == 0) { float m = red[0]; for (int w = 1; w < 8; w++) m = fmaxf(m, red[w]); bc[0] = m; }
    __syncthreads();
    mx = bc[0];

    float s = 0.0f;
    #pragma unroll
    for (int u = 0; u < 4; u++) { v[u] = expf(v[u] - mx); s += v[u]; }
    #pragma unroll
    for (int o = 16; o > 0; o >>= 1) s += __shfl_xor_sync(0xffffffffu, s, o);
    __syncthreads();   // red reuse
    if (lane == 0) red[warp] = s;
    __syncthreads();
    if (t == 0) { float m = 0; for (int w = 0; w < 8; w++) m += red[w]; bc[1] = m; }
    __syncthreads();
    float inv = 1.0f / bc[1];

    float lo = 0.0f, hi = 0.0f;
    #pragma unroll
    for (int u = 0; u < 4; u++) {
        int k = t + 256 * u;
        float p = v[u] * inv;
        sm[k] = p; x[k] = p;
        if (k <= q - 64) lo += p;          // dist clamps to -64 -> bucket 0
        if (k >= q + 64) hi += p;          // dist clamps to +64 -> bucket 128
    }
    #pragma unroll
    for (int o = 16; o > 0; o >>= 1) {
        lo += __shfl_xor_sync(0xffffffffu, lo, o);
        hi += __shfl_xor_sync(0xffffffffu, hi, o);
    }
    __syncthreads();   // red reuse
    if (lane == 0) { red[warp] = lo; red[warp + 8] = hi; }
    __syncthreads();
    if (t == 0) {
        float a = 0, b2 = 0;
        for (int w = 0; w < 8; w++) { a += red[w]; b2 += red[w + 8]; }
        bc[2] = a; bc[3] = b2;
    }
    __syncthreads();

    float* psr = g_ps + (size_t)row * VOCAB;
    if (t == 0)   psr[0]   = bc[2];
    if (t == 128) psr[128] = bc[3];
    if (t >= 1 && t < 128) {
        int k = q + t - 64;
        psr[t] = (k >= 0 && k < SEQ) ? sm[k] : 0.0f;
    }
}

// ---------------- phase 4: ctx = P @ V + ps @ tab, write [b,s,h*64+d] ----------------
// 128x64 tile, BK=16, 256 threads, 8x4 per-thread
__global__ __launch_bounds__(256) void ctx_kernel(float* __restrict__ out) {
    int bh = blockIdx.z;
    int m0 = blockIdx.y * 128;
    const float* P = g_scores + (size_t)bh * SEQ * SEQ;
    const float* V = g_qkv + 2u * BH * SEQ * HDIM + (size_t)bh * SEQ * HDIM;

    __shared__ __align__(16) float Ps[16][128];
    __shared__ __align__(16) float Vs[16][64];
    __shared__ __align__(16) float psS[128 * 8];
    __shared__ __align__(16) float tabS[8 * 64];

    int tid = threadIdx.x;
    int tx = tid & 15, ty = tid >> 4;
    int lr = tid >> 1, lc = (tid & 1) * 8;
    int vr = tid >> 4, vc = (tid & 15) * 4;
    float acc[8][4] = {};

    for (int k0 = 0; k0 < SEQ; k0 += 16) {
        float4 p0 = *(const float4*)(P + (size_t)(m0 + lr) * SEQ + k0 + lc);
        float4 p1 = *(const float4*)(P + (size_t)(m0 + lr) * SEQ + k0 + lc + 4);
        float4 vv = *(const float4*)(V + (size_t)(k0 + vr) * HDIM + vc);
        Ps[lc + 0][lr] = p0.x; Ps[lc + 1][lr] = p0.y; Ps[lc + 2][lr] = p0.z; Ps[lc + 3][lr] = p0.w;
        Ps[lc + 4][lr] = p1.x; Ps[lc + 5][lr] = p1.y; Ps[lc + 6][lr] = p1.z; Ps[lc + 7][lr] = p1.w;
        *(float4*)&Vs[vr][vc] = vv;
        __syncthreads();
        #pragma unroll
        for (int kk = 0; kk < 16; kk++) {
            float4 a0 = *(float4*)&Ps[kk][ty * 8];
            float4 a1 = *(float4*)&Ps[kk][ty * 8 + 4];
            float4 b4 = *(float4*)&Vs[kk][tx * 4];
            float ra[8] = {a0.x, a0.y, a0.z, a0.w, a1.x, a1.y, a1.z, a1.w};
            float rb[4] = {b4.x, b4.y, b4.z, b4.w};
            #pragma unroll
            for (int i = 0; i < 8; i++)
                #pragma unroll
                for (int j = 0; j < 4; j++)
                    acc[i][j] += ra[i] * rb[j];
        }
        __syncthreads();
    }

    // relative-value epilogue: acc += ps[q, r] * tab[r, d], staged in smem
    size_t psbase = ((size_t)bh * SEQ + m0) * VOCAB;
    for (int r0 = 0; r0 < VOCAB; r0 += 8) {
        __syncthreads();
        {
            int qq = tid >> 1, rc0 = (tid & 1) * 4;
            #pragma unroll
            for (int u = 0; u < 4; u++) {
                int r = r0 + rc0 + u;
                psS[qq * 8 + rc0 + u] =
                    (r < VOCAB) ? g_ps[psbase + (size_t)qq * VOCAB + r] : 0.0f;
            }
        }
        if (tid < 128) {
            int rr = tid >> 4, cc = (tid & 15) * 4;
            int r = r0 + rr;
            float4 tv = (r < VOCAB) ? *(const float4*)&g_tab[r * 64 + cc]
                                    : make_float4(0.f, 0.f, 0.f, 0.f);
            *(float4*)&tabS[rr * 64 + cc] = tv;
        }
        __syncthreads();
        #pragma unroll
        for (int rc = 0; rc < 8; rc++) {
            float tb0 = tabS[rc * 64 + tx * 4 + 0];
            float tb1 = tabS[rc * 64 + tx * 4 + 1];
            float tb2 = tabS[rc * 64 + tx * 4 + 2];
            float tb3 = tabS[rc * 64 + tx * 4 + 3];
            #pragma unroll
            for (int i = 0; i < 8; i++) {
                float pv = psS[(ty * 8 + i) * 8 + rc];
                acc[i][0] += pv * tb0; acc[i][1] += pv * tb1;
                acc[i][2] += pv * tb2; acc[i][3] += pv * tb3;
            }
        }
    }

    int b = bh >> 4, h = bh & 15;
    #pragma unroll
    for (int i = 0; i < 8; i++) {
        int qq = m0 + ty * 8 + i;
        *(float4*)(out + ((size_t)(b * SEQ + qq)) * HID + h * 64 + tx * 4) =
            make_float4(acc[i][0], acc[i][1], acc[i][2], acc[i][3]);
    }
}

// ---------------- launcher ----------------
extern "C" void kernel_launch(void* const* d_in, const int* in_sizes, int n_in,
                              void* d_out, int out_size) {
    const float* hs   = (const float*)d_in[0];
    const float* mask = (const float*)d_in[1];
    const float* Wq   = (const float*)d_in[2];
    const float* bq   = (const float*)d_in[3];
    const float* Wk   = (const float*)d_in[4];
    const float* bk   = (const float*)d_in[5];
    const float* Wv   = (const float*)d_in[6];
    const float* bv   = (const float*)d_in[7];
    float* out = (float*)d_out;

    init_tab_kernel<<<(VOCAB * 32 + 127) / 128, 128>>>();
    qkv_kernel<<<dim3(HID / 128, (BATCH * SEQ) / 128, 3), 256>>>(hs, Wq, bq, Wk, bk, Wv, bv);
    qrel_kernel<<<BH * SEQ, 128>>>();
    scores_kernel<<<dim3(SEQ / 128, SEQ / 128, BH), 256>>>(mask);
    softmax_kernel<<<BH * SEQ, 256>>>();
    ctx_kernel<<<dim3(1, SEQ / 128, BH), 256>>>(out);
}

// round 4
// speedup vs baseline: 1.2418x; 1.2418x over previous
#include <cuda_runtime.h>
#include <cuda_bf16.h>
#include <cstdint>

#define BATCH 2
#define SEQ   1024
#define HID   1024
#define NHEAD 16
#define HDIM  64
#define BH    (BATCH*NHEAD)      // 32
#define VOCAB 129                // 2*64+1

// ---------------- scratch (device globals; no allocation allowed) ----------------
__device__ __align__(16) float g_qkv[3 * BH * SEQ * HDIM];       // Q,K,V in [bh][s][d]
__device__ __align__(16) float g_scores[(size_t)BH * SEQ * SEQ]; // 128 MB, probs in-place
__device__ __align__(16) float g_qrel[(size_t)BH * SEQ * VOCAB]; // q . tab[r]
__device__ __align__(16) float g_ps[(size_t)BH * SEQ * VOCAB];   // bucketed probs
__device__ __align__(16) float g_tab[VOCAB * HDIM];              // sinusoid table

// split-bf16 copies for tensor-core projection
__device__ __align__(16) __nv_bfloat16 g_hs_hi[BATCH * SEQ * HID];
__device__ __align__(16) __nv_bfloat16 g_hs_lo[BATCH * SEQ * HID];
__device__ __align__(16) __nv_bfloat16 g_w_hi[3 * HID * HID];
__device__ __align__(16) __nv_bfloat16 g_w_lo[3 * HID * HID];

// ---------------- sinusoid table ----------------
__global__ void init_tab_kernel() {
    int idx = blockIdx.x * blockDim.x + threadIdx.x;   // pair index
    if (idx >= VOCAB * 32) return;
    int p = idx >> 5, i = idx & 31;
    float div = expf((float)(2 * i) * (-9.210340371976184f / 64.0f)); // -ln(10000)/64
    float ang = (float)p * div;
    g_tab[p * 64 + 2 * i]     = sinf(ang);
    g_tab[p * 64 + 2 * i + 1] = cosf(ang);
}

// ---------------- split fp32 -> (hi, lo) bf16 ----------------
__device__ __forceinline__ void split_bf16(float v, __nv_bfloat16& hi, __nv_bfloat16& lo) {
    hi = __float2bfloat16_rn(v);
    lo = __float2bfloat16_rn(v - __bfloat162float(hi));
}

__global__ __launch_bounds__(256) void cvt_hs_kernel(const float* __restrict__ hs) {
    int i = (blockIdx.x * blockDim.x + threadIdx.x) * 4;
    if (i >= BATCH * SEQ * HID) return;
    float4 v = *(const float4*)(hs + i);
    __nv_bfloat16 h, l;
    split_bf16(v.x, h, l); g_hs_hi[i + 0] = h; g_hs_lo[i + 0] = l;
    split_bf16(v.y, h, l); g_hs_hi[i + 1] = h; g_hs_lo[i + 1] = l;
    split_bf16(v.z, h, l); g_hs_hi[i + 2] = h; g_hs_lo[i + 2] = l;
    split_bf16(v.w, h, l); g_hs_hi[i + 3] = h; g_hs_lo[i + 3] = l;
}

__global__ __launch_bounds__(256) void cvt_w_kernel(
    const float* __restrict__ Wq, const float* __restrict__ Wk, const float* __restrict__ Wv) {
    int i = (blockIdx.x * blockDim.x + threadIdx.x) * 4;
    if (i >= 3 * HID * HID) return;
    int z = i / (HID * HID), r = i - z * (HID * HID);
    const float* W = (z == 0) ? Wq : (z == 1 ? Wk : Wv);
    float4 v = *(const float4*)(W + r);
    __nv_bfloat16 h, l;
    split_bf16(v.x, h, l); g_w_hi[i + 0] = h; g_w_lo[i + 0] = l;
    split_bf16(v.y, h, l); g_w_hi[i + 1] = h; g_w_lo[i + 1] = l;
    split_bf16(v.z, h, l); g_w_hi[i + 2] = h; g_w_lo[i + 2] = l;
    split_bf16(v.w, h, l); g_w_hi[i + 3] = h; g_w_lo[i + 3] = l;
}

// ---------------- warp mma helper ----------------
__device__ __forceinline__ void mma_bf16(float* c, const unsigned int* A,
                                         unsigned int b0, unsigned int b1) {
    asm volatile("mma.sync.aligned.m16n8k16.row.col.f32.bf16.bf16.f32 "
        "{%0,%1,%2,%3}, {%4,%5,%6,%7}, {%8,%9}, {%0,%1,%2,%3};"
        : "+f"(c[0]), "+f"(c[1]), "+f"(c[2]), "+f"(c[3])
        : "r"(A[0]), "r"(A[1]), "r"(A[2]), "r"(A[3]), "r"(b0), "r"(b1));
}

// ---------------- phase 1: QKV projection via mma.sync bf16 split ----------------
// C = hs @ W^T + b.  Block tile 128x128, BK=32, 8 warps (2x4), warp tile 64x32.
// smem stride 40 bf16 (80B) => conflict-free fragment loads.
#define SSTR 40

__global__ __launch_bounds__(256) void qkv_mma_kernel(
    const float* __restrict__ bq, const float* __restrict__ bk, const float* __restrict__ bv)
{
    int z = blockIdx.z;
    const float* bias = (z == 0) ? bq : (z == 1 ? bk : bv);
    float* outp = g_qkv + (size_t)z * BH * SEQ * HDIM;
    const __nv_bfloat16* gWhi = g_w_hi + (size_t)z * HID * HID;
    const __nv_bfloat16* gWlo = g_w_lo + (size_t)z * HID * HID;

    int m0 = blockIdx.y * 128, n0 = blockIdx.x * 128;

    __shared__ __align__(16) __nv_bfloat16 sAhi[128 * SSTR];
    __shared__ __align__(16) __nv_bfloat16 sAlo[128 * SSTR];
    __shared__ __align__(16) __nv_bfloat16 sBhi[128 * SSTR];
    __shared__ __align__(16) __nv_bfloat16 sBlo[128 * SSTR];

    int t = threadIdx.x;
    int lane = t & 31, warp = t >> 5;
    int wy = warp >> 2, wx = warp & 3;          // warp grid 2x4
    int g = lane >> 2, tq = (lane & 3) * 2;

    float acc[4][4][4] = {};                     // [mt][nt][frag]

    for (int k0 = 0; k0 < HID; k0 += 32) {
        #pragma unroll
        for (int u = 0; u < 2; u++) {
            int idx = t + 256 * u;
            int r = idx >> 2, c = (idx & 3) * 8;
            size_t ga = (size_t)(m0 + r) * HID + k0 + c;
            size_t gb = (size_t)(n0 + r) * HID + k0 + c;
            uint4 v;
            v = *(const uint4*)(g_hs_hi + ga);
            *(uint2*)&sAhi[r * SSTR + c] = make_uint2(v.x, v.y);
            *(uint2*)&sAhi[r * SSTR + c + 4] = make_uint2(v.z, v.w);
            v = *(const uint4*)(g_hs_lo + ga);
            *(uint2*)&sAlo[r * SSTR + c] = make_uint2(v.x, v.y);
            *(uint2*)&sAlo[r * SSTR + c + 4] = make_uint2(v.z, v.w);
            v = *(const uint4*)(gWhi + gb);
            *(uint2*)&sBhi[r * SSTR + c] = make_uint2(v.x, v.y);
            *(uint2*)&sBhi[r * SSTR + c + 4] = make_uint2(v.z, v.w);
            v = *(const uint4*)(gWlo + gb);
            *(uint2*)&sBlo[r * SSTR + c] = make_uint2(v.x, v.y);
            *(uint2*)&sBlo[r * SSTR + c + 4] = make_uint2(v.z, v.w);
        }
        __syncthreads();

        #pragma unroll
        for (int kk = 0; kk < 32; kk += 16) {
            unsigned int ahi[4][4];
            unsigned int alo[4][4];
            #pragma unroll
            for (int mt = 0; mt < 4; mt++) {
                int abase = (wy * 64 + mt * 16 + g) * SSTR + kk + tq;
                ahi[mt][0] = *(unsigned int*)&sAhi[abase];
                ahi[mt][1] = *(unsigned int*)&sAhi[abase + 8 * SSTR];
                ahi[mt][2] = *(unsigned int*)&sAhi[abase + 8];
                ahi[mt][3] = *(unsigned int*)&sAhi[abase + 8 * SSTR + 8];
                alo[mt][0] = *(unsigned int*)&sAlo[abase];
                alo[mt][1] = *(unsigned int*)&sAlo[abase + 8 * SSTR];
                alo[mt][2] = *(unsigned int*)&sAlo[abase + 8];
                alo[mt][3] = *(unsigned int*)&sAlo[abase + 8 * SSTR + 8];
            }
            #pragma unroll
            for (int nt = 0; nt < 4; nt++) {
                int bbase = (wx * 32 + nt * 8 + g) * SSTR + kk + tq;
                unsigned int bhi0 = *(unsigned int*)&sBhi[bbase];
                unsigned int bhi1 = *(unsigned int*)&sBhi[bbase + 8];
                unsigned int blo0 = *(unsigned int*)&sBlo[bbase];
                unsigned int blo1 = *(unsigned int*)&sBlo[bbase + 8];
                #pragma unroll
                for (int mt = 0; mt < 4; mt++) {
                    mma_bf16(acc[mt][nt], ahi[mt], bhi0, bhi1);
                    mma_bf16(acc[mt][nt], ahi[mt], blo0, blo1);
                    mma_bf16(acc[mt][nt], alo[mt], bhi0, bhi1);
                }
            }
        }
        __syncthreads();
    }

    // epilogue: bias + scatter to [b][h][s][d]
    #pragma unroll
    for (int nt = 0; nt < 4; nt++) {
        int n = n0 + wx * 32 + nt * 8 + tq;
        float2 b2 = *(const float2*)&bias[n];
        int h = n >> 6, d = n & 63;
        #pragma unroll
        for (int mt = 0; mt < 4; mt++) {
            int m = m0 + wy * 64 + mt * 16 + g;
            int b = m >> 10, s = m & (SEQ - 1);
            float* dst0 = outp + (((size_t)(b * NHEAD + h)) * SEQ + s) * HDIM + d;
            *(float2*)dst0 = make_float2(acc[mt][nt][0] + b2.x, acc[mt][nt][1] + b2.y);
            float* dst1 = outp + (((size_t)(b * NHEAD + h)) * SEQ + s + 8) * HDIM + d;
            *(float2*)dst1 = make_float2(acc[mt][nt][2] + b2.x, acc[mt][nt][3] + b2.y);
        }
    }
}

// ---------------- phase 1.5: qrel[row, r] = Q[row,:] . tab[r,:] ----------------
__global__ __launch_bounds__(128) void qrel_kernel() {
    int row = blockIdx.x;                           // bh*SEQ + q
    __shared__ float qrow[64];
    const float* Q = g_qkv + (size_t)row * HDIM;
    if (threadIdx.x < 64) qrow[threadIdx.x] = Q[threadIdx.x];
    __syncthreads();
    for (int r = threadIdx.x; r < VOCAB; r += 128) {
        float s = 0.0f;
        #pragma unroll
        for (int d = 0; d < 64; d++) s += qrow[d] * g_tab[r * 64 + d];
        g_qrel[(size_t)row * VOCAB + r] = s;
    }
}

// ---------------- phase 2: scores = (Q K^T + qrel)/8 + mask ----------------
__global__ __launch_bounds__(256) void scores_kernel(const float* __restrict__ mask) {
    int bh = blockIdx.z;
    const float* Q = g_qkv + (size_t)bh * SEQ * HDIM;
    const float* K = g_qkv + (size_t)BH * SEQ * HDIM + (size_t)bh * SEQ * HDIM;
    int m0 = blockIdx.y * 128, n0 = blockIdx.x * 128;

    __shared__ __align__(16) float As[8][128];
    __shared__ __align__(16) float Bs[8][128];
    int tid = threadIdx.x;
    int lr = tid >> 1, lc = (tid & 1) * 4;
    int tx = tid & 15, ty = tid >> 4;
    float acc[8][8] = {};

    for (int k0 = 0; k0 < HDIM; k0 += 8) {
        float4 a  = *(const float4*)(Q + (size_t)(m0 + lr) * HDIM + k0 + lc);
        float4 bb = *(const float4*)(K + (size_t)(n0 + lr) * HDIM + k0 + lc);
        As[lc + 0][lr] = a.x;  As[lc + 1][lr] = a.y;  As[lc + 2][lr] = a.z;  As[lc + 3][lr] = a.w;
        Bs[lc + 0][lr] = bb.x; Bs[lc + 1][lr] = bb.y; Bs[lc + 2][lr] = bb.z; Bs[lc + 3][lr] = bb.w;
        __syncthreads();
        #pragma unroll
        for (int kk = 0; kk < 8; kk++) {
            float4 a0 = *(float4*)&As[kk][ty * 8];
            float4 a1 = *(float4*)&As[kk][ty * 8 + 4];
            float4 b0 = *(float4*)&Bs[kk][tx * 8];
            float4 b1 = *(float4*)&Bs[kk][tx * 8 + 4];
            float ra[8] = {a0.x, a0.y, a0.z, a0.w, a1.x, a1.y, a1.z, a1.w};
            float rb[8] = {b0.x, b0.y, b0.z, b0.w, b1.x, b1.y, b1.z, b1.w};
            #pragma unroll
            for (int i = 0; i < 8; i++)
                #pragma unroll
                for (int j = 0; j < 8; j++)
                    acc[i][j] += ra[i] * rb[j];
        }
        __syncthreads();
    }

    int b = bh >> 4;
    #pragma unroll
    for (int i = 0; i < 8; i++) {
        int q = m0 + ty * 8 + i;
        const float* qr = g_qrel + ((size_t)bh * SEQ + q) * VOCAB;
        float v[8];
        #pragma unroll
        for (int j = 0; j < 8; j++) {
            int k = n0 + tx * 8 + j;
            int dist = k - q;
            dist = dist < -64 ? -64 : (dist > 64 ? 64 : dist);
            v[j] = (acc[i][j] + qr[dist + 64]) * 0.125f + mask[b * SEQ + k];
        }
        float* dst = g_scores + ((size_t)bh * SEQ + q) * SEQ + n0 + tx * 8;
        *(float4*)(dst)     = make_float4(v[0], v[1], v[2], v[3]);
        *(float4*)(dst + 4) = make_float4(v[4], v[5], v[6], v[7]);
    }
}

// ---------------- phase 3: row softmax (in place) + ps buckets ----------------
__global__ __launch_bounds__(256) void softmax_kernel() {
    int row = blockIdx.x;           // bh*SEQ + q
    int q = row & (SEQ - 1);
    float* x = g_scores + (size_t)row * SEQ;
    __shared__ float sm[SEQ];
    __shared__ float red[16];
    __shared__ float bc[4];
    int t = threadIdx.x;
    int lane = t & 31, warp = t >> 5;

    float v[4];
    float mx = -3.4e38f;
    #pragma unroll
    for (int u = 0; u < 4; u++) { v[u] = x[t + 256 * u]; mx = fmaxf(mx, v[u]); }
    #pragma unroll
    for (int o = 16; o > 0; o >>= 1) mx = fmaxf(mx, __shfl_xor_sync(0xffffffffu, mx, o));
    if (lane == 0) red[warp] = mx;
    __syncthreads();
    if (t == 0) { float m = red[0]; for (int w = 1; w < 8; w++) m = fmaxf(m, red[w]); bc[0] = m; }
    __syncthreads();
    mx = bc[0];

    float s = 0.0f;
    #pragma unroll
    for (int u = 0; u < 4; u++) { v[u] = expf(v[u] - mx); s += v[u]; }
    #pragma unroll
    for (int o = 16; o > 0; o >>= 1) s += __shfl_xor_sync(0xffffffffu, s, o);
    __syncthreads();   // red reuse
    if (lane == 0) red[warp] = s;
    __syncthreads();
    if (t == 0) { float m = 0; for (int w = 0; w < 8; w++) m += red[w]; bc[1] = m; }
    __syncthreads();
    float inv = 1.0f / bc[1];

    float lo = 0.0f, hi = 0.0f;
    #pragma unroll
    for (int u = 0; u < 4; u++) {
        int k = t + 256 * u;
        float p = v[u] * inv;
        sm[k] = p; x[k] = p;
        if (k <= q - 64) lo += p;          // dist clamps to -64 -> bucket 0
        if (k >= q + 64) hi += p;          // dist clamps to +64 -> bucket 128
    }
    #pragma unroll
    for (int o = 16; o > 0; o >>= 1) {
        lo += __shfl_xor_sync(0xffffffffu, lo, o);
        hi += __shfl_xor_sync(0xffffffffu, hi, o);
    }
    __syncthreads();   // red reuse
    if (lane == 0) { red[warp] = lo; red[warp + 8] = hi; }
    __syncthreads();
    if (t == 0) {
        float a = 0, b2 = 0;
        for (int w = 0; w < 8; w++) { a += red[w]; b2 += red[w + 8]; }
        bc[2] = a; bc[3] = b2;
    }
    __syncthreads();

    float* psr = g_ps + (size_t)row * VOCAB;
    if (t == 0)   psr[0]   = bc[2];
    if (t == 128) psr[128] = bc[3];
    if (t >= 1 && t < 128) {
        int k = q + t - 64;
        psr[t] = (k >= 0 && k < SEQ) ? sm[k] : 0.0f;
    }
}

// ---------------- phase 4: ctx = P @ V + ps @ tab, write [b,s,h*64+d] ----------------
__global__ __launch_bounds__(256) void ctx_kernel(float* __restrict__ out) {
    int bh = blockIdx.z;
    int m0 = blockIdx.y * 128;
    const float* P = g_scores + (size_t)bh * SEQ * SEQ;
    const float* V = g_qkv + 2u * BH * SEQ * HDIM + (size_t)bh * SEQ * HDIM;

    __shared__ __align__(16) float Ps[16][128];
    __shared__ __align__(16) float Vs[16][64];
    __shared__ __align__(16) float psS[128 * 8];
    __shared__ __align__(16) float tabS[8 * 64];

    int tid = threadIdx.x;
    int tx = tid & 15, ty = tid >> 4;
    int lr = tid >> 1, lc = (tid & 1) * 8;
    int vr = tid >> 4, vc = (tid & 15) * 4;
    float acc[8][4] = {};

    for (int k0 = 0; k0 < SEQ; k0 += 16) {
        float4 p0 = *(const float4*)(P + (size_t)(m0 + lr) * SEQ + k0 + lc);
        float4 p1 = *(const float4*)(P + (size_t)(m0 + lr) * SEQ + k0 + lc + 4);
        float4 vv = *(const float4*)(V + (size_t)(k0 + vr) * HDIM + vc);
        Ps[lc + 0][lr] = p0.x; Ps[lc + 1][lr] = p0.y; Ps[lc + 2][lr] = p0.z; Ps[lc + 3][lr] = p0.w;
        Ps[lc + 4][lr] = p1.x; Ps[lc + 5][lr] = p1.y; Ps[lc + 6][lr] = p1.z; Ps[lc + 7][lr] = p1.w;
        *(float4*)&Vs[vr][vc] = vv;
        __syncthreads();
        #pragma unroll
        for (int kk = 0; kk < 16; kk++) {
            float4 a0 = *(float4*)&Ps[kk][ty * 8];
            float4 a1 = *(float4*)&Ps[kk][ty * 8 + 4];
            float4 b4 = *(float4*)&Vs[kk][tx * 4];
            float ra[8] = {a0.x, a0.y, a0.z, a0.w, a1.x, a1.y, a1.z, a1.w};
            float rb[4] = {b4.x, b4.y, b4.z, b4.w};
            #pragma unroll
            for (int i = 0; i < 8; i++)
                #pragma unroll
                for (int j = 0; j < 4; j++)
                    acc[i][j] += ra[i] * rb[j];
        }
        __syncthreads();
    }

    // relative-value epilogue: acc += ps[q, r] * tab[r, d], staged in smem
    size_t psbase = ((size_t)bh * SEQ + m0) * VOCAB;
    for (int r0 = 0; r0 < VOCAB; r0 += 8) {
        __syncthreads();
        {
            int qq = tid >> 1, rc0 = (tid & 1) * 4;
            #pragma unroll
            for (int u = 0; u < 4; u++) {
                int r = r0 + rc0 + u;
                psS[qq * 8 + rc0 + u] =
                    (r < VOCAB) ? g_ps[psbase + (size_t)qq * VOCAB + r] : 0.0f;
            }
        }
        if (tid < 128) {
            int rr = tid >> 4, cc = (tid & 15) * 4;
            int r = r0 + rr;
            float4 tv = (r < VOCAB) ? *(const float4*)&g_tab[r * 64 + cc]
                                    : make_float4(0.f, 0.f, 0.f, 0.f);
            *(float4*)&tabS[rr * 64 + cc] = tv;
        }
        __syncthreads();
        #pragma unroll
        for (int rc = 0; rc < 8; rc++) {
            float tb0 = tabS[rc * 64 + tx * 4 + 0];
            float tb1 = tabS[rc * 64 + tx * 4 + 1];
            float tb2 = tabS[rc * 64 + tx * 4 + 2];
            float tb3 = tabS[rc * 64 + tx * 4 + 3];
            #pragma unroll
            for (int i = 0; i < 8; i++) {
                float pv = psS[(ty * 8 + i) * 8 + rc];
                acc[i][0] += pv * tb0; acc[i][1] += pv * tb1;
                acc[i][2] += pv * tb2; acc[i][3] += pv * tb3;
            }
        }
    }

    int b = bh >> 4, h = bh & 15;
    #pragma unroll
    for (int i = 0; i < 8; i++) {
        int qq = m0 + ty * 8 + i;
        *(float4*)(out + ((size_t)(b * SEQ + qq)) * HID + h * 64 + tx * 4) =
            make_float4(acc[i][0], acc[i][1], acc[i][2], acc[i][3]);
    }
}

// ---------------- launcher ----------------
extern "C" void kernel_launch(void* const* d_in, const int* in_sizes, int n_in,
                              void* d_out, int out_size) {
    const float* hs   = (const float*)d_in[0];
    const float* mask = (const float*)d_in[1];
    const float* Wq   = (const float*)d_in[2];
    const float* bq   = (const float*)d_in[3];
    const float* Wk   = (const float*)d_in[4];
    const float* bk   = (const float*)d_in[5];
    const float* Wv   = (const float*)d_in[6];
    const float* bv   = (const float*)d_in[7];
    float* out = (float*)d_out;

    init_tab_kernel<<<(VOCAB * 32 + 127) / 128, 128>>>();
    cvt_hs_kernel<<<(BATCH * SEQ * HID / 4 + 255) / 256, 256>>>(hs);
    cvt_w_kernel<<<(3 * HID * HID / 4 + 255) / 256, 256>>>(Wq, Wk, Wv);
    qkv_mma_kernel<<<dim3(HID / 128, (BATCH * SEQ) / 128, 3), 256>>>(bq, bk, bv);
    qrel_kernel<<<BH * SEQ, 128>>>();
    scores_kernel<<<dim3(SEQ / 128, SEQ / 128, BH), 256>>>(mask);
    softmax_kernel<<<BH * SEQ, 256>>>();
    ctx_kernel<<<dim3(1, SEQ / 128, BH), 256>>>(out);
}

// round 5
// speedup vs baseline: 1.3970x; 1.1250x over previous
#include <cuda_runtime.h>
#include <cuda_bf16.h>
#include <cstdint>

#define BATCH 2
#define SEQ   1024
#define HID   1024
#define NHEAD 16
#define HDIM  64
#define BH    (BATCH*NHEAD)      // 32
#define VOCAB 129                // 2*64+1
#define SSTR  40                 // bf16 smem stride: conflict-free fragments

// ---------------- scratch (device globals; no allocation allowed) ----------------
__device__ __align__(16) float g_qkv[BH * SEQ * HDIM];           // Q fp32 (for qrel)
__device__ __align__(16) float g_scores[(size_t)BH * SEQ * SEQ]; // fp32 scores
__device__ __align__(16) float g_qrel[(size_t)BH * SEQ * VOCAB];
__device__ __align__(16) float g_ps[(size_t)BH * SEQ * VOCAB];
__device__ __align__(16) float g_tab[VOCAB * HDIM];

// split-bf16 operands
__device__ __align__(16) __nv_bfloat16 g_hs_hi[BATCH * SEQ * HID];
__device__ __align__(16) __nv_bfloat16 g_hs_lo[BATCH * SEQ * HID];
__device__ __align__(16) __nv_bfloat16 g_w_hi[3 * HID * HID];
__device__ __align__(16) __nv_bfloat16 g_w_lo[3 * HID * HID];
__device__ __align__(16) __nv_bfloat16 g_qh[BH * SEQ * HDIM];
__device__ __align__(16) __nv_bfloat16 g_ql[BH * SEQ * HDIM];
__device__ __align__(16) __nv_bfloat16 g_kh[BH * SEQ * HDIM];
__device__ __align__(16) __nv_bfloat16 g_kl[BH * SEQ * HDIM];
__device__ __align__(16) __nv_bfloat16 g_vth[BH * HDIM * SEQ];   // V^T [bh][d][s]
__device__ __align__(16) __nv_bfloat16 g_vtl[BH * HDIM * SEQ];
__device__ __align__(16) __nv_bfloat16 g_ph[(size_t)BH * SEQ * SEQ]; // probs hi
__device__ __align__(16) __nv_bfloat16 g_pl[(size_t)BH * SEQ * SEQ]; // probs lo

// ---------------- sinusoid table ----------------
__global__ void init_tab_kernel() {
    int idx = blockIdx.x * blockDim.x + threadIdx.x;
    if (idx >= VOCAB * 32) return;
    int p = idx >> 5, i = idx & 31;
    float div = expf((float)(2 * i) * (-9.210340371976184f / 64.0f));
    float ang = (float)p * div;
    g_tab[p * 64 + 2 * i]     = sinf(ang);
    g_tab[p * 64 + 2 * i + 1] = cosf(ang);
}

// ---------------- split fp32 -> (hi, lo) bf16 ----------------
__device__ __forceinline__ void split_bf16(float v, __nv_bfloat16& hi, __nv_bfloat16& lo) {
    hi = __float2bfloat16_rn(v);
    lo = __float2bfloat16_rn(v - __bfloat162float(hi));
}

__global__ __launch_bounds__(256) void cvt_hs_kernel(const float* __restrict__ hs) {
    int i = (blockIdx.x * blockDim.x + threadIdx.x) * 4;
    if (i >= BATCH * SEQ * HID) return;
    float4 v = *(const float4*)(hs + i);
    __nv_bfloat16 h, l;
    split_bf16(v.x, h, l); g_hs_hi[i + 0] = h; g_hs_lo[i + 0] = l;
    split_bf16(v.y, h, l); g_hs_hi[i + 1] = h; g_hs_lo[i + 1] = l;
    split_bf16(v.z, h, l); g_hs_hi[i + 2] = h; g_hs_lo[i + 2] = l;
    split_bf16(v.w, h, l); g_hs_hi[i + 3] = h; g_hs_lo[i + 3] = l;
}

__global__ __launch_bounds__(256) void cvt_w_kernel(
    const float* __restrict__ Wq, const float* __restrict__ Wk, const float* __restrict__ Wv) {
    int i = (blockIdx.x * blockDim.x + threadIdx.x) * 4;
    if (i >= 3 * HID * HID) return;
    int z = i / (HID * HID), r = i - z * (HID * HID);
    const float* W = (z == 0) ? Wq : (z == 1 ? Wk : Wv);
    float4 v = *(const float4*)(W + r);
    __nv_bfloat16 h, l;
    split_bf16(v.x, h, l); g_w_hi[i + 0] = h; g_w_lo[i + 0] = l;
    split_bf16(v.y, h, l); g_w_hi[i + 1] = h; g_w_lo[i + 1] = l;
    split_bf16(v.z, h, l); g_w_hi[i + 2] = h; g_w_lo[i + 2] = l;
    split_bf16(v.w, h, l); g_w_hi[i + 3] = h; g_w_lo[i + 3] = l;
}

// ---------------- warp mma helper ----------------
__device__ __forceinline__ void mma_bf16(float* c, const unsigned int* A,
                                         unsigned int b0, unsigned int b1) {
    asm volatile("mma.sync.aligned.m16n8k16.row.col.f32.bf16.bf16.f32 "
        "{%0,%1,%2,%3}, {%4,%5,%6,%7}, {%8,%9}, {%0,%1,%2,%3};"
        : "+f"(c[0]), "+f"(c[1]), "+f"(c[2]), "+f"(c[3])
        : "r"(A[0]), "r"(A[1]), "r"(A[2]), "r"(A[3]), "r"(b0), "r"(b1));
}

// ---------------- phase 1: QKV projection, split-bf16 MMA ----------------
__global__ __launch_bounds__(256) void qkv_mma_kernel(
    const float* __restrict__ bq, const float* __restrict__ bk, const float* __restrict__ bv)
{
    int z = blockIdx.z;
    const float* bias = (z == 0) ? bq : (z == 1 ? bk : bv);
    const __nv_bfloat16* gWhi = g_w_hi + (size_t)z * HID * HID;
    const __nv_bfloat16* gWlo = g_w_lo + (size_t)z * HID * HID;

    int m0 = blockIdx.y * 128, n0 = blockIdx.x * 128;

    __shared__ __align__(16) __nv_bfloat16 sAhi[128 * SSTR];
    __shared__ __align__(16) __nv_bfloat16 sAlo[128 * SSTR];
    __shared__ __align__(16) __nv_bfloat16 sBhi[128 * SSTR];
    __shared__ __align__(16) __nv_bfloat16 sBlo[128 * SSTR];

    int t = threadIdx.x;
    int lane = t & 31, warp = t >> 5;
    int wy = warp >> 2, wx = warp & 3;
    int g = lane >> 2, tq = (lane & 3) * 2;

    float acc[4][4][4] = {};

    for (int k0 = 0; k0 < HID; k0 += 32) {
        #pragma unroll
        for (int u = 0; u < 2; u++) {
            int idx = t + 256 * u;
            int r = idx >> 2, c = (idx & 3) * 8;
            size_t ga = (size_t)(m0 + r) * HID + k0 + c;
            size_t gb = (size_t)(n0 + r) * HID + k0 + c;
            uint4 v;
            v = *(const uint4*)(g_hs_hi + ga);
            *(uint2*)&sAhi[r * SSTR + c] = make_uint2(v.x, v.y);
            *(uint2*)&sAhi[r * SSTR + c + 4] = make_uint2(v.z, v.w);
            v = *(const uint4*)(g_hs_lo + ga);
            *(uint2*)&sAlo[r * SSTR + c] = make_uint2(v.x, v.y);
            *(uint2*)&sAlo[r * SSTR + c + 4] = make_uint2(v.z, v.w);
            v = *(const uint4*)(gWhi + gb);
            *(uint2*)&sBhi[r * SSTR + c] = make_uint2(v.x, v.y);
            *(uint2*)&sBhi[r * SSTR + c + 4] = make_uint2(v.z, v.w);
            v = *(const uint4*)(gWlo + gb);
            *(uint2*)&sBlo[r * SSTR + c] = make_uint2(v.x, v.y);
            *(uint2*)&sBlo[r * SSTR + c + 4] = make_uint2(v.z, v.w);
        }
        __syncthreads();

        #pragma unroll
        for (int kk = 0; kk < 32; kk += 16) {
            unsigned int ahi[4][4], alo[4][4];
            #pragma unroll
            for (int mt = 0; mt < 4; mt++) {
                int abase = (wy * 64 + mt * 16 + g) * SSTR + kk + tq;
                ahi[mt][0] = *(unsigned int*)&sAhi[abase];
                ahi[mt][1] = *(unsigned int*)&sAhi[abase + 8 * SSTR];
                ahi[mt][2] = *(unsigned int*)&sAhi[abase + 8];
                ahi[mt][3] = *(unsigned int*)&sAhi[abase + 8 * SSTR + 8];
                alo[mt][0] = *(unsigned int*)&sAlo[abase];
                alo[mt][1] = *(unsigned int*)&sAlo[abase + 8 * SSTR];
                alo[mt][2] = *(unsigned int*)&sAlo[abase + 8];
                alo[mt][3] = *(unsigned int*)&sAlo[abase + 8 * SSTR + 8];
            }
            #pragma unroll
            for (int nt = 0; nt < 4; nt++) {
                int bbase = (wx * 32 + nt * 8 + g) * SSTR + kk + tq;
                unsigned int bhi0 = *(unsigned int*)&sBhi[bbase];
                unsigned int bhi1 = *(unsigned int*)&sBhi[bbase + 8];
                unsigned int blo0 = *(unsigned int*)&sBlo[bbase];
                unsigned int blo1 = *(unsigned int*)&sBlo[bbase + 8];
                #pragma unroll
                for (int mt = 0; mt < 4; mt++) {
                    mma_bf16(acc[mt][nt], ahi[mt], bhi0, bhi1);
                    mma_bf16(acc[mt][nt], ahi[mt], blo0, blo1);
                    mma_bf16(acc[mt][nt], alo[mt], bhi0, bhi1);
                }
            }
        }
        __syncthreads();
    }

    // epilogue: bias, then emit bf16 hi/lo operands (and fp32 Q for qrel)
    #pragma unroll
    for (int nt = 0; nt < 4; nt++) {
        int n = n0 + wx * 32 + nt * 8 + tq;
        float2 b2 = *(const float2*)&bias[n];
        int h = n >> 6, d = n & 63;
        #pragma unroll
        for (int mt = 0; mt < 4; mt++) {
            int m = m0 + wy * 64 + mt * 16 + g;
            int b = m >> 10, s = m & (SEQ - 1);
            int bh = b * NHEAD + h;
            float v0 = acc[mt][nt][0] + b2.x, v1 = acc[mt][nt][1] + b2.y;
            float v2 = acc[mt][nt][2] + b2.x, v3 = acc[mt][nt][3] + b2.y;
            __nv_bfloat16 h0, l0, h1, l1, h2, l2, h3, l3;
            split_bf16(v0, h0, l0); split_bf16(v1, h1, l1);
            split_bf16(v2, h2, l2); split_bf16(v3, h3, l3);
            if (z < 2) {
                __nv_bfloat16* ah = (z == 0) ? g_qh : g_kh;
                __nv_bfloat16* al = (z == 0) ? g_ql : g_kl;
                size_t o0 = ((size_t)bh * SEQ + s) * HDIM + d;
                size_t o1 = o0 + 8 * HDIM;
                *(__nv_bfloat162*)(ah + o0) = __nv_bfloat162(h0, h1);
                *(__nv_bfloat162*)(al + o0) = __nv_bfloat162(l0, l1);
                *(__nv_bfloat162*)(ah + o1) = __nv_bfloat162(h2, h3);
                *(__nv_bfloat162*)(al + o1) = __nv_bfloat162(l2, l3);
                if (z == 0) {
                    float* dst0 = g_qkv + o0;
                    float* dst1 = g_qkv + o1;
                    *(float2*)dst0 = make_float2(v0, v1);
                    *(float2*)dst1 = make_float2(v2, v3);
                }
            } else {
                size_t base = ((size_t)bh * HDIM + d) * SEQ + s;   // [bh][d][s]
                g_vth[base] = h0;           g_vtl[base] = l0;
                g_vth[base + SEQ] = h1;     g_vtl[base + SEQ] = l1;
                g_vth[base + 8] = h2;       g_vtl[base + 8] = l2;
                g_vth[base + SEQ + 8] = h3; g_vtl[base + SEQ + 8] = l3;
            }
        }
    }
}

// ---------------- phase 1.5: qrel[row, r] = Q[row,:] . tab[r,:] ----------------
__global__ __launch_bounds__(128) void qrel_kernel() {
    int row = blockIdx.x;
    __shared__ float qrow[64];
    const float* Q = g_qkv + (size_t)row * HDIM;
    if (threadIdx.x < 64) qrow[threadIdx.x] = Q[threadIdx.x];
    __syncthreads();
    for (int r = threadIdx.x; r < VOCAB; r += 128) {
        float s = 0.0f;
        #pragma unroll
        for (int d = 0; d < 64; d++) s += qrow[d] * g_tab[r * 64 + d];
        g_qrel[(size_t)row * VOCAB + r] = s;
    }
}

// ---------------- phase 2: scores = (Q K^T + qrel)/8 + mask, split-bf16 MMA ----------------
__global__ __launch_bounds__(256) void scores_mma_kernel(const float* __restrict__ mask) {
    int bh = blockIdx.z, b = bh >> 4;
    int m0 = blockIdx.y * 128, n0 = blockIdx.x * 128;

    __shared__ __align__(16) __nv_bfloat16 sAhi[128 * SSTR];
    __shared__ __align__(16) __nv_bfloat16 sAlo[128 * SSTR];
    __shared__ __align__(16) __nv_bfloat16 sBhi[128 * SSTR];
    __shared__ __align__(16) __nv_bfloat16 sBlo[128 * SSTR];

    int t = threadIdx.x;
    int lane = t & 31, warp = t >> 5;
    int wy = warp >> 2, wx = warp & 3;
    int g = lane >> 2, tq = (lane & 3) * 2;

    float acc[4][4][4] = {};

    for (int k0 = 0; k0 < HDIM; k0 += 32) {
        #pragma unroll
        for (int u = 0; u < 2; u++) {
            int idx = t + 256 * u;
            int r = idx >> 2, c = (idx & 3) * 8;
            size_t ga = ((size_t)bh * SEQ + m0 + r) * HDIM + k0 + c;
            size_t gb = ((size_t)bh * SEQ + n0 + r) * HDIM + k0 + c;
            uint4 v;
            v = *(const uint4*)(g_qh + ga);
            *(uint2*)&sAhi[r * SSTR + c] = make_uint2(v.x, v.y);
            *(uint2*)&sAhi[r * SSTR + c + 4] = make_uint2(v.z, v.w);
            v = *(const uint4*)(g_ql + ga);
            *(uint2*)&sAlo[r * SSTR + c] = make_uint2(v.x, v.y);
            *(uint2*)&sAlo[r * SSTR + c + 4] = make_uint2(v.z, v.w);
            v = *(const uint4*)(g_kh + gb);
            *(uint2*)&sBhi[r * SSTR + c] = make_uint2(v.x, v.y);
            *(uint2*)&sBhi[r * SSTR + c + 4] = make_uint2(v.z, v.w);
            v = *(const uint4*)(g_kl + gb);
            *(uint2*)&sBlo[r * SSTR + c] = make_uint2(v.x, v.y);
            *(uint2*)&sBlo[r * SSTR + c + 4] = make_uint2(v.z, v.w);
        }
        __syncthreads();

        #pragma unroll
        for (int kk = 0; kk < 32; kk += 16) {
            unsigned int ahi[4][4], alo[4][4];
            #pragma unroll
            for (int mt = 0; mt < 4; mt++) {
                int abase = (wy * 64 + mt * 16 + g) * SSTR + kk + tq;
                ahi[mt][0] = *(unsigned int*)&sAhi[abase];
                ahi[mt][1] = *(unsigned int*)&sAhi[abase + 8 * SSTR];
                ahi[mt][2] = *(unsigned int*)&sAhi[abase + 8];
                ahi[mt][3] = *(unsigned int*)&sAhi[abase + 8 * SSTR + 8];
                alo[mt][0] = *(unsigned int*)&sAlo[abase];
                alo[mt][1] = *(unsigned int*)&sAlo[abase + 8 * SSTR];
                alo[mt][2] = *(unsigned int*)&sAlo[abase + 8];
                alo[mt][3] = *(unsigned int*)&sAlo[abase + 8 * SSTR + 8];
            }
            #pragma unroll
            for (int nt = 0; nt < 4; nt++) {
                int bbase = (wx * 32 + nt * 8 + g) * SSTR + kk + tq;
                unsigned int bhi0 = *(unsigned int*)&sBhi[bbase];
                unsigned int bhi1 = *(unsigned int*)&sBhi[bbase + 8];
                unsigned int blo0 = *(unsigned int*)&sBlo[bbase];
                unsigned int blo1 = *(unsigned int*)&sBlo[bbase + 8];
                #pragma unroll
                for (int mt = 0; mt < 4; mt++) {
                    mma_bf16(acc[mt][nt], ahi[mt], bhi0, bhi1);
                    mma_bf16(acc[mt][nt], ahi[mt], blo0, blo1);
                    mma_bf16(acc[mt][nt], alo[mt], bhi0, bhi1);
                }
            }
        }
        __syncthreads();
    }

    // epilogue: + qrel(dist), /8, + mask
    #pragma unroll
    for (int nt = 0; nt < 4; nt++) {
        int n = n0 + wx * 32 + nt * 8 + tq;
        float mk0 = mask[b * SEQ + n], mk1 = mask[b * SEQ + n + 1];
        #pragma unroll
        for (int mt = 0; mt < 4; mt++) {
            int q0 = m0 + wy * 64 + mt * 16 + g;
            #pragma unroll
            for (int hrow = 0; hrow < 2; hrow++) {
                int q = q0 + hrow * 8;
                const float* qr = g_qrel + ((size_t)bh * SEQ + q) * VOCAB;
                int d0 = n - q;     d0 = d0 < -64 ? -64 : (d0 > 64 ? 64 : d0);
                int d1 = n + 1 - q; d1 = d1 < -64 ? -64 : (d1 > 64 ? 64 : d1);
                float r0 = (acc[mt][nt][hrow * 2 + 0] + qr[d0 + 64]) * 0.125f + mk0;
                float r1 = (acc[mt][nt][hrow * 2 + 1] + qr[d1 + 64]) * 0.125f + mk1;
                *(float2*)(g_scores + ((size_t)bh * SEQ + q) * SEQ + n) = make_float2(r0, r1);
            }
        }
    }
}

// ---------------- phase 3: row softmax -> bf16 hi/lo probs + ps buckets ----------------
__global__ __launch_bounds__(256) void softmax_kernel() {
    int row = blockIdx.x;
    int q = row & (SEQ - 1);
    const float* x = g_scores + (size_t)row * SEQ;
    __shared__ float sm[SEQ];
    __shared__ float red[16];
    __shared__ float bc[4];
    int t = threadIdx.x;
    int lane = t & 31, warp = t >> 5;

    float v[4];
    float mx = -3.4e38f;
    #pragma unroll
    for (int u = 0; u < 4; u++) { v[u] = x[t + 256 * u]; mx = fmaxf(mx, v[u]); }
    #pragma unroll
    for (int o = 16; o > 0; o >>= 1) mx = fmaxf(mx, __shfl_xor_sync(0xffffffffu, mx, o));
    if (lane == 0) red[warp] = mx;
    __syncthreads();
    if (t == 0) { float m = red[0]; for (int w = 1; w < 8; w++) m = fmaxf(m, red[w]); bc[0] = m; }
    __syncthreads();
    mx = bc[0];

    float s = 0.0f;
    #pragma unroll
    for (int u = 0; u < 4; u++) { v[u] = expf(v[u] - mx); s += v[u]; }
    #pragma unroll
    for (int o = 16; o > 0; o >>= 1) s += __shfl_xor_sync(0xffffffffu, s, o);
    __syncthreads();
    if (lane == 0) red[warp] = s;
    __syncthreads();
    if (t == 0) { float m = 0; for (int w = 0; w < 8; w++) m += red[w]; bc[1] = m; }
    __syncthreads();
    float inv = 1.0f / bc[1];

    float lo = 0.0f, hi = 0.0f;
    size_t pbase = (size_t)row * SEQ;
    #pragma unroll
    for (int u = 0; u < 4; u++) {
        int k = t + 256 * u;
        float p = v[u] * inv;
        sm[k] = p;
        __nv_bfloat16 ph, pl;
        split_bf16(p, ph, pl);
        g_ph[pbase + k] = ph;
        g_pl[pbase + k] = pl;
        if (k <= q - 64) lo += p;
        if (k >= q + 64) hi += p;
    }
    #pragma unroll
    for (int o = 16; o > 0; o >>= 1) {
        lo += __shfl_xor_sync(0xffffffffu, lo, o);
        hi += __shfl_xor_sync(0xffffffffu, hi, o);
    }
    __syncthreads();
    if (lane == 0) { red[warp] = lo; red[warp + 8] = hi; }
    __syncthreads();
    if (t == 0) {
        float a = 0, b2 = 0;
        for (int w = 0; w < 8; w++) { a += red[w]; b2 += red[w + 8]; }
        bc[2] = a; bc[3] = b2;
    }
    __syncthreads();

    float* psr = g_ps + (size_t)row * VOCAB;
    if (t == 0)   psr[0]   = bc[2];
    if (t == 128) psr[128] = bc[3];
    if (t >= 1 && t < 128) {
        int k = q + t - 64;
        psr[t] = (k >= 0 && k < SEQ) ? sm[k] : 0.0f;
    }
}

// ---------------- phase 4: ctx = P @ V (split-bf16 MMA) + ps @ tab ----------------
// Block: 128 q-rows x 64 d-cols. Warps 4x2, warp tile 32x32. K loop over SEQ, BK=32.
__global__ __launch_bounds__(256) void ctx_mma_kernel(float* __restrict__ out) {
    int bh = blockIdx.z;
    int m0 = blockIdx.y * 128;
    int b = bh >> 4, h = bh & 15;

    __shared__ __align__(16) __nv_bfloat16 sPhi[128 * SSTR];
    __shared__ __align__(16) __nv_bfloat16 sPlo[128 * SSTR];
    __shared__ __align__(16) __nv_bfloat16 sVhi[64 * SSTR];
    __shared__ __align__(16) __nv_bfloat16 sVlo[64 * SSTR];
    __shared__ __align__(16) float psS[128 * 17];
    __shared__ __align__(16) float tabS[16 * 68];

    int t = threadIdx.x;
    int lane = t & 31, warp = t >> 5;
    int wy = warp >> 1, wx = warp & 1;       // 4 (m) x 2 (n)
    int g = lane >> 2, tq = (lane & 3) * 2;

    float acc[2][4][4] = {};

    for (int k0 = 0; k0 < SEQ; k0 += 32) {
        // load P tile [128][32]
        #pragma unroll
        for (int u = 0; u < 2; u++) {
            int idx = t + 256 * u;
            int r = idx >> 2, c = (idx & 3) * 8;
            size_t gp = ((size_t)bh * SEQ + m0 + r) * SEQ + k0 + c;
            uint4 v;
            v = *(const uint4*)(g_ph + gp);
            *(uint2*)&sPhi[r * SSTR + c] = make_uint2(v.x, v.y);
            *(uint2*)&sPhi[r * SSTR + c + 4] = make_uint2(v.z, v.w);
            v = *(const uint4*)(g_pl + gp);
            *(uint2*)&sPlo[r * SSTR + c] = make_uint2(v.x, v.y);
            *(uint2*)&sPlo[r * SSTR + c + 4] = make_uint2(v.z, v.w);
        }
        // load V^T tile [64][32]
        {
            int r = t >> 2, c = (t & 3) * 8;
            size_t gv = ((size_t)bh * HDIM + r) * SEQ + k0 + c;
            uint4 v;
            v = *(const uint4*)(g_vth + gv);
            *(uint2*)&sVhi[r * SSTR + c] = make_uint2(v.x, v.y);
            *(uint2*)&sVhi[r * SSTR + c + 4] = make_uint2(v.z, v.w);
            v = *(const uint4*)(g_vtl + gv);
            *(uint2*)&sVlo[r * SSTR + c] = make_uint2(v.x, v.y);
            *(uint2*)&sVlo[r * SSTR + c + 4] = make_uint2(v.z, v.w);
        }
        __syncthreads();

        #pragma unroll
        for (int kk = 0; kk < 32; kk += 16) {
            unsigned int ahi[2][4], alo[2][4];
            #pragma unroll
            for (int mt = 0; mt < 2; mt++) {
                int abase = (wy * 32 + mt * 16 + g) * SSTR + kk + tq;
                ahi[mt][0] = *(unsigned int*)&sPhi[abase];
                ahi[mt][1] = *(unsigned int*)&sPhi[abase + 8 * SSTR];
                ahi[mt][2] = *(unsigned int*)&sPhi[abase + 8];
                ahi[mt][3] = *(unsigned int*)&sPhi[abase + 8 * SSTR + 8];
                alo[mt][0] = *(unsigned int*)&sPlo[abase];
                alo[mt][1] = *(unsigned int*)&sPlo[abase + 8 * SSTR];
                alo[mt][2] = *(unsigned int*)&sPlo[abase + 8];
                alo[mt][3] = *(unsigned int*)&sPlo[abase + 8 * SSTR + 8];
            }
            #pragma unroll
            for (int nt = 0; nt < 4; nt++) {
                int bbase = (wx * 32 + nt * 8 + g) * SSTR + kk + tq;
                unsigned int bhi0 = *(unsigned int*)&sVhi[bbase];
                unsigned int bhi1 = *(unsigned int*)&sVhi[bbase + 8];
                unsigned int blo0 = *(unsigned int*)&sVlo[bbase];
                unsigned int blo1 = *(unsigned int*)&sVlo[bbase + 8];
                #pragma unroll
                for (int mt = 0; mt < 2; mt++) {
                    mma_bf16(acc[mt][nt], ahi[mt], bhi0, bhi1);
                    mma_bf16(acc[mt][nt], ahi[mt], blo0, blo1);
                    mma_bf16(acc[mt][nt], alo[mt], bhi0, bhi1);
                }
            }
        }
        __syncthreads();
    }

    // relative-value epilogue: acc += ps[q, r] * tab[r, d], staged 16 r at a time
    for (int r0 = 0; r0 < VOCAB; r0 += 16) {
        __syncthreads();
        {
            int row = t >> 1, rc0 = (t & 1) * 8;
            size_t base = ((size_t)bh * SEQ + m0 + row) * VOCAB;
            #pragma unroll
            for (int u = 0; u < 8; u++) {
                int r = r0 + rc0 + u;
                psS[row * 17 + rc0 + u] = (r < VOCAB) ? g_ps[base + r] : 0.0f;
            }
        }
        {
            int rr = t >> 4, cc = (t & 15) * 4;
            int r = r0 + rr;
            float4 tv = (r < VOCAB) ? *(const float4*)&g_tab[r * 64 + cc]
                                    : make_float4(0.f, 0.f, 0.f, 0.f);
            *(float4*)&tabS[rr * 68 + cc] = tv;
        }
        __syncthreads();
        #pragma unroll
        for (int rc = 0; rc < 16; rc++) {
            float pr[2][2];
            #pragma unroll
            for (int mt = 0; mt < 2; mt++) {
                int rbase = (wy * 32 + mt * 16 + g) * 17 + rc;
                pr[mt][0] = psS[rbase];
                pr[mt][1] = psS[rbase + 8 * 17];
            }
            #pragma unroll
            for (int nt = 0; nt < 4; nt++) {
                int col = wx * 32 + nt * 8 + tq;
                float t0 = tabS[rc * 68 + col];
                float t1 = tabS[rc * 68 + col + 1];
                #pragma unroll
                for (int mt = 0; mt < 2; mt++) {
                    acc[mt][nt][0] += pr[mt][0] * t0;
                    acc[mt][nt][1] += pr[mt][0] * t1;
                    acc[mt][nt][2] += pr[mt][1] * t0;
                    acc[mt][nt][3] += pr[mt][1] * t1;
                }
            }
        }
    }

    // write out [b][s][h*64+d]
    #pragma unroll
    for (int nt = 0; nt < 4; nt++) {
        int d = wx * 32 + nt * 8 + tq;
        #pragma unroll
        for (int mt = 0; mt < 2; mt++) {
            int q0 = m0 + wy * 32 + mt * 16 + g;
            *(float2*)(out + ((size_t)(b * SEQ + q0)) * HID + h * 64 + d) =
                make_float2(acc[mt][nt][0], acc[mt][nt][1]);
            *(float2*)(out + ((size_t)(b * SEQ + q0 + 8)) * HID + h * 64 + d) =
                make_float2(acc[mt][nt][2], acc[mt][nt][3]);
        }
    }
}

// ---------------- launcher ----------------
extern "C" void kernel_launch(void* const* d_in, const int* in_sizes, int n_in,
                              void* d_out, int out_size) {
    const float* hs   = (const float*)d_in[0];
    const float* mask = (const float*)d_in[1];
    const float* Wq   = (const float*)d_in[2];
    const float* bq   = (const float*)d_in[3];
    const float* Wk   = (const float*)d_in[4];
    const float* bk   = (const float*)d_in[5];
    const float* Wv   = (const float*)d_in[6];
    const float* bv   = (const float*)d_in[7];
    float* out = (float*)d_out;

    init_tab_kernel<<<(VOCAB * 32 + 127) / 128, 128>>>();
    cvt_hs_kernel<<<(BATCH * SEQ * HID / 4 + 255) / 256, 256>>>(hs);
    cvt_w_kernel<<<(3 * HID * HID / 4 + 255) / 256, 256>>>(Wq, Wk, Wv);
    qkv_mma_kernel<<<dim3(HID / 128, (BATCH * SEQ) / 128, 3), 256>>>(bq, bk, bv);
    qrel_kernel<<<BH * SEQ, 128>>>();
    scores_mma_kernel<<<dim3(SEQ / 128, SEQ / 128, BH), 256>>>(mask);
    softmax_kernel<<<BH * SEQ, 256>>>();
    ctx_mma_kernel<<<dim3(1, SEQ / 128, BH), 256>>>(out);
}

// round 6
// speedup vs baseline: 1.4436x; 1.0334x over previous
#include <cuda_runtime.h>
#include <cuda_bf16.h>
#include <cstdint>

#define BATCH 2
#define SEQ   1024
#define HID   1024
#define NHEAD 16
#define HDIM  64
#define BH    (BATCH*NHEAD)      // 32
#define VOCAB 129                // 2*64+1
#define SSTR  40                 // bf16 smem stride (BK=32 tiles): conflict-free
#define SST2  72                 // bf16 smem stride (K=64 tiles): conflict-free

// ---------------- scratch (device globals; no allocation allowed) ----------------
__device__ __align__(16) float g_qkv[BH * SEQ * HDIM];           // Q fp32 (for qrel)
__device__ __align__(16) float g_scores[(size_t)BH * SEQ * SEQ]; // fp32 scores
__device__ __align__(16) float g_qrel[(size_t)BH * SEQ * VOCAB];
__device__ __align__(16) float g_ps[(size_t)BH * SEQ * VOCAB];
__device__ __align__(16) float g_tab[VOCAB * HDIM];

// split-bf16 operands
__device__ __align__(16) __nv_bfloat16 g_hs_hi[BATCH * SEQ * HID];
__device__ __align__(16) __nv_bfloat16 g_hs_lo[BATCH * SEQ * HID];
__device__ __align__(16) __nv_bfloat16 g_w_hi[3 * HID * HID];
__device__ __align__(16) __nv_bfloat16 g_w_lo[3 * HID * HID];
__device__ __align__(16) __nv_bfloat16 g_qh[BH * SEQ * HDIM];
__device__ __align__(16) __nv_bfloat16 g_ql[BH * SEQ * HDIM];
__device__ __align__(16) __nv_bfloat16 g_kh[BH * SEQ * HDIM];
__device__ __align__(16) __nv_bfloat16 g_kl[BH * SEQ * HDIM];
__device__ __align__(16) __nv_bfloat16 g_vth[BH * HDIM * SEQ];   // V^T [bh][d][s]
__device__ __align__(16) __nv_bfloat16 g_vtl[BH * HDIM * SEQ];
__device__ __align__(16) __nv_bfloat16 g_ph[(size_t)BH * SEQ * SEQ]; // probs hi
__device__ __align__(16) __nv_bfloat16 g_pl[(size_t)BH * SEQ * SEQ]; // probs lo

// ---------------- helpers ----------------
__device__ __forceinline__ void cp_async16(void* dst, const void* src) {
    unsigned int d = (unsigned int)__cvta_generic_to_shared(dst);
    asm volatile("cp.async.cg.shared.global [%0], [%1], 16;" :: "r"(d), "l"(src));
}
__device__ __forceinline__ void cp_commit() { asm volatile("cp.async.commit_group;"); }
__device__ __forceinline__ void cp_wait0()  { asm volatile("cp.async.wait_group 0;"); }
__device__ __forceinline__ void cp_wait1()  { asm volatile("cp.async.wait_group 1;"); }

__device__ __forceinline__ void split_bf16(float v, __nv_bfloat16& hi, __nv_bfloat16& lo) {
    hi = __float2bfloat16_rn(v);
    lo = __float2bfloat16_rn(v - __bfloat162float(hi));
}

__device__ __forceinline__ void mma_bf16(float* c, const unsigned int* A,
                                         unsigned int b0, unsigned int b1) {
    asm volatile("mma.sync.aligned.m16n8k16.row.col.f32.bf16.bf16.f32 "
        "{%0,%1,%2,%3}, {%4,%5,%6,%7}, {%8,%9}, {%0,%1,%2,%3};"
        : "+f"(c[0]), "+f"(c[1]), "+f"(c[2]), "+f"(c[3])
        : "r"(A[0]), "r"(A[1]), "r"(A[2]), "r"(A[3]), "r"(b0), "r"(b1));
}

// ---------------- sinusoid table ----------------
__global__ void init_tab_kernel() {
    int idx = blockIdx.x * blockDim.x + threadIdx.x;
    if (idx >= VOCAB * 32) return;
    int p = idx >> 5, i = idx & 31;
    float div = expf((float)(2 * i) * (-9.210340371976184f / 64.0f));
    float ang = (float)p * div;
    g_tab[p * 64 + 2 * i]     = sinf(ang);
    g_tab[p * 64 + 2 * i + 1] = cosf(ang);
}

__global__ __launch_bounds__(256) void cvt_hs_kernel(const float* __restrict__ hs) {
    int i = (blockIdx.x * blockDim.x + threadIdx.x) * 4;
    if (i >= BATCH * SEQ * HID) return;
    float4 v = *(const float4*)(hs + i);
    __nv_bfloat16 h, l;
    split_bf16(v.x, h, l); g_hs_hi[i + 0] = h; g_hs_lo[i + 0] = l;
    split_bf16(v.y, h, l); g_hs_hi[i + 1] = h; g_hs_lo[i + 1] = l;
    split_bf16(v.z, h, l); g_hs_hi[i + 2] = h; g_hs_lo[i + 2] = l;
    split_bf16(v.w, h, l); g_hs_hi[i + 3] = h; g_hs_lo[i + 3] = l;
}

__global__ __launch_bounds__(256) void cvt_w_kernel(
    const float* __restrict__ Wq, const float* __restrict__ Wk, const float* __restrict__ Wv) {
    int i = (blockIdx.x * blockDim.x + threadIdx.x) * 4;
    if (i >= 3 * HID * HID) return;
    int z = i / (HID * HID), r = i - z * (HID * HID);
    const float* W = (z == 0) ? Wq : (z == 1 ? Wk : Wv);
    float4 v = *(const float4*)(W + r);
    __nv_bfloat16 h, l;
    split_bf16(v.x, h, l); g_w_hi[i + 0] = h; g_w_lo[i + 0] = l;
    split_bf16(v.y, h, l); g_w_hi[i + 1] = h; g_w_lo[i + 1] = l;
    split_bf16(v.z, h, l); g_w_hi[i + 2] = h; g_w_lo[i + 2] = l;
    split_bf16(v.w, h, l); g_w_hi[i + 3] = h; g_w_lo[i + 3] = l;
}

// ---------------- phase 1: QKV projection, cp.async double-buffered MMA ----------------
#define QKV_AS    (128 * SSTR)        // elements per array
#define QKV_STAGE (4 * QKV_AS)        // elements per stage
#define QKV_SMEM  (2 * QKV_STAGE * 2) // bytes (81920)

__global__ __launch_bounds__(256) void qkv_mma_kernel(
    const float* __restrict__ bq, const float* __restrict__ bk, const float* __restrict__ bv)
{
    extern __shared__ __align__(16) __nv_bfloat16 dsm[];
    int z = blockIdx.z;
    const float* bias = (z == 0) ? bq : (z == 1 ? bk : bv);
    const __nv_bfloat16* gWhi = g_w_hi + (size_t)z * HID * HID;
    const __nv_bfloat16* gWlo = g_w_lo + (size_t)z * HID * HID;

    int m0 = blockIdx.y * 128, n0 = blockIdx.x * 128;
    int t = threadIdx.x;
    int lane = t & 31, warp = t >> 5;
    int wy = warp >> 2, wx = warp & 3;
    int g = lane >> 2, tq = (lane & 3) * 2;

    float acc[4][4][4] = {};

    auto load_stage = [&](int stg, int k0) {
        __nv_bfloat16* base = dsm + stg * QKV_STAGE;
        #pragma unroll
        for (int u = 0; u < 2; u++) {
            int idx = t + 256 * u;
            int r = idx >> 2, ce = (idx & 3) * 8;
            size_t ga = (size_t)(m0 + r) * HID + k0 + ce;
            size_t gb = (size_t)(n0 + r) * HID + k0 + ce;
            int so = r * SSTR + ce;
            cp_async16(base + 0 * QKV_AS + so, g_hs_hi + ga);
            cp_async16(base + 1 * QKV_AS + so, g_hs_lo + ga);
            cp_async16(base + 2 * QKV_AS + so, gWhi + gb);
            cp_async16(base + 3 * QKV_AS + so, gWlo + gb);
        }
    };

    load_stage(0, 0);
    cp_commit();

    for (int k0 = 0; k0 < HID; k0 += 32) {
        int stg = (k0 >> 5) & 1;
        if (k0 + 32 < HID) { load_stage(stg ^ 1, k0 + 32); cp_commit(); cp_wait1(); }
        else               { cp_wait0(); }
        __syncthreads();
        const __nv_bfloat16* sAhi = dsm + stg * QKV_STAGE;
        const __nv_bfloat16* sAlo = sAhi + QKV_AS;
        const __nv_bfloat16* sBhi = sAlo + QKV_AS;
        const __nv_bfloat16* sBlo = sBhi + QKV_AS;

        #pragma unroll
        for (int kk = 0; kk < 32; kk += 16) {
            unsigned int ahi[4][4], alo[4][4];
            #pragma unroll
            for (int mt = 0; mt < 4; mt++) {
                int abase = (wy * 64 + mt * 16 + g) * SSTR + kk + tq;
                ahi[mt][0] = *(unsigned int*)&sAhi[abase];
                ahi[mt][1] = *(unsigned int*)&sAhi[abase + 8 * SSTR];
                ahi[mt][2] = *(unsigned int*)&sAhi[abase + 8];
                ahi[mt][3] = *(unsigned int*)&sAhi[abase + 8 * SSTR + 8];
                alo[mt][0] = *(unsigned int*)&sAlo[abase];
                alo[mt][1] = *(unsigned int*)&sAlo[abase + 8 * SSTR];
                alo[mt][2] = *(unsigned int*)&sAlo[abase + 8];
                alo[mt][3] = *(unsigned int*)&sAlo[abase + 8 * SSTR + 8];
            }
            #pragma unroll
            for (int nt = 0; nt < 4; nt++) {
                int bbase = (wx * 32 + nt * 8 + g) * SSTR + kk + tq;
                unsigned int bhi0 = *(unsigned int*)&sBhi[bbase];
                unsigned int bhi1 = *(unsigned int*)&sBhi[bbase + 8];
                unsigned int blo0 = *(unsigned int*)&sBlo[bbase];
                unsigned int blo1 = *(unsigned int*)&sBlo[bbase + 8];
                #pragma unroll
                for (int mt = 0; mt < 4; mt++) {
                    mma_bf16(acc[mt][nt], ahi[mt], bhi0, bhi1);
                    mma_bf16(acc[mt][nt], ahi[mt], blo0, blo1);
                    mma_bf16(acc[mt][nt], alo[mt], bhi0, bhi1);
                }
            }
        }
        __syncthreads();
    }

    // epilogue: bias, then emit bf16 hi/lo operands (and fp32 Q for qrel)
    #pragma unroll
    for (int nt = 0; nt < 4; nt++) {
        int n = n0 + wx * 32 + nt * 8 + tq;
        float2 b2 = *(const float2*)&bias[n];
        int h = n >> 6, d = n & 63;
        #pragma unroll
        for (int mt = 0; mt < 4; mt++) {
            int m = m0 + wy * 64 + mt * 16 + g;
            int b = m >> 10, s = m & (SEQ - 1);
            int bh = b * NHEAD + h;
            float v0 = acc[mt][nt][0] + b2.x, v1 = acc[mt][nt][1] + b2.y;
            float v2 = acc[mt][nt][2] + b2.x, v3 = acc[mt][nt][3] + b2.y;
            __nv_bfloat16 h0, l0, h1, l1, h2, l2, h3, l3;
            split_bf16(v0, h0, l0); split_bf16(v1, h1, l1);
            split_bf16(v2, h2, l2); split_bf16(v3, h3, l3);
            if (z < 2) {
                __nv_bfloat16* ah = (z == 0) ? g_qh : g_kh;
                __nv_bfloat16* al = (z == 0) ? g_ql : g_kl;
                size_t o0 = ((size_t)bh * SEQ + s) * HDIM + d;
                size_t o1 = o0 + 8 * HDIM;
                *(__nv_bfloat162*)(ah + o0) = __nv_bfloat162(h0, h1);
                *(__nv_bfloat162*)(al + o0) = __nv_bfloat162(l0, l1);
                *(__nv_bfloat162*)(ah + o1) = __nv_bfloat162(h2, h3);
                *(__nv_bfloat162*)(al + o1) = __nv_bfloat162(l2, l3);
                if (z == 0) {
                    *(float2*)(g_qkv + o0) = make_float2(v0, v1);
                    *(float2*)(g_qkv + o1) = make_float2(v2, v3);
                }
            } else {
                size_t base = ((size_t)bh * HDIM + d) * SEQ + s;   // [bh][d][s]
                g_vth[base] = h0;           g_vtl[base] = l0;
                g_vth[base + SEQ] = h1;     g_vtl[base + SEQ] = l1;
                g_vth[base + 8] = h2;       g_vtl[base + 8] = l2;
                g_vth[base + SEQ + 8] = h3; g_vtl[base + SEQ + 8] = l3;
            }
        }
    }
}

// ---------------- phase 1.5: qrel ----------------
__global__ __launch_bounds__(128) void qrel_kernel() {
    int row = blockIdx.x;
    __shared__ float qrow[64];
    const float* Q = g_qkv + (size_t)row * HDIM;
    if (threadIdx.x < 64) qrow[threadIdx.x] = Q[threadIdx.x];
    __syncthreads();
    for (int r = threadIdx.x; r < VOCAB; r += 128) {
        float s = 0.0f;
        #pragma unroll
        for (int d = 0; d < 64; d++) s += qrow[d] * g_tab[r * 64 + d];
        g_qrel[(size_t)row * VOCAB + r] = s;
    }
}

// ---------------- phase 2: scores, full-K prefetch MMA ----------------
#define SC_AS   (128 * SST2)          // elements per array (full K=64)
#define SC_SMEM (4 * SC_AS * 2)       // bytes (73728)

__global__ __launch_bounds__(256) void scores_mma_kernel(const float* __restrict__ mask) {
    extern __shared__ __align__(16) __nv_bfloat16 dsm[];
    int bh = blockIdx.z, b = bh >> 4;
    int m0 = blockIdx.y * 128, n0 = blockIdx.x * 128;

    int t = threadIdx.x;
    int lane = t & 31, warp = t >> 5;
    int wy = warp >> 2, wx = warp & 3;
    int g = lane >> 2, tq = (lane & 3) * 2;

    __nv_bfloat16* sAhi = dsm;
    __nv_bfloat16* sAlo = sAhi + SC_AS;
    __nv_bfloat16* sBhi = sAlo + SC_AS;
    __nv_bfloat16* sBlo = sBhi + SC_AS;

    // prefetch the whole 128x64 hi/lo Q and K tiles
    #pragma unroll
    for (int u = 0; u < 4; u++) {
        int idx = t + 256 * u;
        int r = idx >> 3, ce = (idx & 7) * 8;
        size_t ga = ((size_t)bh * SEQ + m0 + r) * HDIM + ce;
        size_t gb = ((size_t)bh * SEQ + n0 + r) * HDIM + ce;
        int so = r * SST2 + ce;
        cp_async16(sAhi + so, g_qh + ga);
        cp_async16(sAlo + so, g_ql + ga);
        cp_async16(sBhi + so, g_kh + gb);
        cp_async16(sBlo + so, g_kl + gb);
    }
    cp_commit();

    float acc[4][4][4] = {};
    cp_wait0();
    __syncthreads();

    #pragma unroll
    for (int kk = 0; kk < 64; kk += 16) {
        unsigned int ahi[4][4], alo[4][4];
        #pragma unroll
        for (int mt = 0; mt < 4; mt++) {
            int abase = (wy * 64 + mt * 16 + g) * SST2 + kk + tq;
            ahi[mt][0] = *(unsigned int*)&sAhi[abase];
            ahi[mt][1] = *(unsigned int*)&sAhi[abase + 8 * SST2];
            ahi[mt][2] = *(unsigned int*)&sAhi[abase + 8];
            ahi[mt][3] = *(unsigned int*)&sAhi[abase + 8 * SST2 + 8];
            alo[mt][0] = *(unsigned int*)&sAlo[abase];
            alo[mt][1] = *(unsigned int*)&sAlo[abase + 8 * SST2];
            alo[mt][2] = *(unsigned int*)&sAlo[abase + 8];
            alo[mt][3] = *(unsigned int*)&sAlo[abase + 8 * SST2 + 8];
        }
        #pragma unroll
        for (int nt = 0; nt < 4; nt++) {
            int bbase = (wx * 32 + nt * 8 + g) * SST2 + kk + tq;
            unsigned int bhi0 = *(unsigned int*)&sBhi[bbase];
            unsigned int bhi1 = *(unsigned int*)&sBhi[bbase + 8];
            unsigned int blo0 = *(unsigned int*)&sBlo[bbase];
            unsigned int blo1 = *(unsigned int*)&sBlo[bbase + 8];
            #pragma unroll
            for (int mt = 0; mt < 4; mt++) {
                mma_bf16(acc[mt][nt], ahi[mt], bhi0, bhi1);
                mma_bf16(acc[mt][nt], ahi[mt], blo0, blo1);
                mma_bf16(acc[mt][nt], alo[mt], bhi0, bhi1);
            }
        }
    }

    // epilogue: + qrel(dist), /8, + mask
    #pragma unroll
    for (int nt = 0; nt < 4; nt++) {
        int n = n0 + wx * 32 + nt * 8 + tq;
        float mk0 = mask[b * SEQ + n], mk1 = mask[b * SEQ + n + 1];
        #pragma unroll
        for (int mt = 0; mt < 4; mt++) {
            int q0 = m0 + wy * 64 + mt * 16 + g;
            #pragma unroll
            for (int hrow = 0; hrow < 2; hrow++) {
                int q = q0 + hrow * 8;
                const float* qr = g_qrel + ((size_t)bh * SEQ + q) * VOCAB;
                int d0 = n - q;     d0 = d0 < -64 ? -64 : (d0 > 64 ? 64 : d0);
                int d1 = n + 1 - q; d1 = d1 < -64 ? -64 : (d1 > 64 ? 64 : d1);
                float r0 = (acc[mt][nt][hrow * 2 + 0] + qr[d0 + 64]) * 0.125f + mk0;
                float r1 = (acc[mt][nt][hrow * 2 + 1] + qr[d1 + 64]) * 0.125f + mk1;
                *(float2*)(g_scores + ((size_t)bh * SEQ + q) * SEQ + n) = make_float2(r0, r1);
            }
        }
    }
}

// ---------------- phase 3: row softmax -> bf16 hi/lo probs + ps buckets ----------------
__global__ __launch_bounds__(256) void softmax_kernel() {
    int row = blockIdx.x;
    int q = row & (SEQ - 1);
    const float* x = g_scores + (size_t)row * SEQ;
    __shared__ float sm[SEQ];
    __shared__ float red[16];
    __shared__ float bc[4];
    int t = threadIdx.x;
    int lane = t & 31, warp = t >> 5;

    float v[4];
    float mx = -3.4e38f;
    #pragma unroll
    for (int u = 0; u < 4; u++) { v[u] = x[t + 256 * u]; mx = fmaxf(mx, v[u]); }
    #pragma unroll
    for (int o = 16; o > 0; o >>= 1) mx = fmaxf(mx, __shfl_xor_sync(0xffffffffu, mx, o));
    if (lane == 0) red[warp] = mx;
    __syncthreads();
    if (t == 0) { float m = red[0]; for (int w = 1; w < 8; w++) m = fmaxf(m, red[w]); bc[0] = m; }
    __syncthreads();
    mx = bc[0];

    float s = 0.0f;
    #pragma unroll
    for (int u = 0; u < 4; u++) { v[u] = expf(v[u] - mx); s += v[u]; }
    #pragma unroll
    for (int o = 16; o > 0; o >>= 1) s += __shfl_xor_sync(0xffffffffu, s, o);
    __syncthreads();
    if (lane == 0) red[warp] = s;
    __syncthreads();
    if (t == 0) { float m = 0; for (int w = 0; w < 8; w++) m += red[w]; bc[1] = m; }
    __syncthreads();
    float inv = 1.0f / bc[1];

    float lo = 0.0f, hi = 0.0f;
    size_t pbase = (size_t)row * SEQ;
    #pragma unroll
    for (int u = 0; u < 4; u++) {
        int k = t + 256 * u;
        float p = v[u] * inv;
        sm[k] = p;
        __nv_bfloat16 ph, pl;
        split_bf16(p, ph, pl);
        g_ph[pbase + k] = ph;
        g_pl[pbase + k] = pl;
        if (k <= q - 64) lo += p;
        if (k >= q + 64) hi += p;
    }
    #pragma unroll
    for (int o = 16; o > 0; o >>= 1) {
        lo += __shfl_xor_sync(0xffffffffu, lo, o);
        hi += __shfl_xor_sync(0xffffffffu, hi, o);
    }
    __syncthreads();
    if (lane == 0) { red[warp] = lo; red[warp + 8] = hi; }
    __syncthreads();
    if (t == 0) {
        float a = 0, b2 = 0;
        for (int w = 0; w < 8; w++) { a += red[w]; b2 += red[w + 8]; }
        bc[2] = a; bc[3] = b2;
    }
    __syncthreads();

    float* psr = g_ps + (size_t)row * VOCAB;
    if (t == 0)   psr[0]   = bc[2];
    if (t == 128) psr[128] = bc[3];
    if (t >= 1 && t < 128) {
        int k = q + t - 64;
        psr[t] = (k >= 0 && k < SEQ) ? sm[k] : 0.0f;
    }
}

// ---------------- phase 4: ctx = P @ V (cp.async double-buffered) + ps @ tab ----------------
#define CTX_PAS   (128 * SSTR)
#define CTX_VAS   (64 * SSTR)
#define CTX_STAGE (2 * CTX_PAS + 2 * CTX_VAS)
#define CTX_SMEM  (2 * CTX_STAGE * 2)   // bytes (61440)

__global__ __launch_bounds__(256) void ctx_mma_kernel(float* __restrict__ out) {
    extern __shared__ __align__(16) __nv_bfloat16 dsm[];
    __shared__ __align__(16) float psS[128 * 17];
    __shared__ __align__(16) float tabS[16 * 68];

    int bh = blockIdx.z;
    int m0 = blockIdx.y * 128;
    int b = bh >> 4, h = bh & 15;

    int t = threadIdx.x;
    int lane = t & 31, warp = t >> 5;
    int wy = warp >> 1, wx = warp & 1;       // 4 (m) x 2 (n)
    int g = lane >> 2, tq = (lane & 3) * 2;

    float acc[2][4][4] = {};

    auto load_stage = [&](int stg, int k0) {
        __nv_bfloat16* base = dsm + stg * CTX_STAGE;
        __nv_bfloat16* pPhi = base;
        __nv_bfloat16* pPlo = base + CTX_PAS;
        __nv_bfloat16* pVhi = base + 2 * CTX_PAS;
        __nv_bfloat16* pVlo = pVhi + CTX_VAS;
        #pragma unroll
        for (int u = 0; u < 2; u++) {
            int idx = t + 256 * u;
            int r = idx >> 2, ce = (idx & 3) * 8;
            size_t gp = ((size_t)bh * SEQ + m0 + r) * SEQ + k0 + ce;
            int so = r * SSTR + ce;
            cp_async16(pPhi + so, g_ph + gp);
            cp_async16(pPlo + so, g_pl + gp);
        }
        {
            int r = t >> 2, ce = (t & 3) * 8;
            size_t gv = ((size_t)bh * HDIM + r) * SEQ + k0 + ce;
            int so = r * SSTR + ce;
            cp_async16(pVhi + so, g_vth + gv);
            cp_async16(pVlo + so, g_vtl + gv);
        }
    };

    load_stage(0, 0);
    cp_commit();

    for (int k0 = 0; k0 < SEQ; k0 += 32) {
        int stg = (k0 >> 5) & 1;
        if (k0 + 32 < SEQ) { load_stage(stg ^ 1, k0 + 32); cp_commit(); cp_wait1(); }
        else               { cp_wait0(); }
        __syncthreads();
        const __nv_bfloat16* sPhi = dsm + stg * CTX_STAGE;
        const __nv_bfloat16* sPlo = sPhi + CTX_PAS;
        const __nv_bfloat16* sVhi = sPlo + CTX_PAS;
        const __nv_bfloat16* sVlo = sVhi + CTX_VAS;

        #pragma unroll
        for (int kk = 0; kk < 32; kk += 16) {
            unsigned int ahi[2][4], alo[2][4];
            #pragma unroll
            for (int mt = 0; mt < 2; mt++) {
                int abase = (wy * 32 + mt * 16 + g) * SSTR + kk + tq;
                ahi[mt][0] = *(unsigned int*)&sPhi[abase];
                ahi[mt][1] = *(unsigned int*)&sPhi[abase + 8 * SSTR];
                ahi[mt][2] = *(unsigned int*)&sPhi[abase + 8];
                ahi[mt][3] = *(unsigned int*)&sPhi[abase + 8 * SSTR + 8];
                alo[mt][0] = *(unsigned int*)&sPlo[abase];
                alo[mt][1] = *(unsigned int*)&sPlo[abase + 8 * SSTR];
                alo[mt][2] = *(unsigned int*)&sPlo[abase + 8];
                alo[mt][3] = *(unsigned int*)&sPlo[abase + 8 * SSTR + 8];
            }
            #pragma unroll
            for (int nt = 0; nt < 4; nt++) {
                int bbase = (wx * 32 + nt * 8 + g) * SSTR + kk + tq;
                unsigned int bhi0 = *(unsigned int*)&sVhi[bbase];
                unsigned int bhi1 = *(unsigned int*)&sVhi[bbase + 8];
                unsigned int blo0 = *(unsigned int*)&sVlo[bbase];
                unsigned int blo1 = *(unsigned int*)&sVlo[bbase + 8];
                #pragma unroll
                for (int mt = 0; mt < 2; mt++) {
                    mma_bf16(acc[mt][nt], ahi[mt], bhi0, bhi1);
                    mma_bf16(acc[mt][nt], ahi[mt], blo0, blo1);
                    mma_bf16(acc[mt][nt], alo[mt], bhi0, bhi1);
                }
            }
        }
        __syncthreads();
    }

    // relative-value epilogue: acc += ps[q, r] * tab[r, d]
    for (int r0 = 0; r0 < VOCAB; r0 += 16) {
        __syncthreads();
        {
            int row = t >> 1, rc0 = (t & 1) * 8;
            size_t base = ((size_t)bh * SEQ + m0 + row) * VOCAB;
            #pragma unroll
            for (int u = 0; u < 8; u++) {
                int r = r0 + rc0 + u;
                psS[row * 17 + rc0 + u] = (r < VOCAB) ? g_ps[base + r] : 0.0f;
            }
        }
        {
            int rr = t >> 4, cc = (t & 15) * 4;
            int r = r0 + rr;
            float4 tv = (r < VOCAB) ? *(const float4*)&g_tab[r * 64 + cc]
                                    : make_float4(0.f, 0.f, 0.f, 0.f);
            *(float4*)&tabS[rr * 68 + cc] = tv;
        }
        __syncthreads();
        #pragma unroll
        for (int rc = 0; rc < 16; rc++) {
            float pr[2][2];
            #pragma unroll
            for (int mt = 0; mt < 2; mt++) {
                int rbase = (wy * 32 + mt * 16 + g) * 17 + rc;
                pr[mt][0] = psS[rbase];
                pr[mt][1] = psS[rbase + 8 * 17];
            }
            #pragma unroll
            for (int nt = 0; nt < 4; nt++) {
                int col = wx * 32 + nt * 8 + tq;
                float t0 = tabS[rc * 68 + col];
                float t1 = tabS[rc * 68 + col + 1];
                #pragma unroll
                for (int mt = 0; mt < 2; mt++) {
                    acc[mt][nt][0] += pr[mt][0] * t0;
                    acc[mt][nt][1] += pr[mt][0] * t1;
                    acc[mt][nt][2] += pr[mt][1] * t0;
                    acc[mt][nt][3] += pr[mt][1] * t1;
                }
            }
        }
    }

    // write out [b][s][h*64+d]
    #pragma unroll
    for (int nt = 0; nt < 4; nt++) {
        int d = wx * 32 + nt * 8 + tq;
        #pragma unroll
        for (int mt = 0; mt < 2; mt++) {
            int q0 = m0 + wy * 32 + mt * 16 + g;
            *(float2*)(out + ((size_t)(b * SEQ + q0)) * HID + h * 64 + d) =
                make_float2(acc[mt][nt][0], acc[mt][nt][1]);
            *(float2*)(out + ((size_t)(b * SEQ + q0 + 8)) * HID + h * 64 + d) =
                make_float2(acc[mt][nt][2], acc[mt][nt][3]);
        }
    }
}

// ---------------- launcher ----------------
extern "C" void kernel_launch(void* const* d_in, const int* in_sizes, int n_in,
                              void* d_out, int out_size) {
    const float* hs   = (const float*)d_in[0];
    const float* mask = (const float*)d_in[1];
    const float* Wq   = (const float*)d_in[2];
    const float* bq   = (const float*)d_in[3];
    const float* Wk   = (const float*)d_in[4];
    const float* bk   = (const float*)d_in[5];
    const float* Wv   = (const float*)d_in[6];
    const float* bv   = (const float*)d_in[7];
    float* out = (float*)d_out;

    cudaFuncSetAttribute(qkv_mma_kernel,    cudaFuncAttributeMaxDynamicSharedMemorySize, QKV_SMEM);
    cudaFuncSetAttribute(scores_mma_kernel, cudaFuncAttributeMaxDynamicSharedMemorySize, SC_SMEM);
    cudaFuncSetAttribute(ctx_mma_kernel,    cudaFuncAttributeMaxDynamicSharedMemorySize, CTX_SMEM);

    init_tab_kernel<<<(VOCAB * 32 + 127) / 128, 128>>>();
    cvt_hs_kernel<<<(BATCH * SEQ * HID / 4 + 255) / 256, 256>>>(hs);
    cvt_w_kernel<<<(3 * HID * HID / 4 + 255) / 256, 256>>>(Wq, Wk, Wv);
    qkv_mma_kernel<<<dim3(HID / 128, (BATCH * SEQ) / 128, 3), 256, QKV_SMEM>>>(bq, bk, bv);
    qrel_kernel<<<BH * SEQ, 128>>>();
    scores_mma_kernel<<<dim3(SEQ / 128, SEQ / 128, BH), 256, SC_SMEM>>>(mask);
    softmax_kernel<<<BH * SEQ, 256>>>();
    ctx_mma_kernel<<<dim3(1, SEQ / 128, BH), 256, CTX_SMEM>>>(out);
}

// round 7
// speedup vs baseline: 1.5915x; 1.1025x over previous
#include <cuda_runtime.h>
#include <cuda_bf16.h>
#include <cstdint>

#define BATCH 2
#define SEQ   1024
#define HID   1024
#define NHEAD 16
#define HDIM  64
#define BH    (BATCH*NHEAD)      // 32
#define VOCAB 129                // 2*64+1
#define SSTR  40                 // bf16 smem stride (BK=32 tiles)
#define SST2  72                 // bf16 smem stride (64-col tiles)

// ---------------- scratch ----------------
__device__ __align__(16) float g_qkv[BH * SEQ * HDIM];           // Q fp32 (for qrel)
__device__ __align__(16) float g_qrel[(size_t)BH * SEQ * VOCAB];
__device__ __align__(16) float g_tab[VOCAB * HDIM];

__device__ __align__(16) __nv_bfloat16 g_hs_hi[BATCH * SEQ * HID];
__device__ __align__(16) __nv_bfloat16 g_hs_lo[BATCH * SEQ * HID];
__device__ __align__(16) __nv_bfloat16 g_w_hi[3 * HID * HID];
__device__ __align__(16) __nv_bfloat16 g_w_lo[3 * HID * HID];
__device__ __align__(16) __nv_bfloat16 g_qh[BH * SEQ * HDIM];
__device__ __align__(16) __nv_bfloat16 g_ql[BH * SEQ * HDIM];
__device__ __align__(16) __nv_bfloat16 g_kh[BH * SEQ * HDIM];
__device__ __align__(16) __nv_bfloat16 g_kl[BH * SEQ * HDIM];
__device__ __align__(16) __nv_bfloat16 g_vth[BH * HDIM * SEQ];   // V^T [bh][d][s]
__device__ __align__(16) __nv_bfloat16 g_vtl[BH * HDIM * SEQ];

// ---------------- helpers ----------------
__device__ __forceinline__ void cp_async16(void* dst, const void* src) {
    unsigned int d = (unsigned int)__cvta_generic_to_shared(dst);
    asm volatile("cp.async.cg.shared.global [%0], [%1], 16;" :: "r"(d), "l"(src));
}
__device__ __forceinline__ void cp_commit() { asm volatile("cp.async.commit_group;"); }
__device__ __forceinline__ void cp_wait0()  { asm volatile("cp.async.wait_group 0;"); }
__device__ __forceinline__ void cp_wait1()  { asm volatile("cp.async.wait_group 1;"); }

__device__ __forceinline__ void split_bf16(float v, __nv_bfloat16& hi, __nv_bfloat16& lo) {
    hi = __float2bfloat16_rn(v);
    lo = __float2bfloat16_rn(v - __bfloat162float(hi));
}
__device__ __forceinline__ unsigned pack2h(float a, float b) {
    __nv_bfloat162 p(__float2bfloat16_rn(a), __float2bfloat16_rn(b));
    return *(unsigned*)&p;
}
__device__ __forceinline__ unsigned pack2l(float a, float b) {
    float ra = a - __bfloat162float(__float2bfloat16_rn(a));
    float rb = b - __bfloat162float(__float2bfloat16_rn(b));
    __nv_bfloat162 p(__float2bfloat16_rn(ra), __float2bfloat16_rn(rb));
    return *(unsigned*)&p;
}
__device__ __forceinline__ float quadmax(float v) {
    v = fmaxf(v, __shfl_xor_sync(0xffffffffu, v, 1));
    v = fmaxf(v, __shfl_xor_sync(0xffffffffu, v, 2));
    return v;
}
__device__ __forceinline__ float quadsum(float v) {
    v += __shfl_xor_sync(0xffffffffu, v, 1);
    v += __shfl_xor_sync(0xffffffffu, v, 2);
    return v;
}
__device__ __forceinline__ void mma_bf16(float* c, const unsigned int* A,
                                         unsigned int b0, unsigned int b1) {
    asm volatile("mma.sync.aligned.m16n8k16.row.col.f32.bf16.bf16.f32 "
        "{%0,%1,%2,%3}, {%4,%5,%6,%7}, {%8,%9}, {%0,%1,%2,%3};"
        : "+f"(c[0]), "+f"(c[1]), "+f"(c[2]), "+f"(c[3])
        : "r"(A[0]), "r"(A[1]), "r"(A[2]), "r"(A[3]), "r"(b0), "r"(b1));
}

// ---------------- sinusoid table ----------------
__global__ void init_tab_kernel() {
    int idx = blockIdx.x * blockDim.x + threadIdx.x;
    if (idx >= VOCAB * 32) return;
    int p = idx >> 5, i = idx & 31;
    float div = expf((float)(2 * i) * (-9.210340371976184f / 64.0f));
    float ang = (float)p * div;
    g_tab[p * 64 + 2 * i]     = sinf(ang);
    g_tab[p * 64 + 2 * i + 1] = cosf(ang);
}

__global__ __launch_bounds__(256) void cvt_hs_kernel(const float* __restrict__ hs) {
    int i = (blockIdx.x * blockDim.x + threadIdx.x) * 4;
    if (i >= BATCH * SEQ * HID) return;
    float4 v = *(const float4*)(hs + i);
    __nv_bfloat16 h, l;
    split_bf16(v.x, h, l); g_hs_hi[i + 0] = h; g_hs_lo[i + 0] = l;
    split_bf16(v.y, h, l); g_hs_hi[i + 1] = h; g_hs_lo[i + 1] = l;
    split_bf16(v.z, h, l); g_hs_hi[i + 2] = h; g_hs_lo[i + 2] = l;
    split_bf16(v.w, h, l); g_hs_hi[i + 3] = h; g_hs_lo[i + 3] = l;
}

__global__ __launch_bounds__(256) void cvt_w_kernel(
    const float* __restrict__ Wq, const float* __restrict__ Wk, const float* __restrict__ Wv) {
    int i = (blockIdx.x * blockDim.x + threadIdx.x) * 4;
    if (i >= 3 * HID * HID) return;
    int z = i / (HID * HID), r = i - z * (HID * HID);
    const float* W = (z == 0) ? Wq : (z == 1 ? Wk : Wv);
    float4 v = *(const float4*)(W + r);
    __nv_bfloat16 h, l;
    split_bf16(v.x, h, l); g_w_hi[i + 0] = h; g_w_lo[i + 0] = l;
    split_bf16(v.y, h, l); g_w_hi[i + 1] = h; g_w_lo[i + 1] = l;
    split_bf16(v.z, h, l); g_w_hi[i + 2] = h; g_w_lo[i + 2] = l;
    split_bf16(v.w, h, l); g_w_hi[i + 3] = h; g_w_lo[i + 3] = l;
}

// ---------------- phase 1: QKV projection (unchanged, cp.async pipelined) ----------------
#define QKV_AS    (128 * SSTR)
#define QKV_STAGE (4 * QKV_AS)
#define QKV_SMEM  (2 * QKV_STAGE * 2)

__global__ __launch_bounds__(256) void qkv_mma_kernel(
    const float* __restrict__ bq, const float* __restrict__ bk, const float* __restrict__ bv)
{
    extern __shared__ __align__(16) __nv_bfloat16 dsm[];
    int z = blockIdx.z;
    const float* bias = (z == 0) ? bq : (z == 1 ? bk : bv);
    const __nv_bfloat16* gWhi = g_w_hi + (size_t)z * HID * HID;
    const __nv_bfloat16* gWlo = g_w_lo + (size_t)z * HID * HID;

    int m0 = blockIdx.y * 128, n0 = blockIdx.x * 128;
    int t = threadIdx.x;
    int lane = t & 31, warp = t >> 5;
    int wy = warp >> 2, wx = warp & 3;
    int g = lane >> 2, tq = (lane & 3) * 2;

    float acc[4][4][4] = {};

    auto load_stage = [&](int stg, int k0) {
        __nv_bfloat16* base = dsm + stg * QKV_STAGE;
        #pragma unroll
        for (int u = 0; u < 2; u++) {
            int idx = t + 256 * u;
            int r = idx >> 2, ce = (idx & 3) * 8;
            size_t ga = (size_t)(m0 + r) * HID + k0 + ce;
            size_t gb = (size_t)(n0 + r) * HID + k0 + ce;
            int so = r * SSTR + ce;
            cp_async16(base + 0 * QKV_AS + so, g_hs_hi + ga);
            cp_async16(base + 1 * QKV_AS + so, g_hs_lo + ga);
            cp_async16(base + 2 * QKV_AS + so, gWhi + gb);
            cp_async16(base + 3 * QKV_AS + so, gWlo + gb);
        }
    };

    load_stage(0, 0);
    cp_commit();

    for (int k0 = 0; k0 < HID; k0 += 32) {
        int stg = (k0 >> 5) & 1;
        if (k0 + 32 < HID) { load_stage(stg ^ 1, k0 + 32); cp_commit(); cp_wait1(); }
        else               { cp_wait0(); }
        __syncthreads();
        const __nv_bfloat16* sAhi = dsm + stg * QKV_STAGE;
        const __nv_bfloat16* sAlo = sAhi + QKV_AS;
        const __nv_bfloat16* sBhi = sAlo + QKV_AS;
        const __nv_bfloat16* sBlo = sBhi + QKV_AS;

        #pragma unroll
        for (int kk = 0; kk < 32; kk += 16) {
            unsigned int ahi[4][4], alo[4][4];
            #pragma unroll
            for (int mt = 0; mt < 4; mt++) {
                int abase = (wy * 64 + mt * 16 + g) * SSTR + kk + tq;
                ahi[mt][0] = *(unsigned int*)&sAhi[abase];
                ahi[mt][1] = *(unsigned int*)&sAhi[abase + 8 * SSTR];
                ahi[mt][2] = *(unsigned int*)&sAhi[abase + 8];
                ahi[mt][3] = *(unsigned int*)&sAhi[abase + 8 * SSTR + 8];
                alo[mt][0] = *(unsigned int*)&sAlo[abase];
                alo[mt][1] = *(unsigned int*)&sAlo[abase + 8 * SSTR];
                alo[mt][2] = *(unsigned int*)&sAlo[abase + 8];
                alo[mt][3] = *(unsigned int*)&sAlo[abase + 8 * SSTR + 8];
            }
            #pragma unroll
            for (int nt = 0; nt < 4; nt++) {
                int bbase = (wx * 32 + nt * 8 + g) * SSTR + kk + tq;
                unsigned int bhi0 = *(unsigned int*)&sBhi[bbase];
                unsigned int bhi1 = *(unsigned int*)&sBhi[bbase + 8];
                unsigned int blo0 = *(unsigned int*)&sBlo[bbase];
                unsigned int blo1 = *(unsigned int*)&sBlo[bbase + 8];
                #pragma unroll
                for (int mt = 0; mt < 4; mt++) {
                    mma_bf16(acc[mt][nt], ahi[mt], bhi0, bhi1);
                    mma_bf16(acc[mt][nt], ahi[mt], blo0, blo1);
                    mma_bf16(acc[mt][nt], alo[mt], bhi0, bhi1);
                }
            }
        }
        __syncthreads();
    }

    #pragma unroll
    for (int nt = 0; nt < 4; nt++) {
        int n = n0 + wx * 32 + nt * 8 + tq;
        float2 b2 = *(const float2*)&bias[n];
        int h = n >> 6, d = n & 63;
        #pragma unroll
        for (int mt = 0; mt < 4; mt++) {
            int m = m0 + wy * 64 + mt * 16 + g;
            int b = m >> 10, s = m & (SEQ - 1);
            int bh = b * NHEAD + h;
            float v0 = acc[mt][nt][0] + b2.x, v1 = acc[mt][nt][1] + b2.y;
            float v2 = acc[mt][nt][2] + b2.x, v3 = acc[mt][nt][3] + b2.y;
            __nv_bfloat16 h0, l0, h1, l1, h2, l2, h3, l3;
            split_bf16(v0, h0, l0); split_bf16(v1, h1, l1);
            split_bf16(v2, h2, l2); split_bf16(v3, h3, l3);
            if (z < 2) {
                __nv_bfloat16* ah = (z == 0) ? g_qh : g_kh;
                __nv_bfloat16* al = (z == 0) ? g_ql : g_kl;
                size_t o0 = ((size_t)bh * SEQ + s) * HDIM + d;
                size_t o1 = o0 + 8 * HDIM;
                *(__nv_bfloat162*)(ah + o0) = __nv_bfloat162(h0, h1);
                *(__nv_bfloat162*)(al + o0) = __nv_bfloat162(l0, l1);
                *(__nv_bfloat162*)(ah + o1) = __nv_bfloat162(h2, h3);
                *(__nv_bfloat162*)(al + o1) = __nv_bfloat162(l2, l3);
                if (z == 0) {
                    *(float2*)(g_qkv + o0) = make_float2(v0, v1);
                    *(float2*)(g_qkv + o1) = make_float2(v2, v3);
                }
            } else {
                size_t base = ((size_t)bh * HDIM + d) * SEQ + s;
                g_vth[base] = h0;           g_vtl[base] = l0;
                g_vth[base + SEQ] = h1;     g_vtl[base + SEQ] = l1;
                g_vth[base + 8] = h2;       g_vtl[base + 8] = l2;
                g_vth[base + SEQ + 8] = h3; g_vtl[base + SEQ + 8] = l3;
            }
        }
    }
}

// ---------------- phase 1.5: qrel ----------------
__global__ __launch_bounds__(128) void qrel_kernel() {
    int row = blockIdx.x;
    __shared__ float qrow[64];
    const float* Q = g_qkv + (size_t)row * HDIM;
    if (threadIdx.x < 64) qrow[threadIdx.x] = Q[threadIdx.x];
    __syncthreads();
    for (int r = threadIdx.x; r < VOCAB; r += 128) {
        float s = 0.0f;
        #pragma unroll
        for (int d = 0; d < 64; d++) s += qrow[d] * g_tab[r * 64 + d];
        g_qrel[(size_t)row * VOCAB + r] = s;
    }
}

// ---------------- phase 2-4 fused: flash attention + rel-pos ----------------
// smem (bf16 elems): Q hi/lo 2*9216 | stages 2*(4*4608) | ps (float 128*132)
#define FA_QAS   9216                  // 128*72
#define FA_KAS   4608                  // 64*72
#define FA_STAGE (4 * FA_KAS)
#define FA_PSOFF (2 * FA_QAS + 2 * FA_STAGE)   // elem offset of ps
#define FA_SMEM  (FA_PSOFF * 2 + 128 * 132 * 4) // 110592 + 67584 = 178176 B

__global__ __launch_bounds__(256) void attn_fused_kernel(
    const float* __restrict__ mask, float* __restrict__ out)
{
    extern __shared__ __align__(16) __nv_bfloat16 dsm[];
    const int bh = blockIdx.y, b = bh >> 4, h = bh & 15;
    const int q0 = blockIdx.x * 128;
    const int t = threadIdx.x, lane = t & 31, w = t >> 5;
    const int g = lane >> 2, tq = (lane & 3) * 2;

    __nv_bfloat16* sQhi = dsm;
    __nv_bfloat16* sQlo = dsm + FA_QAS;
    float* psm = (float*)(dsm + FA_PSOFF);

    // zero ps
    for (int i = t; i < 128 * 132; i += 256) psm[i] = 0.0f;

    // load Q tile (hi/lo), stage 0 of K/V; one commit group
    #pragma unroll
    for (int u = 0; u < 4; u++) {
        int idx = t + 256 * u;
        int r = idx >> 3, ce = (idx & 7) * 8;
        size_t ga = ((size_t)bh * SEQ + q0 + r) * HDIM + ce;
        int so = r * SST2 + ce;
        cp_async16(sQhi + so, g_qh + ga);
        cp_async16(sQlo + so, g_ql + ga);
    }
    auto load_kv = [&](int stg, int kt0) {
        __nv_bfloat16* base = dsm + 2 * FA_QAS + stg * FA_STAGE;
        #pragma unroll
        for (int u = 0; u < 2; u++) {
            int idx = t + 256 * u;
            int r = idx >> 3, ce = (idx & 7) * 8;
            int so = r * SST2 + ce;
            size_t gk = ((size_t)bh * SEQ + kt0 + r) * HDIM + ce;
            size_t gv = ((size_t)bh * HDIM + r) * SEQ + kt0 + ce;
            cp_async16(base + 0 * FA_KAS + so, g_kh + gk);
            cp_async16(base + 1 * FA_KAS + so, g_kl + gk);
            cp_async16(base + 2 * FA_KAS + so, g_vth + gv);
            cp_async16(base + 3 * FA_KAS + so, g_vtl + gv);
        }
    };
    load_kv(0, 0);
    cp_commit();

    const int qg = q0 + w * 16 + g;
    const int qh2 = qg + 8;
    const float* qrg = g_qrel + ((size_t)bh * SEQ + qg) * VOCAB;
    const float* qrh = g_qrel + ((size_t)bh * SEQ + qh2) * VOCAB;
    float* prowg = psm + (w * 16 + g) * 132;
    float* prowh = prowg + 8 * 132;

    float acc[8][4] = {};
    float m_g = -1e30f, m_h = -1e30f;
    float l_g = 0.f, l_h = 0.f, lo_g = 0.f, lo_h = 0.f, hi_g = 0.f, hi_h = 0.f;

    for (int kt = 0; kt < 16; kt++) {
        int kt0 = kt * 64;
        if (kt < 15) { load_kv((kt ^ 1) & 1, kt0 + 64); cp_commit(); cp_wait1(); }
        else         { cp_wait0(); }
        __syncthreads();
        const __nv_bfloat16* stage = dsm + 2 * FA_QAS + (kt & 1) * FA_STAGE;
        const __nv_bfloat16* sKhi = stage;
        const __nv_bfloat16* sKlo = stage + FA_KAS;
        const __nv_bfloat16* sVhi = stage + 2 * FA_KAS;
        const __nv_bfloat16* sVlo = stage + 3 * FA_KAS;

        // ---- S = Q K^T (split) ----
        float s[8][4] = {};
        #pragma unroll
        for (int kk = 0; kk < 64; kk += 16) {
            unsigned ahi[4], alo[4];
            int abase = (w * 16 + g) * SST2 + kk + tq;
            ahi[0] = *(unsigned*)&sQhi[abase];
            ahi[1] = *(unsigned*)&sQhi[abase + 8 * SST2];
            ahi[2] = *(unsigned*)&sQhi[abase + 8];
            ahi[3] = *(unsigned*)&sQhi[abase + 8 * SST2 + 8];
            alo[0] = *(unsigned*)&sQlo[abase];
            alo[1] = *(unsigned*)&sQlo[abase + 8 * SST2];
            alo[2] = *(unsigned*)&sQlo[abase + 8];
            alo[3] = *(unsigned*)&sQlo[abase + 8 * SST2 + 8];
            #pragma unroll
            for (int nt = 0; nt < 8; nt++) {
                int bbase = (nt * 8 + g) * SST2 + kk + tq;
                unsigned bh0 = *(unsigned*)&sKhi[bbase];
                unsigned bh1 = *(unsigned*)&sKhi[bbase + 8];
                unsigned bl0 = *(unsigned*)&sKlo[bbase];
                unsigned bl1 = *(unsigned*)&sKlo[bbase + 8];
                mma_bf16(s[nt], ahi, bh0, bh1);
                mma_bf16(s[nt], ahi, bl0, bl1);
                mma_bf16(s[nt], alo, bh0, bh1);
            }
        }

        // ---- scores epilogue: qrel + scale + mask ----
        #pragma unroll
        for (int nt = 0; nt < 8; nt++) {
            int k = kt0 + nt * 8 + tq;
            float mk0 = mask[b * SEQ + k], mk1 = mask[b * SEQ + k + 1];
            int c;
            c = k - qg;      c = c < -64 ? -64 : (c > 64 ? 64 : c);
            s[nt][0] = (s[nt][0] + qrg[c + 64]) * 0.125f + mk0;
            c = k + 1 - qg;  c = c < -64 ? -64 : (c > 64 ? 64 : c);
            s[nt][1] = (s[nt][1] + qrg[c + 64]) * 0.125f + mk1;
            c = k - qh2;     c = c < -64 ? -64 : (c > 64 ? 64 : c);
            s[nt][2] = (s[nt][2] + qrh[c + 64]) * 0.125f + mk0;
            c = k + 1 - qh2; c = c < -64 ? -64 : (c > 64 ? 64 : c);
            s[nt][3] = (s[nt][3] + qrh[c + 64]) * 0.125f + mk1;
        }

        // ---- online softmax ----
        float tg = -1e30f, th = -1e30f;
        #pragma unroll
        for (int nt = 0; nt < 8; nt++) {
            tg = fmaxf(tg, fmaxf(s[nt][0], s[nt][1]));
            th = fmaxf(th, fmaxf(s[nt][2], s[nt][3]));
        }
        tg = quadmax(tg); th = quadmax(th);
        float mng = fmaxf(m_g, tg), mnh = fmaxf(m_h, th);
        float scg = __expf(m_g - mng), sch = __expf(m_h - mnh);
        if (scg < 1.0f) {
            #pragma unroll
            for (int nt = 0; nt < 8; nt++) { acc[nt][0] *= scg; acc[nt][1] *= scg; }
            l_g *= scg; lo_g *= scg; hi_g *= scg;
            int c0 = (lane & 3) * 33, c1 = c0 + 33 > 129 ? 129 : c0 + 33;
            for (int c = c0; c < c1; c++) prowg[c] *= scg;
        }
        if (sch < 1.0f) {
            #pragma unroll
            for (int nt = 0; nt < 8; nt++) { acc[nt][2] *= sch; acc[nt][3] *= sch; }
            l_h *= sch; lo_h *= sch; hi_h *= sch;
            int c0 = (lane & 3) * 33, c1 = c0 + 33 > 129 ? 129 : c0 + 33;
            for (int c = c0; c < c1; c++) prowh[c] *= sch;
        }
        __syncwarp();
        m_g = mng; m_h = mnh;

        // ---- p = exp, band/edges, pack A-frags ----
        unsigned phi[4][4], plo[4][4];
        #pragma unroll
        for (int nt = 0; nt < 8; nt++) {
            int k = kt0 + nt * 8 + tq;
            float p0 = __expf(s[nt][0] - m_g), p1 = __expf(s[nt][1] - m_g);
            float p2 = __expf(s[nt][2] - m_h), p3 = __expf(s[nt][3] - m_h);
            l_g += p0 + p1; l_h += p2 + p3;
            int d0 = k - qg, d1 = k + 1 - qg;
            if (d0 <= -64) lo_g += p0; else if (d0 >= 64) hi_g += p0; else prowg[d0 + 64] = p0;
            if (d1 <= -64) lo_g += p1; else if (d1 >= 64) hi_g += p1; else prowg[d1 + 64] = p1;
            int e0 = k - qh2, e1 = k + 1 - qh2;
            if (e0 <= -64) lo_h += p2; else if (e0 >= 64) hi_h += p2; else prowh[e0 + 64] = p2;
            if (e1 <= -64) lo_h += p3; else if (e1 >= 64) hi_h += p3; else prowh[e1 + 64] = p3;
            int kb = nt >> 1;
            if ((nt & 1) == 0) {
                phi[kb][0] = pack2h(p0, p1); phi[kb][1] = pack2h(p2, p3);
                plo[kb][0] = pack2l(p0, p1); plo[kb][1] = pack2l(p2, p3);
            } else {
                phi[kb][2] = pack2h(p0, p1); phi[kb][3] = pack2h(p2, p3);
                plo[kb][2] = pack2l(p0, p1); plo[kb][3] = pack2l(p2, p3);
            }
        }

        // ---- O += P V (split) ----
        #pragma unroll
        for (int kb = 0; kb < 4; kb++) {
            int kk = kb * 16;
            #pragma unroll
            for (int nt = 0; nt < 8; nt++) {
                int bbase = (nt * 8 + g) * SST2 + kk + tq;
                unsigned vh0 = *(unsigned*)&sVhi[bbase];
                unsigned vh1 = *(unsigned*)&sVhi[bbase + 8];
                unsigned vl0 = *(unsigned*)&sVlo[bbase];
                unsigned vl1 = *(unsigned*)&sVlo[bbase + 8];
                mma_bf16(acc[nt], phi[kb], vh0, vh1);
                mma_bf16(acc[nt], phi[kb], vl0, vl1);
                mma_bf16(acc[nt], plo[kb], vh0, vh1);
            }
        }
        __syncthreads();
    }

    // ---- finalize edges + row sums ----
    l_g = quadsum(l_g); l_h = quadsum(l_h);
    lo_g = quadsum(lo_g); lo_h = quadsum(lo_h);
    hi_g = quadsum(hi_g); hi_h = quadsum(hi_h);
    if ((lane & 3) == 0) {
        prowg[0] = lo_g; prowg[128] = hi_g;
        prowh[0] = lo_h; prowh[128] = hi_h;
    }
    __syncthreads();

    // ---- rel-value epilogue: acc += ps @ tab (tab staged in freed K/V smem) ----
    float* tabS = (float*)(dsm + 2 * FA_QAS);   // 16 x 68 floats
    for (int r0 = 0; r0 < VOCAB; r0 += 16) {
        __syncthreads();
        {
            int rr = t >> 4, cc = (t & 15) * 4;
            int r = r0 + rr;
            float4 tv = (r < VOCAB) ? *(const float4*)&g_tab[r * 64 + cc]
                                    : make_float4(0.f, 0.f, 0.f, 0.f);
            *(float4*)&tabS[rr * 68 + cc] = tv;
        }
        __syncthreads();
        #pragma unroll
        for (int rc = 0; rc < 16; rc++) {
            int rr2 = r0 + rc; if (rr2 > 128) rr2 = 128;  // value *0 via zero tab rows
            float pg = prowg[rr2];
            float ph = prowh[rr2];
            #pragma unroll
            for (int nt = 0; nt < 8; nt++) {
                int d = nt * 8 + tq;
                float t0 = tabS[rc * 68 + d], t1 = tabS[rc * 68 + d + 1];
                acc[nt][0] += pg * t0; acc[nt][1] += pg * t1;
                acc[nt][2] += ph * t0; acc[nt][3] += ph * t1;
            }
        }
    }

    // ---- normalize + write ----
    float ig = 1.0f / l_g, ih = 1.0f / l_h;
    #pragma unroll
    for (int nt = 0; nt < 8; nt++) {
        int d = nt * 8 + tq;
        *(float2*)(out + ((size_t)(b * SEQ + qg)) * HID + h * 64 + d) =
            make_float2(acc[nt][0] * ig, acc[nt][1] * ig);
        *(float2*)(out + ((size_t)(b * SEQ + qh2)) * HID + h * 64 + d) =
            make_float2(acc[nt][2] * ih, acc[nt][3] * ih);
    }
}

// ---------------- launcher ----------------
extern "C" void kernel_launch(void* const* d_in, const int* in_sizes, int n_in,
                              void* d_out, int out_size) {
    const float* hs   = (const float*)d_in[0];
    const float* mask = (const float*)d_in[1];
    const float* Wq   = (const float*)d_in[2];
    const float* bq   = (const float*)d_in[3];
    const float* Wk   = (const float*)d_in[4];
    const float* bk   = (const float*)d_in[5];
    const float* Wv   = (const float*)d_in[6];
    const float* bv   = (const float*)d_in[7];
    float* out = (float*)d_out;

    cudaFuncSetAttribute(qkv_mma_kernel,   cudaFuncAttributeMaxDynamicSharedMemorySize, QKV_SMEM);
    cudaFuncSetAttribute(attn_fused_kernel, cudaFuncAttributeMaxDynamicSharedMemorySize, FA_SMEM);

    init_tab_kernel<<<(VOCAB * 32 + 127) / 128, 128>>>();
    cvt_hs_kernel<<<(BATCH * SEQ * HID / 4 + 255) / 256, 256>>>(hs);
    cvt_w_kernel<<<(3 * HID * HID / 4 + 255) / 256, 256>>>(Wq, Wk, Wv);
    qkv_mma_kernel<<<dim3(HID / 128, (BATCH * SEQ) / 128, 3), 256, QKV_SMEM>>>(bq, bk, bv);
    qrel_kernel<<<BH * SEQ, 128>>>();
    attn_fused_kernel<<<dim3(SEQ / 128, BH), 256, FA_SMEM>>>(mask, out);
}

// round 8
// speedup vs baseline: 2.4273x; 1.5251x over previous
#include <cuda_runtime.h>
#include <cuda_bf16.h>
#include <cstdint>

#define BATCH 2
#define SEQ   1024
#define HID   1024
#define NHEAD 16
#define HDIM  64
#define BH    (BATCH*NHEAD)      // 32
#define VOCAB 129                // 2*64+1
#define SST2  72                 // bf16 smem stride (64-col tiles): conflict-free

// ---------------- scratch ----------------
__device__ __align__(16) float g_qkv[BH * SEQ * HDIM];           // Q fp32 (for qrel)
__device__ __align__(16) float g_qrel[(size_t)BH * SEQ * VOCAB];
__device__ __align__(16) float g_tab[VOCAB * HDIM];

__device__ __align__(16) __nv_bfloat16 g_hs_hi[BATCH * SEQ * HID];
__device__ __align__(16) __nv_bfloat16 g_hs_lo[BATCH * SEQ * HID];
__device__ __align__(16) __nv_bfloat16 g_w_hi[3 * HID * HID];
__device__ __align__(16) __nv_bfloat16 g_w_lo[3 * HID * HID];
__device__ __align__(16) __nv_bfloat16 g_qh[BH * SEQ * HDIM];
__device__ __align__(16) __nv_bfloat16 g_ql[BH * SEQ * HDIM];
__device__ __align__(16) __nv_bfloat16 g_kh[BH * SEQ * HDIM];
__device__ __align__(16) __nv_bfloat16 g_kl[BH * SEQ * HDIM];
__device__ __align__(16) __nv_bfloat16 g_vth[BH * HDIM * SEQ];   // V^T [bh][d][s]
__device__ __align__(16) __nv_bfloat16 g_vtl[BH * HDIM * SEQ];

// ---------------- helpers ----------------
__device__ __forceinline__ void cp_async16(void* dst, const void* src) {
    unsigned int d = (unsigned int)__cvta_generic_to_shared(dst);
    asm volatile("cp.async.cg.shared.global [%0], [%1], 16;" :: "r"(d), "l"(src));
}
__device__ __forceinline__ void cp_commit() { asm volatile("cp.async.commit_group;"); }
__device__ __forceinline__ void cp_wait0()  { asm volatile("cp.async.wait_group 0;"); }
__device__ __forceinline__ void cp_wait1()  { asm volatile("cp.async.wait_group 1;"); }

__device__ __forceinline__ void ldsm4(unsigned* r, const void* p) {
    unsigned a = (unsigned)__cvta_generic_to_shared(p);
    asm volatile("ldmatrix.sync.aligned.m8n8.x4.shared.b16 {%0,%1,%2,%3}, [%4];"
                 : "=r"(r[0]), "=r"(r[1]), "=r"(r[2]), "=r"(r[3]) : "r"(a));
}

__device__ __forceinline__ void split_bf16(float v, __nv_bfloat16& hi, __nv_bfloat16& lo) {
    hi = __float2bfloat16_rn(v);
    lo = __float2bfloat16_rn(v - __bfloat162float(hi));
}
__device__ __forceinline__ unsigned pack2h(float a, float b) {
    __nv_bfloat162 p(__float2bfloat16_rn(a), __float2bfloat16_rn(b));
    return *(unsigned*)&p;
}
__device__ __forceinline__ unsigned pack2l(float a, float b) {
    float ra = a - __bfloat162float(__float2bfloat16_rn(a));
    float rb = b - __bfloat162float(__float2bfloat16_rn(b));
    __nv_bfloat162 p(__float2bfloat16_rn(ra), __float2bfloat16_rn(rb));
    return *(unsigned*)&p;
}
__device__ __forceinline__ float quadmax(float v) {
    v = fmaxf(v, __shfl_xor_sync(0xffffffffu, v, 1));
    v = fmaxf(v, __shfl_xor_sync(0xffffffffu, v, 2));
    return v;
}
__device__ __forceinline__ float quadsum(float v) {
    v += __shfl_xor_sync(0xffffffffu, v, 1);
    v += __shfl_xor_sync(0xffffffffu, v, 2);
    return v;
}
__device__ __forceinline__ void mma_bf16(float* c, const unsigned int* A,
                                         unsigned int b0, unsigned int b1) {
    asm volatile("mma.sync.aligned.m16n8k16.row.col.f32.bf16.bf16.f32 "
        "{%0,%1,%2,%3}, {%4,%5,%6,%7}, {%8,%9}, {%0,%1,%2,%3};"
        : "+f"(c[0]), "+f"(c[1]), "+f"(c[2]), "+f"(c[3])
        : "r"(A[0]), "r"(A[1]), "r"(A[2]), "r"(A[3]), "r"(b0), "r"(b1));
}

// ---------------- sinusoid table ----------------
__global__ void init_tab_kernel() {
    int idx = blockIdx.x * blockDim.x + threadIdx.x;
    if (idx >= VOCAB * 32) return;
    int p = idx >> 5, i = idx & 31;
    float div = expf((float)(2 * i) * (-9.210340371976184f / 64.0f));
    float ang = (float)p * div;
    g_tab[p * 64 + 2 * i]     = sinf(ang);
    g_tab[p * 64 + 2 * i + 1] = cosf(ang);
}

__global__ __launch_bounds__(256) void cvt_hs_kernel(const float* __restrict__ hs) {
    int i = (blockIdx.x * blockDim.x + threadIdx.x) * 4;
    if (i >= BATCH * SEQ * HID) return;
    float4 v = *(const float4*)(hs + i);
    __nv_bfloat16 h, l;
    split_bf16(v.x, h, l); g_hs_hi[i + 0] = h; g_hs_lo[i + 0] = l;
    split_bf16(v.y, h, l); g_hs_hi[i + 1] = h; g_hs_lo[i + 1] = l;
    split_bf16(v.z, h, l); g_hs_hi[i + 2] = h; g_hs_lo[i + 2] = l;
    split_bf16(v.w, h, l); g_hs_hi[i + 3] = h; g_hs_lo[i + 3] = l;
}

__global__ __launch_bounds__(256) void cvt_w_kernel(
    const float* __restrict__ Wq, const float* __restrict__ Wk, const float* __restrict__ Wv) {
    int i = (blockIdx.x * blockDim.x + threadIdx.x) * 4;
    if (i >= 3 * HID * HID) return;
    int z = i / (HID * HID), r = i - z * (HID * HID);
    const float* W = (z == 0) ? Wq : (z == 1 ? Wk : Wv);
    float4 v = *(const float4*)(W + r);
    __nv_bfloat16 h, l;
    split_bf16(v.x, h, l); g_w_hi[i + 0] = h; g_w_lo[i + 0] = l;
    split_bf16(v.y, h, l); g_w_hi[i + 1] = h; g_w_lo[i + 1] = l;
    split_bf16(v.z, h, l); g_w_hi[i + 2] = h; g_w_lo[i + 2] = l;
    split_bf16(v.w, h, l); g_w_hi[i + 3] = h; g_w_lo[i + 3] = l;
}

// ---------------- phase 1: QKV projection, BK=64 + ldmatrix ----------------
#define QKV_AS    (128 * SST2)        // 9216 elems per array
#define QKV_STAGE (4 * QKV_AS)
#define QKV_SMEM  (2 * QKV_STAGE * 2) // 147456 B

__global__ __launch_bounds__(256) void qkv_mma_kernel(
    const float* __restrict__ bq, const float* __restrict__ bk, const float* __restrict__ bv)
{
    extern __shared__ __align__(16) __nv_bfloat16 dsm[];
    int z = blockIdx.z;
    const float* bias = (z == 0) ? bq : (z == 1 ? bk : bv);
    const __nv_bfloat16* gWhi = g_w_hi + (size_t)z * HID * HID;
    const __nv_bfloat16* gWlo = g_w_lo + (size_t)z * HID * HID;

    int m0 = blockIdx.y * 128, n0 = blockIdx.x * 128;
    int t = threadIdx.x;
    int lane = t & 31, warp = t >> 5;
    int wy = warp >> 2, wx = warp & 3;
    int g = lane >> 2, tq = (lane & 3) * 2;
    int arow = lane & 15, acol8 = (lane >> 4) * 8;
    int brow = ((lane >> 4) << 3) + (lane & 7), bcol8 = ((lane >> 3) & 1) * 8;

    float acc[4][4][4] = {};

    auto load_stage = [&](int stg, int k0) {
        __nv_bfloat16* base = dsm + stg * QKV_STAGE;
        #pragma unroll
        for (int u = 0; u < 4; u++) {
            int idx = t + 256 * u;
            int r = idx >> 3, ce = (idx & 7) * 8;
            size_t ga = (size_t)(m0 + r) * HID + k0 + ce;
            size_t gb = (size_t)(n0 + r) * HID + k0 + ce;
            int so = r * SST2 + ce;
            cp_async16(base + 0 * QKV_AS + so, g_hs_hi + ga);
            cp_async16(base + 1 * QKV_AS + so, g_hs_lo + ga);
            cp_async16(base + 2 * QKV_AS + so, gWhi + gb);
            cp_async16(base + 3 * QKV_AS + so, gWlo + gb);
        }
    };

    load_stage(0, 0);
    cp_commit();

    for (int k0 = 0; k0 < HID; k0 += 64) {
        int stg = (k0 >> 6) & 1;
        if (k0 + 64 < HID) { load_stage(stg ^ 1, k0 + 64); cp_commit(); cp_wait1(); }
        else               { cp_wait0(); }
        __syncthreads();
        const __nv_bfloat16* sAhi = dsm + stg * QKV_STAGE;
        const __nv_bfloat16* sAlo = sAhi + QKV_AS;
        const __nv_bfloat16* sBhi = sAlo + QKV_AS;
        const __nv_bfloat16* sBlo = sBhi + QKV_AS;

        #pragma unroll
        for (int kk = 0; kk < 64; kk += 16) {
            unsigned ahi[4][4], alo[4][4];
            #pragma unroll
            for (int mt = 0; mt < 4; mt++) {
                int ab = (wy * 64 + mt * 16 + arow) * SST2 + kk + acol8;
                ldsm4(ahi[mt], sAhi + ab);
                ldsm4(alo[mt], sAlo + ab);
            }
            #pragma unroll
            for (int ntp = 0; ntp < 2; ntp++) {
                int bb = (wx * 32 + ntp * 16 + brow) * SST2 + kk + bcol8;
                unsigned bh[4], bl[4];
                ldsm4(bh, sBhi + bb);
                ldsm4(bl, sBlo + bb);
                #pragma unroll
                for (int mt = 0; mt < 4; mt++) {
                    mma_bf16(acc[mt][2 * ntp],     ahi[mt], bh[0], bh[1]);
                    mma_bf16(acc[mt][2 * ntp],     ahi[mt], bl[0], bl[1]);
                    mma_bf16(acc[mt][2 * ntp],     alo[mt], bh[0], bh[1]);
                    mma_bf16(acc[mt][2 * ntp + 1], ahi[mt], bh[2], bh[3]);
                    mma_bf16(acc[mt][2 * ntp + 1], ahi[mt], bl[2], bl[3]);
                    mma_bf16(acc[mt][2 * ntp + 1], alo[mt], bh[2], bh[3]);
                }
            }
        }
        __syncthreads();
    }

    #pragma unroll
    for (int nt = 0; nt < 4; nt++) {
        int n = n0 + wx * 32 + nt * 8 + tq;
        float2 b2 = *(const float2*)&bias[n];
        int h = n >> 6, d = n & 63;
        #pragma unroll
        for (int mt = 0; mt < 4; mt++) {
            int m = m0 + wy * 64 + mt * 16 + g;
            int b = m >> 10, s = m & (SEQ - 1);
            int bh = b * NHEAD + h;
            float v0 = acc[mt][nt][0] + b2.x, v1 = acc[mt][nt][1] + b2.y;
            float v2 = acc[mt][nt][2] + b2.x, v3 = acc[mt][nt][3] + b2.y;
            __nv_bfloat16 h0, l0, h1, l1, h2, l2, h3, l3;
            split_bf16(v0, h0, l0); split_bf16(v1, h1, l1);
            split_bf16(v2, h2, l2); split_bf16(v3, h3, l3);
            if (z < 2) {
                __nv_bfloat16* ah = (z == 0) ? g_qh : g_kh;
                __nv_bfloat16* al = (z == 0) ? g_ql : g_kl;
                size_t o0 = ((size_t)bh * SEQ + s) * HDIM + d;
                size_t o1 = o0 + 8 * HDIM;
                *(__nv_bfloat162*)(ah + o0) = __nv_bfloat162(h0, h1);
                *(__nv_bfloat162*)(al + o0) = __nv_bfloat162(l0, l1);
                *(__nv_bfloat162*)(ah + o1) = __nv_bfloat162(h2, h3);
                *(__nv_bfloat162*)(al + o1) = __nv_bfloat162(l2, l3);
                if (z == 0) {
                    *(float2*)(g_qkv + o0) = make_float2(v0, v1);
                    *(float2*)(g_qkv + o1) = make_float2(v2, v3);
                }
            } else {
                size_t base = ((size_t)bh * HDIM + d) * SEQ + s;
                g_vth[base] = h0;           g_vtl[base] = l0;
                g_vth[base + SEQ] = h1;     g_vtl[base + SEQ] = l1;
                g_vth[base + 8] = h2;       g_vtl[base + 8] = l2;
                g_vth[base + SEQ + 8] = h3; g_vtl[base + SEQ + 8] = l3;
            }
        }
    }
}

// ---------------- phase 1.5: qrel = Q @ tab^T, broadcast-friendly ----------------
// 256 blocks x 256 threads; 2 threads per q-row; tab reads are warp-uniform.
__global__ __launch_bounds__(256) void qrel_kernel() {
    int t = threadIdx.x;
    int row = blockIdx.x * 128 + (t & 127);
    int half = t >> 7;
    const float* Q = g_qkv + (size_t)row * HDIM;
    float q[64];
    #pragma unroll
    for (int d4 = 0; d4 < 16; d4++) {
        float4 v = *(const float4*)(Q + d4 * 4);
        q[d4 * 4 + 0] = v.x; q[d4 * 4 + 1] = v.y;
        q[d4 * 4 + 2] = v.z; q[d4 * 4 + 3] = v.w;
    }
    int c0 = half * 65;
    int cn = half ? 64 : 65;
    float* dst = g_qrel + (size_t)row * VOCAB;
    for (int j = 0; j < cn; j++) {
        int c = c0 + j;
        const float* tr = g_tab + c * 64;
        float s = 0.f;
        #pragma unroll
        for (int d4 = 0; d4 < 16; d4++) {
            float4 tv = *(const float4*)(tr + d4 * 4);
            s += q[d4*4]*tv.x + q[d4*4+1]*tv.y + q[d4*4+2]*tv.z + q[d4*4+3]*tv.w;
        }
        dst[c] = s;
    }
}

// ---------------- phase 2-4 fused: flash attention + rel-pos (ldmatrix) ----------------
#define FA_QAS   9216                  // 128*72
#define FA_KAS   4608                  // 64*72
#define FA_STAGE (4 * FA_KAS)
#define FA_PSOFF (2 * FA_QAS + 2 * FA_STAGE)
#define FA_SMEM  (FA_PSOFF * 2 + 128 * 132 * 4)

__global__ __launch_bounds__(256) void attn_fused_kernel(
    const float* __restrict__ mask, float* __restrict__ out)
{
    extern __shared__ __align__(16) __nv_bfloat16 dsm[];
    const int bh = blockIdx.y, b = bh >> 4, h = bh & 15;
    const int q0 = blockIdx.x * 128;
    const int t = threadIdx.x, lane = t & 31, w = t >> 5;
    const int g = lane >> 2, tq = (lane & 3) * 2;
    const int arow = lane & 15, acol8 = (lane >> 4) * 8;
    const int brow = ((lane >> 4) << 3) + (lane & 7), bcol8 = ((lane >> 3) & 1) * 8;

    __nv_bfloat16* sQhi = dsm;
    __nv_bfloat16* sQlo = dsm + FA_QAS;
    float* psm = (float*)(dsm + FA_PSOFF);

    for (int i = t; i < 128 * 132; i += 256) psm[i] = 0.0f;

    #pragma unroll
    for (int u = 0; u < 4; u++) {
        int idx = t + 256 * u;
        int r = idx >> 3, ce = (idx & 7) * 8;
        size_t ga = ((size_t)bh * SEQ + q0 + r) * HDIM + ce;
        int so = r * SST2 + ce;
        cp_async16(sQhi + so, g_qh + ga);
        cp_async16(sQlo + so, g_ql + ga);
    }
    auto load_kv = [&](int stg, int kt0) {
        __nv_bfloat16* base = dsm + 2 * FA_QAS + stg * FA_STAGE;
        #pragma unroll
        for (int u = 0; u < 2; u++) {
            int idx = t + 256 * u;
            int r = idx >> 3, ce = (idx & 7) * 8;
            int so = r * SST2 + ce;
            size_t gk = ((size_t)bh * SEQ + kt0 + r) * HDIM + ce;
            size_t gv = ((size_t)bh * HDIM + r) * SEQ + kt0 + ce;
            cp_async16(base + 0 * FA_KAS + so, g_kh + gk);
            cp_async16(base + 1 * FA_KAS + so, g_kl + gk);
            cp_async16(base + 2 * FA_KAS + so, g_vth + gv);
            cp_async16(base + 3 * FA_KAS + so, g_vtl + gv);
        }
    };
    load_kv(0, 0);
    cp_commit();

    const int qg = q0 + w * 16 + g;
    const int qh2 = qg + 8;
    const float* qrg = g_qrel + ((size_t)bh * SEQ + qg) * VOCAB;
    const float* qrh = g_qrel + ((size_t)bh * SEQ + qh2) * VOCAB;
    float* prowg = psm + (w * 16 + g) * 132;
    float* prowh = prowg + 8 * 132;

    float acc[8][4] = {};
    float m_g = -1e30f, m_h = -1e30f;
    float l_g = 0.f, l_h = 0.f, lo_g = 0.f, lo_h = 0.f, hi_g = 0.f, hi_h = 0.f;

    for (int kt = 0; kt < 16; kt++) {
        int kt0 = kt * 64;
        if (kt < 15) { load_kv((kt ^ 1) & 1, kt0 + 64); cp_commit(); cp_wait1(); }
        else         { cp_wait0(); }
        __syncthreads();
        const __nv_bfloat16* stage = dsm + 2 * FA_QAS + (kt & 1) * FA_STAGE;
        const __nv_bfloat16* sKhi = stage;
        const __nv_bfloat16* sKlo = stage + FA_KAS;
        const __nv_bfloat16* sVhi = stage + 2 * FA_KAS;
        const __nv_bfloat16* sVlo = stage + 3 * FA_KAS;

        // ---- S = Q K^T (split, ldmatrix) ----
        float s[8][4] = {};
        #pragma unroll
        for (int kk = 0; kk < 64; kk += 16) {
            unsigned ahi[4], alo[4];
            int ab = (w * 16 + arow) * SST2 + kk + acol8;
            ldsm4(ahi, sQhi + ab);
            ldsm4(alo, sQlo + ab);
            #pragma unroll
            for (int ntp = 0; ntp < 4; ntp++) {
                int bb = (ntp * 16 + brow) * SST2 + kk + bcol8;
                unsigned kh[4], kl[4];
                ldsm4(kh, sKhi + bb);
                ldsm4(kl, sKlo + bb);
                mma_bf16(s[2 * ntp],     ahi, kh[0], kh[1]);
                mma_bf16(s[2 * ntp],     ahi, kl[0], kl[1]);
                mma_bf16(s[2 * ntp],     alo, kh[0], kh[1]);
                mma_bf16(s[2 * ntp + 1], ahi, kh[2], kh[3]);
                mma_bf16(s[2 * ntp + 1], ahi, kl[2], kl[3]);
                mma_bf16(s[2 * ntp + 1], alo, kh[2], kh[3]);
            }
        }

        // ---- scores epilogue: qrel + scale + mask ----
        #pragma unroll
        for (int nt = 0; nt < 8; nt++) {
            int k = kt0 + nt * 8 + tq;
            float mk0 = mask[b * SEQ + k], mk1 = mask[b * SEQ + k + 1];
            int c;
            c = k - qg;      c = c < -64 ? -64 : (c > 64 ? 64 : c);
            s[nt][0] = (s[nt][0] + qrg[c + 64]) * 0.125f + mk0;
            c = k + 1 - qg;  c = c < -64 ? -64 : (c > 64 ? 64 : c);
            s[nt][1] = (s[nt][1] + qrg[c + 64]) * 0.125f + mk1;
            c = k - qh2;     c = c < -64 ? -64 : (c > 64 ? 64 : c);
            s[nt][2] = (s[nt][2] + qrh[c + 64]) * 0.125f + mk0;
            c = k + 1 - qh2; c = c < -64 ? -64 : (c > 64 ? 64 : c);
            s[nt][3] = (s[nt][3] + qrh[c + 64]) * 0.125f + mk1;
        }

        // ---- online softmax ----
        float tg = -1e30f, th = -1e30f;
        #pragma unroll
        for (int nt = 0; nt < 8; nt++) {
            tg = fmaxf(tg, fmaxf(s[nt][0], s[nt][1]));
            th = fmaxf(th, fmaxf(s[nt][2], s[nt][3]));
        }
        tg = quadmax(tg); th = quadmax(th);
        float mng = fmaxf(m_g, tg), mnh = fmaxf(m_h, th);
        float scg = __expf(m_g - mng), sch = __expf(m_h - mnh);
        if (scg < 1.0f) {
            #pragma unroll
            for (int nt = 0; nt < 8; nt++) { acc[nt][0] *= scg; acc[nt][1] *= scg; }
            l_g *= scg; lo_g *= scg; hi_g *= scg;
            int c0 = (lane & 3) * 33, c1 = c0 + 33 > 129 ? 129 : c0 + 33;
            for (int c = c0; c < c1; c++) prowg[c] *= scg;
        }
        if (sch < 1.0f) {
            #pragma unroll
            for (int nt = 0; nt < 8; nt++) { acc[nt][2] *= sch; acc[nt][3] *= sch; }
            l_h *= sch; lo_h *= sch; hi_h *= sch;
            int c0 = (lane & 3) * 33, c1 = c0 + 33 > 129 ? 129 : c0 + 33;
            for (int c = c0; c < c1; c++) prowh[c] *= sch;
        }
        __syncwarp();
        m_g = mng; m_h = mnh;

        // ---- p = exp, band/edges, pack A-frags ----
        unsigned phi[4][4], plo[4][4];
        #pragma unroll
        for (int nt = 0; nt < 8; nt++) {
            int k = kt0 + nt * 8 + tq;
            float p0 = __expf(s[nt][0] - m_g), p1 = __expf(s[nt][1] - m_g);
            float p2 = __expf(s[nt][2] - m_h), p3 = __expf(s[nt][3] - m_h);
            l_g += p0 + p1; l_h += p2 + p3;
            int d0 = k - qg, d1 = k + 1 - qg;
            if (d0 <= -64) lo_g += p0; else if (d0 >= 64) hi_g += p0; else prowg[d0 + 64] = p0;
            if (d1 <= -64) lo_g += p1; else if (d1 >= 64) hi_g += p1; else prowg[d1 + 64] = p1;
            int e0 = k - qh2, e1 = k + 1 - qh2;
            if (e0 <= -64) lo_h += p2; else if (e0 >= 64) hi_h += p2; else prowh[e0 + 64] = p2;
            if (e1 <= -64) lo_h += p3; else if (e1 >= 64) hi_h += p3; else prowh[e1 + 64] = p3;
            int kb = nt >> 1;
            if ((nt & 1) == 0) {
                phi[kb][0] = pack2h(p0, p1); phi[kb][1] = pack2h(p2, p3);
                plo[kb][0] = pack2l(p0, p1); plo[kb][1] = pack2l(p2, p3);
            } else {
                phi[kb][2] = pack2h(p0, p1); phi[kb][3] = pack2h(p2, p3);
                plo[kb][2] = pack2l(p0, p1); plo[kb][3] = pack2l(p2, p3);
            }
        }

        // ---- O += P V (split, ldmatrix B) ----
        #pragma unroll
        for (int kb = 0; kb < 4; kb++) {
            int kk = kb * 16;
            #pragma unroll
            for (int ntp = 0; ntp < 4; ntp++) {
                int bb = (ntp * 16 + brow) * SST2 + kk + bcol8;
                unsigned vh[4], vl[4];
                ldsm4(vh, sVhi + bb);
                ldsm4(vl, sVlo + bb);
                mma_bf16(acc[2 * ntp],     phi[kb], vh[0], vh[1]);
                mma_bf16(acc[2 * ntp],     phi[kb], vl[0], vl[1]);
                mma_bf16(acc[2 * ntp],     plo[kb], vh[0], vh[1]);
                mma_bf16(acc[2 * ntp + 1], phi[kb], vh[2], vh[3]);
                mma_bf16(acc[2 * ntp + 1], phi[kb], vl[2], vl[3]);
                mma_bf16(acc[2 * ntp + 1], plo[kb], vh[2], vh[3]);
            }
        }
        __syncthreads();
    }

    // ---- finalize edges + row sums ----
    l_g = quadsum(l_g); l_h = quadsum(l_h);
    lo_g = quadsum(lo_g); lo_h = quadsum(lo_h);
    hi_g = quadsum(hi_g); hi_h = quadsum(hi_h);
    if ((lane & 3) == 0) {
        prowg[0] = lo_g; prowg[128] = hi_g;
        prowh[0] = lo_h; prowh[128] = hi_h;
    }
    __syncthreads();

    // ---- rel-value epilogue: acc += ps @ tab ----
    float* tabS = (float*)(dsm + 2 * FA_QAS);
    for (int r0 = 0; r0 < VOCAB; r0 += 16) {
        __syncthreads();
        {
            int rr = t >> 4, cc = (t & 15) * 4;
            int r = r0 + rr;
            float4 tv = (r < VOCAB) ? *(const float4*)&g_tab[r * 64 + cc]
                                    : make_float4(0.f, 0.f, 0.f, 0.f);
            *(float4*)&tabS[rr * 68 + cc] = tv;
        }
        __syncthreads();
        #pragma unroll
        for (int rc = 0; rc < 16; rc++) {
            int rr2 = r0 + rc; if (rr2 > 128) rr2 = 128;
            float pg = prowg[rr2];
            float ph = prowh[rr2];
            #pragma unroll
            for (int nt = 0; nt < 8; nt++) {
                int d = nt * 8 + tq;
                float t0 = tabS[rc * 68 + d], t1 = tabS[rc * 68 + d + 1];
                acc[nt][0] += pg * t0; acc[nt][1] += pg * t1;
                acc[nt][2] += ph * t0; acc[nt][3] += ph * t1;
            }
        }
    }

    // ---- normalize + write ----
    float ig = 1.0f / l_g, ih = 1.0f / l_h;
    #pragma unroll
    for (int nt = 0; nt < 8; nt++) {
        int d = nt * 8 + tq;
        *(float2*)(out + ((size_t)(b * SEQ + qg)) * HID + h * 64 + d) =
            make_float2(acc[nt][0] * ig, acc[nt][1] * ig);
        *(float2*)(out + ((size_t)(b * SEQ + qh2)) * HID + h * 64 + d) =
            make_float2(acc[nt][2] * ih, acc[nt][3] * ih);
    }
}

// ---------------- launcher ----------------
extern "C" void kernel_launch(void* const* d_in, const int* in_sizes, int n_in,
                              void* d_out, int out_size) {
    const float* hs   = (const float*)d_in[0];
    const float* mask = (const float*)d_in[1];
    const float* Wq   = (const float*)d_in[2];
    const float* bq   = (const float*)d_in[3];
    const float* Wk   = (const float*)d_in[4];
    const float* bk   = (const float*)d_in[5];
    const float* Wv   = (const float*)d_in[6];
    const float* bv   = (const float*)d_in[7];
    float* out = (float*)d_out;

    cudaFuncSetAttribute(qkv_mma_kernel,    cudaFuncAttributeMaxDynamicSharedMemorySize, QKV_SMEM);
    cudaFuncSetAttribute(attn_fused_kernel, cudaFuncAttributeMaxDynamicSharedMemorySize, FA_SMEM);

    init_tab_kernel<<<(VOCAB * 32 + 127) / 128, 128>>>();
    cvt_hs_kernel<<<(BATCH * SEQ * HID / 4 + 255) / 256, 256>>>(hs);
    cvt_w_kernel<<<(3 * HID * HID / 4 + 255) / 256, 256>>>(Wq, Wk, Wv);
    qkv_mma_kernel<<<dim3(HID / 128, (BATCH * SEQ) / 128, 3), 256, QKV_SMEM>>>(bq, bk, bv);
    qrel_kernel<<<BH * SEQ / 128, 256>>>();
    attn_fused_kernel<<<dim3(SEQ / 128, BH), 256, FA_SMEM>>>(mask, out);
}

// round 9
// speedup vs baseline: 2.6411x; 1.0881x over previous
#include <cuda_runtime.h>
#include <cuda_bf16.h>
#include <cstdint>

#define BATCH 2
#define SEQ   1024
#define HID   1024
#define NHEAD 16
#define HDIM  64
#define BH    (BATCH*NHEAD)      // 32
#define VOCAB 129                // 2*64+1
#define SSTR  40                 // bf16 smem stride (BK=32 tiles): conflict-free
#define SST2  72                 // bf16 smem stride (64-col tiles): conflict-free

// ---------------- scratch ----------------
__device__ __align__(16) float g_qkv[BH * SEQ * HDIM];           // Q fp32 (for qrel)
__device__ __align__(16) float g_qrel[(size_t)BH * SEQ * VOCAB];
__device__ __align__(16) float g_tab[VOCAB * HDIM];

__device__ __align__(16) __nv_bfloat16 g_hs_hi[BATCH * SEQ * HID];
__device__ __align__(16) __nv_bfloat16 g_hs_lo[BATCH * SEQ * HID];
__device__ __align__(16) __nv_bfloat16 g_w_hi[3 * HID * HID];
__device__ __align__(16) __nv_bfloat16 g_w_lo[3 * HID * HID];
__device__ __align__(16) __nv_bfloat16 g_qh[BH * SEQ * HDIM];
__device__ __align__(16) __nv_bfloat16 g_ql[BH * SEQ * HDIM];
__device__ __align__(16) __nv_bfloat16 g_kh[BH * SEQ * HDIM];
__device__ __align__(16) __nv_bfloat16 g_kl[BH * SEQ * HDIM];
__device__ __align__(16) __nv_bfloat16 g_vth[BH * HDIM * SEQ];   // V^T [bh][d][s]
__device__ __align__(16) __nv_bfloat16 g_vtl[BH * HDIM * SEQ];

// ---------------- helpers ----------------
__device__ __forceinline__ void cp_async16(void* dst, const void* src) {
    unsigned int d = (unsigned int)__cvta_generic_to_shared(dst);
    asm volatile("cp.async.cg.shared.global [%0], [%1], 16;" :: "r"(d), "l"(src));
}
__device__ __forceinline__ void cp_commit() { asm volatile("cp.async.commit_group;"); }
__device__ __forceinline__ void cp_wait0()  { asm volatile("cp.async.wait_group 0;"); }
__device__ __forceinline__ void cp_wait1()  { asm volatile("cp.async.wait_group 1;"); }
__device__ __forceinline__ void cp_wait2()  { asm volatile("cp.async.wait_group 2;"); }

__device__ __forceinline__ void ldsm4(unsigned* r, const void* p) {
    unsigned a = (unsigned)__cvta_generic_to_shared(p);
    asm volatile("ldmatrix.sync.aligned.m8n8.x4.shared.b16 {%0,%1,%2,%3}, [%4];"
                 : "=r"(r[0]), "=r"(r[1]), "=r"(r[2]), "=r"(r[3]) : "r"(a));
}

__device__ __forceinline__ void split_bf16(float v, __nv_bfloat16& hi, __nv_bfloat16& lo) {
    hi = __float2bfloat16_rn(v);
    lo = __float2bfloat16_rn(v - __bfloat162float(hi));
}
__device__ __forceinline__ unsigned pack2h(float a, float b) {
    __nv_bfloat162 p(__float2bfloat16_rn(a), __float2bfloat16_rn(b));
    return *(unsigned*)&p;
}
__device__ __forceinline__ unsigned pack2l(float a, float b) {
    float ra = a - __bfloat162float(__float2bfloat16_rn(a));
    float rb = b - __bfloat162float(__float2bfloat16_rn(b));
    __nv_bfloat162 p(__float2bfloat16_rn(ra), __float2bfloat16_rn(rb));
    return *(unsigned*)&p;
}
__device__ __forceinline__ float quadmax(float v) {
    v = fmaxf(v, __shfl_xor_sync(0xffffffffu, v, 1));
    v = fmaxf(v, __shfl_xor_sync(0xffffffffu, v, 2));
    return v;
}
__device__ __forceinline__ float quadsum(float v) {
    v += __shfl_xor_sync(0xffffffffu, v, 1);
    v += __shfl_xor_sync(0xffffffffu, v, 2);
    return v;
}
__device__ __forceinline__ void mma_bf16(float* c, const unsigned int* A,
                                         unsigned int b0, unsigned int b1) {
    asm volatile("mma.sync.aligned.m16n8k16.row.col.f32.bf16.bf16.f32 "
        "{%0,%1,%2,%3}, {%4,%5,%6,%7}, {%8,%9}, {%0,%1,%2,%3};"
        : "+f"(c[0]), "+f"(c[1]), "+f"(c[2]), "+f"(c[3])
        : "r"(A[0]), "r"(A[1]), "r"(A[2]), "r"(A[3]), "r"(b0), "r"(b1));
}

// ---------------- sinusoid table ----------------
__global__ void init_tab_kernel() {
    int idx = blockIdx.x * blockDim.x + threadIdx.x;
    if (idx >= VOCAB * 32) return;
    int p = idx >> 5, i = idx & 31;
    float div = expf((float)(2 * i) * (-9.210340371976184f / 64.0f));
    float ang = (float)p * div;
    g_tab[p * 64 + 2 * i]     = sinf(ang);
    g_tab[p * 64 + 2 * i + 1] = cosf(ang);
}

__global__ __launch_bounds__(256) void cvt_hs_kernel(const float* __restrict__ hs) {
    int i = (blockIdx.x * blockDim.x + threadIdx.x) * 4;
    if (i >= BATCH * SEQ * HID) return;
    float4 v = *(const float4*)(hs + i);
    __nv_bfloat16 h, l;
    split_bf16(v.x, h, l); g_hs_hi[i + 0] = h; g_hs_lo[i + 0] = l;
    split_bf16(v.y, h, l); g_hs_hi[i + 1] = h; g_hs_lo[i + 1] = l;
    split_bf16(v.z, h, l); g_hs_hi[i + 2] = h; g_hs_lo[i + 2] = l;
    split_bf16(v.w, h, l); g_hs_hi[i + 3] = h; g_hs_lo[i + 3] = l;
}

__global__ __launch_bounds__(256) void cvt_w_kernel(
    const float* __restrict__ Wq, const float* __restrict__ Wk, const float* __restrict__ Wv) {
    int i = (blockIdx.x * blockDim.x + threadIdx.x) * 4;
    if (i >= 3 * HID * HID) return;
    int z = i / (HID * HID), r = i - z * (HID * HID);
    const float* W = (z == 0) ? Wq : (z == 1 ? Wk : Wv);
    float4 v = *(const float4*)(W + r);
    __nv_bfloat16 h, l;
    split_bf16(v.x, h, l); g_w_hi[i + 0] = h; g_w_lo[i + 0] = l;
    split_bf16(v.y, h, l); g_w_hi[i + 1] = h; g_w_lo[i + 1] = l;
    split_bf16(v.z, h, l); g_w_hi[i + 2] = h; g_w_lo[i + 2] = l;
    split_bf16(v.w, h, l); g_w_hi[i + 3] = h; g_w_lo[i + 3] = l;
}

// ---------------- phase 1: QKV projection, 3-stage BK=32 + ldmatrix ----------------
#define QKV_AS    (128 * SSTR)        // 5120 elems per array
#define QKV_STAGE (4 * QKV_AS)        // 20480 elems
#define QKV_SMEM  (3 * QKV_STAGE * 2) // 122880 B

__global__ __launch_bounds__(256) void qkv_mma_kernel(
    const float* __restrict__ bq, const float* __restrict__ bk, const float* __restrict__ bv)
{
    extern __shared__ __align__(16) __nv_bfloat16 dsm[];
    int z = blockIdx.z;
    const float* bias = (z == 0) ? bq : (z == 1 ? bk : bv);
    const __nv_bfloat16* gWhi = g_w_hi + (size_t)z * HID * HID;
    const __nv_bfloat16* gWlo = g_w_lo + (size_t)z * HID * HID;

    int m0 = blockIdx.y * 128, n0 = blockIdx.x * 128;
    int t = threadIdx.x;
    int lane = t & 31, warp = t >> 5;
    int wy = warp >> 2, wx = warp & 3;
    int g = lane >> 2, tq = (lane & 3) * 2;
    int arow = lane & 15, acol8 = (lane >> 4) * 8;
    int brow = ((lane >> 4) << 3) + (lane & 7), bcol8 = ((lane >> 3) & 1) * 8;

    float acc[4][4][4] = {};

    auto load_stage = [&](int stg, int k0) {
        __nv_bfloat16* base = dsm + stg * QKV_STAGE;
        #pragma unroll
        for (int u = 0; u < 2; u++) {
            int idx = t + 256 * u;
            int r = idx >> 2, ce = (idx & 3) * 8;
            size_t ga = (size_t)(m0 + r) * HID + k0 + ce;
            size_t gb = (size_t)(n0 + r) * HID + k0 + ce;
            int so = r * SSTR + ce;
            cp_async16(base + 0 * QKV_AS + so, g_hs_hi + ga);
            cp_async16(base + 1 * QKV_AS + so, g_hs_lo + ga);
            cp_async16(base + 2 * QKV_AS + so, gWhi + gb);
            cp_async16(base + 3 * QKV_AS + so, gWlo + gb);
        }
    };

    load_stage(0, 0);  cp_commit();
    load_stage(1, 32); cp_commit();

    for (int k0 = 0; k0 < HID; k0 += 32) {
        int it = k0 >> 5;
        int stg = it % 3;
        if (k0 + 64 < HID) { load_stage((it + 2) % 3, k0 + 64); cp_commit(); cp_wait2(); }
        else               { cp_wait0(); }
        __syncthreads();
        const __nv_bfloat16* sAhi = dsm + stg * QKV_STAGE;
        const __nv_bfloat16* sAlo = sAhi + QKV_AS;
        const __nv_bfloat16* sBhi = sAlo + QKV_AS;
        const __nv_bfloat16* sBlo = sBhi + QKV_AS;

        #pragma unroll
        for (int kk = 0; kk < 32; kk += 16) {
            unsigned ahi[4][4], alo[4][4];
            #pragma unroll
            for (int mt = 0; mt < 4; mt++) {
                int ab = (wy * 64 + mt * 16 + arow) * SSTR + kk + acol8;
                ldsm4(ahi[mt], sAhi + ab);
                ldsm4(alo[mt], sAlo + ab);
            }
            #pragma unroll
            for (int ntp = 0; ntp < 2; ntp++) {
                int bb = (wx * 32 + ntp * 16 + brow) * SSTR + kk + bcol8;
                unsigned bh[4], bl[4];
                ldsm4(bh, sBhi + bb);
                ldsm4(bl, sBlo + bb);
                #pragma unroll
                for (int mt = 0; mt < 4; mt++) {
                    mma_bf16(acc[mt][2 * ntp],     ahi[mt], bh[0], bh[1]);
                    mma_bf16(acc[mt][2 * ntp],     ahi[mt], bl[0], bl[1]);
                    mma_bf16(acc[mt][2 * ntp],     alo[mt], bh[0], bh[1]);
                    mma_bf16(acc[mt][2 * ntp + 1], ahi[mt], bh[2], bh[3]);
                    mma_bf16(acc[mt][2 * ntp + 1], ahi[mt], bl[2], bl[3]);
                    mma_bf16(acc[mt][2 * ntp + 1], alo[mt], bh[2], bh[3]);
                }
            }
        }
        __syncthreads();
    }

    #pragma unroll
    for (int nt = 0; nt < 4; nt++) {
        int n = n0 + wx * 32 + nt * 8 + tq;
        float2 b2 = *(const float2*)&bias[n];
        int h = n >> 6, d = n & 63;
        #pragma unroll
        for (int mt = 0; mt < 4; mt++) {
            int m = m0 + wy * 64 + mt * 16 + g;
            int b = m >> 10, s = m & (SEQ - 1);
            int bh = b * NHEAD + h;
            float v0 = acc[mt][nt][0] + b2.x, v1 = acc[mt][nt][1] + b2.y;
            float v2 = acc[mt][nt][2] + b2.x, v3 = acc[mt][nt][3] + b2.y;
            __nv_bfloat16 h0, l0, h1, l1, h2, l2, h3, l3;
            split_bf16(v0, h0, l0); split_bf16(v1, h1, l1);
            split_bf16(v2, h2, l2); split_bf16(v3, h3, l3);
            if (z < 2) {
                __nv_bfloat16* ah = (z == 0) ? g_qh : g_kh;
                __nv_bfloat16* al = (z == 0) ? g_ql : g_kl;
                size_t o0 = ((size_t)bh * SEQ + s) * HDIM + d;
                size_t o1 = o0 + 8 * HDIM;
                *(__nv_bfloat162*)(ah + o0) = __nv_bfloat162(h0, h1);
                *(__nv_bfloat162*)(al + o0) = __nv_bfloat162(l0, l1);
                *(__nv_bfloat162*)(ah + o1) = __nv_bfloat162(h2, h3);
                *(__nv_bfloat162*)(al + o1) = __nv_bfloat162(l2, l3);
                if (z == 0) {
                    *(float2*)(g_qkv + o0) = make_float2(v0, v1);
                    *(float2*)(g_qkv + o1) = make_float2(v2, v3);
                }
            } else {
                size_t base = ((size_t)bh * HDIM + d) * SEQ + s;
                g_vth[base] = h0;           g_vtl[base] = l0;
                g_vth[base + SEQ] = h1;     g_vtl[base + SEQ] = l1;
                g_vth[base + 8] = h2;       g_vtl[base + 8] = l2;
                g_vth[base + SEQ + 8] = h3; g_vtl[base + SEQ + 8] = l3;
            }
        }
    }
}

// ---------------- phase 1.5: qrel = Q @ tab^T, broadcast-friendly ----------------
__global__ __launch_bounds__(256) void qrel_kernel() {
    int t = threadIdx.x;
    int row = blockIdx.x * 128 + (t & 127);
    int half = t >> 7;
    const float* Q = g_qkv + (size_t)row * HDIM;
    float q[64];
    #pragma unroll
    for (int d4 = 0; d4 < 16; d4++) {
        float4 v = *(const float4*)(Q + d4 * 4);
        q[d4 * 4 + 0] = v.x; q[d4 * 4 + 1] = v.y;
        q[d4 * 4 + 2] = v.z; q[d4 * 4 + 3] = v.w;
    }
    int c0 = half * 65;
    int cn = half ? 64 : 65;
    float* dst = g_qrel + (size_t)row * VOCAB;
    for (int j = 0; j < cn; j++) {
        int c = c0 + j;
        const float* tr = g_tab + c * 64;
        float s = 0.f;
        #pragma unroll
        for (int d4 = 0; d4 < 16; d4++) {
            float4 tv = *(const float4*)(tr + d4 * 4);
            s += q[d4*4]*tv.x + q[d4*4+1]*tv.y + q[d4*4+2]*tv.z + q[d4*4+3]*tv.w;
        }
        dst[c] = s;
    }
}

// ---------------- phase 2-4 fused: flash attention + rel-pos ----------------
// ps band stores RAW SCORES (no online rescale); exp applied once at the end.
#define FA_QAS   9216                  // 128*72
#define FA_KAS   4608                  // 64*72
#define FA_STAGE (4 * FA_KAS)
#define FA_PSOFF (2 * FA_QAS + 2 * FA_STAGE)
#define FA_SMEM  (FA_PSOFF * 2 + 128 * 132 * 4)

__global__ __launch_bounds__(256) void attn_fused_kernel(
    const float* __restrict__ mask, float* __restrict__ out)
{
    extern __shared__ __align__(16) __nv_bfloat16 dsm[];
    const int bh = blockIdx.y, b = bh >> 4, h = bh & 15;
    const int q0 = blockIdx.x * 128;
    const int t = threadIdx.x, lane = t & 31, w = t >> 5;
    const int g = lane >> 2, tq = (lane & 3) * 2;
    const int arow = lane & 15, acol8 = (lane >> 4) * 8;
    const int brow = ((lane >> 4) << 3) + (lane & 7), bcol8 = ((lane >> 3) & 1) * 8;

    __nv_bfloat16* sQhi = dsm;
    __nv_bfloat16* sQlo = dsm + FA_QAS;
    float* psm = (float*)(dsm + FA_PSOFF);

    for (int i = t; i < 128 * 132; i += 256) psm[i] = -1e30f;

    #pragma unroll
    for (int u = 0; u < 4; u++) {
        int idx = t + 256 * u;
        int r = idx >> 3, ce = (idx & 7) * 8;
        size_t ga = ((size_t)bh * SEQ + q0 + r) * HDIM + ce;
        int so = r * SST2 + ce;
        cp_async16(sQhi + so, g_qh + ga);
        cp_async16(sQlo + so, g_ql + ga);
    }
    auto load_kv = [&](int stg, int kt0) {
        __nv_bfloat16* base = dsm + 2 * FA_QAS + stg * FA_STAGE;
        #pragma unroll
        for (int u = 0; u < 2; u++) {
            int idx = t + 256 * u;
            int r = idx >> 3, ce = (idx & 7) * 8;
            int so = r * SST2 + ce;
            size_t gk = ((size_t)bh * SEQ + kt0 + r) * HDIM + ce;
            size_t gv = ((size_t)bh * HDIM + r) * SEQ + kt0 + ce;
            cp_async16(base + 0 * FA_KAS + so, g_kh + gk);
            cp_async16(base + 1 * FA_KAS + so, g_kl + gk);
            cp_async16(base + 2 * FA_KAS + so, g_vth + gv);
            cp_async16(base + 3 * FA_KAS + so, g_vtl + gv);
        }
    };
    load_kv(0, 0);
    cp_commit();

    const int qg = q0 + w * 16 + g;
    const int qh2 = qg + 8;
    const float* qrg = g_qrel + ((size_t)bh * SEQ + qg) * VOCAB;
    const float* qrh = g_qrel + ((size_t)bh * SEQ + qh2) * VOCAB;
    float* prowg = psm + (w * 16 + g) * 132;
    float* prowh = prowg + 8 * 132;

    float acc[8][4] = {};
    float m_g = -1e30f, m_h = -1e30f;
    float l_g = 0.f, l_h = 0.f, lo_g = 0.f, lo_h = 0.f, hi_g = 0.f, hi_h = 0.f;

    for (int kt = 0; kt < 16; kt++) {
        int kt0 = kt * 64;
        if (kt < 15) { load_kv((kt ^ 1) & 1, kt0 + 64); cp_commit(); cp_wait1(); }
        else         { cp_wait0(); }
        __syncthreads();
        const __nv_bfloat16* stage = dsm + 2 * FA_QAS + (kt & 1) * FA_STAGE;
        const __nv_bfloat16* sKhi = stage;
        const __nv_bfloat16* sKlo = stage + FA_KAS;
        const __nv_bfloat16* sVhi = stage + 2 * FA_KAS;
        const __nv_bfloat16* sVlo = stage + 3 * FA_KAS;

        // ---- S = Q K^T (split, ldmatrix) ----
        float s[8][4] = {};
        #pragma unroll
        for (int kk = 0; kk < 64; kk += 16) {
            unsigned ahi[4], alo[4];
            int ab = (w * 16 + arow) * SST2 + kk + acol8;
            ldsm4(ahi, sQhi + ab);
            ldsm4(alo, sQlo + ab);
            #pragma unroll
            for (int ntp = 0; ntp < 4; ntp++) {
                int bb = (ntp * 16 + brow) * SST2 + kk + bcol8;
                unsigned kh[4], kl[4];
                ldsm4(kh, sKhi + bb);
                ldsm4(kl, sKlo + bb);
                mma_bf16(s[2 * ntp],     ahi, kh[0], kh[1]);
                mma_bf16(s[2 * ntp],     ahi, kl[0], kl[1]);
                mma_bf16(s[2 * ntp],     alo, kh[0], kh[1]);
                mma_bf16(s[2 * ntp + 1], ahi, kh[2], kh[3]);
                mma_bf16(s[2 * ntp + 1], ahi, kl[2], kl[3]);
                mma_bf16(s[2 * ntp + 1], alo, kh[2], kh[3]);
            }
        }

        // ---- scores epilogue: qrel + scale + mask; stash raw s in band ----
        #pragma unroll
        for (int nt = 0; nt < 8; nt++) {
            int k = kt0 + nt * 8 + tq;
            float mk0 = mask[b * SEQ + k], mk1 = mask[b * SEQ + k + 1];
            int c;
            c = k - qg;      c = c < -64 ? -64 : (c > 64 ? 64 : c);
            s[nt][0] = (s[nt][0] + qrg[c + 64]) * 0.125f + mk0;
            c = k + 1 - qg;  c = c < -64 ? -64 : (c > 64 ? 64 : c);
            s[nt][1] = (s[nt][1] + qrg[c + 64]) * 0.125f + mk1;
            c = k - qh2;     c = c < -64 ? -64 : (c > 64 ? 64 : c);
            s[nt][2] = (s[nt][2] + qrh[c + 64]) * 0.125f + mk0;
            c = k + 1 - qh2; c = c < -64 ? -64 : (c > 64 ? 64 : c);
            s[nt][3] = (s[nt][3] + qrh[c + 64]) * 0.125f + mk1;
            // raw scores into band (unique (q,k); no rescale needed)
            int d0 = k - qg, d1 = k + 1 - qg;
            if (d0 > -64 && d0 < 64) prowg[d0 + 64] = s[nt][0];
            if (d1 > -64 && d1 < 64) prowg[d1 + 64] = s[nt][1];
            int e0 = k - qh2, e1 = k + 1 - qh2;
            if (e0 > -64 && e0 < 64) prowh[e0 + 64] = s[nt][2];
            if (e1 > -64 && e1 < 64) prowh[e1 + 64] = s[nt][3];
        }

        // ---- online softmax (registers only) ----
        float tg = -1e30f, th = -1e30f;
        #pragma unroll
        for (int nt = 0; nt < 8; nt++) {
            tg = fmaxf(tg, fmaxf(s[nt][0], s[nt][1]));
            th = fmaxf(th, fmaxf(s[nt][2], s[nt][3]));
        }
        tg = quadmax(tg); th = quadmax(th);
        float mng = fmaxf(m_g, tg), mnh = fmaxf(m_h, th);
        float scg = __expf(m_g - mng), sch = __expf(m_h - mnh);
        if (scg < 1.0f) {
            #pragma unroll
            for (int nt = 0; nt < 8; nt++) { acc[nt][0] *= scg; acc[nt][1] *= scg; }
            l_g *= scg; lo_g *= scg; hi_g *= scg;
        }
        if (sch < 1.0f) {
            #pragma unroll
            for (int nt = 0; nt < 8; nt++) { acc[nt][2] *= sch; acc[nt][3] *= sch; }
            l_h *= sch; lo_h *= sch; hi_h *= sch;
        }
        m_g = mng; m_h = mnh;

        // ---- p = exp, edge sums, pack A-frags ----
        unsigned phi[4][4], plo[4][4];
        #pragma unroll
        for (int nt = 0; nt < 8; nt++) {
            int k = kt0 + nt * 8 + tq;
            float p0 = __expf(s[nt][0] - m_g), p1 = __expf(s[nt][1] - m_g);
            float p2 = __expf(s[nt][2] - m_h), p3 = __expf(s[nt][3] - m_h);
            l_g += p0 + p1; l_h += p2 + p3;
            int d0 = k - qg, d1 = k + 1 - qg;
            if (d0 <= -64) lo_g += p0; else if (d0 >= 64) hi_g += p0;
            if (d1 <= -64) lo_g += p1; else if (d1 >= 64) hi_g += p1;
            int e0 = k - qh2, e1 = k + 1 - qh2;
            if (e0 <= -64) lo_h += p2; else if (e0 >= 64) hi_h += p2;
            if (e1 <= -64) lo_h += p3; else if (e1 >= 64) hi_h += p3;
            int kb = nt >> 1;
            if ((nt & 1) == 0) {
                phi[kb][0] = pack2h(p0, p1); phi[kb][1] = pack2h(p2, p3);
                plo[kb][0] = pack2l(p0, p1); plo[kb][1] = pack2l(p2, p3);
            } else {
                phi[kb][2] = pack2h(p0, p1); phi[kb][3] = pack2h(p2, p3);
                plo[kb][2] = pack2l(p0, p1); plo[kb][3] = pack2l(p2, p3);
            }
        }

        // ---- O += P V (split, ldmatrix B) ----
        #pragma unroll
        for (int kb = 0; kb < 4; kb++) {
            int kk = kb * 16;
            #pragma unroll
            for (int ntp = 0; ntp < 4; ntp++) {
                int bb = (ntp * 16 + brow) * SST2 + kk + bcol8;
                unsigned vh[4], vl[4];
                ldsm4(vh, sVhi + bb);
                ldsm4(vl, sVlo + bb);
                mma_bf16(acc[2 * ntp],     phi[kb], vh[0], vh[1]);
                mma_bf16(acc[2 * ntp],     phi[kb], vl[0], vl[1]);
                mma_bf16(acc[2 * ntp],     plo[kb], vh[0], vh[1]);
                mma_bf16(acc[2 * ntp + 1], phi[kb], vh[2], vh[3]);
                mma_bf16(acc[2 * ntp + 1], phi[kb], vl[2], vl[3]);
                mma_bf16(acc[2 * ntp + 1], plo[kb], vh[2], vh[3]);
            }
        }
        __syncthreads();
    }

    // ---- finalize: row sums, edges, convert band scores -> probs ----
    l_g = quadsum(l_g); l_h = quadsum(l_h);
    lo_g = quadsum(lo_g); lo_h = quadsum(lo_h);
    hi_g = quadsum(hi_g); hi_h = quadsum(hi_h);
    if ((lane & 3) == 0) {
        prowg[0] = lo_g; prowg[128] = hi_g;
        prowh[0] = lo_h; prowh[128] = hi_h;
    }
    {
        int c0 = (lane & 3) * 33; if (c0 == 0) c0 = 1;
        int c1 = (lane & 3) * 33 + 33; if (c1 > 128) c1 = 128;
        for (int c = c0; c < c1; c++) {
            prowg[c] = __expf(prowg[c] - m_g);
            prowh[c] = __expf(prowh[c] - m_h);
        }
    }
    __syncthreads();

    // ---- rel-value epilogue: acc += ps @ tab ----
    float* tabS = (float*)(dsm + 2 * FA_QAS);
    for (int r0 = 0; r0 < VOCAB; r0 += 16) {
        __syncthreads();
        {
            int rr = t >> 4, cc = (t & 15) * 4;
            int r = r0 + rr;
            float4 tv = (r < VOCAB) ? *(const float4*)&g_tab[r * 64 + cc]
                                    : make_float4(0.f, 0.f, 0.f, 0.f);
            *(float4*)&tabS[rr * 68 + cc] = tv;
        }
        __syncthreads();
        #pragma unroll
        for (int rc = 0; rc < 16; rc++) {
            int rr2 = r0 + rc; if (rr2 > 128) rr2 = 128;
            float pg = prowg[rr2];
            float ph = prowh[rr2];
            #pragma unroll
            for (int nt = 0; nt < 8; nt++) {
                int d = nt * 8 + tq;
                float t0 = tabS[rc * 68 + d], t1 = tabS[rc * 68 + d + 1];
                acc[nt][0] += pg * t0; acc[nt][1] += pg * t1;
                acc[nt][2] += ph * t0; acc[nt][3] += ph * t1;
            }
        }
    }

    // ---- normalize + write ----
    float ig = 1.0f / l_g, ih = 1.0f / l_h;
    #pragma unroll
    for (int nt = 0; nt < 8; nt++) {
        int d = nt * 8 + tq;
        *(float2*)(out + ((size_t)(b * SEQ + qg)) * HID + h * 64 + d) =
            make_float2(acc[nt][0] * ig, acc[nt][1] * ig);
        *(float2*)(out + ((size_t)(b * SEQ + qh2)) * HID + h * 64 + d) =
            make_float2(acc[nt][2] * ih, acc[nt][3] * ih);
    }
}

// ---------------- launcher ----------------
extern "C" void kernel_launch(void* const* d_in, const int* in_sizes, int n_in,
                              void* d_out, int out_size) {
    const float* hs   = (const float*)d_in[0];
    const float* mask = (const float*)d_in[1];
    const float* Wq   = (const float*)d_in[2];
    const float* bq   = (const float*)d_in[3];
    const float* Wk   = (const float*)d_in[4];
    const float* bk   = (const float*)d_in[5];
    const float* Wv   = (const float*)d_in[6];
    const float* bv   = (const float*)d_in[7];
    float* out = (float*)d_out;

    cudaFuncSetAttribute(qkv_mma_kernel,    cudaFuncAttributeMaxDynamicSharedMemorySize, QKV_SMEM);
    cudaFuncSetAttribute(attn_fused_kernel, cudaFuncAttributeMaxDynamicSharedMemorySize, FA_SMEM);

    init_tab_kernel<<<(VOCAB * 32 + 127) / 128, 128>>>();
    cvt_hs_kernel<<<(BATCH * SEQ * HID / 4 + 255) / 256, 256>>>(hs);
    cvt_w_kernel<<<(3 * HID * HID / 4 + 255) / 256, 256>>>(Wq, Wk, Wv);
    qkv_mma_kernel<<<dim3(HID / 128, (BATCH * SEQ) / 128, 3), 256, QKV_SMEM>>>(bq, bk, bv);
    qrel_kernel<<<BH * SEQ / 128, 256>>>();
    attn_fused_kernel<<<dim3(SEQ / 128, BH), 256, FA_SMEM>>>(mask, out);
}

// round 10
// speedup vs baseline: 2.7524x; 1.0421x over previous
#include <cuda_runtime.h>
#include <cuda_bf16.h>
#include <cstdint>

#define BATCH 2
#define SEQ   1024
#define HID   1024
#define NHEAD 16
#define HDIM  64
#define BH    (BATCH*NHEAD)      // 32
#define VOCAB 129                // 2*64+1
#define SST2  72                 // bf16 smem stride: conflict-free

// ---------------- scratch ----------------
__device__ __align__(16) float g_qkv[BH * SEQ * HDIM];           // Q fp32 (for qrel)
__device__ __align__(16) float g_qrel[(size_t)BH * SEQ * VOCAB];
__device__ __align__(16) float g_tab[VOCAB * HDIM];

__device__ __align__(16) __nv_bfloat16 g_hs_hi[BATCH * SEQ * HID];
__device__ __align__(16) __nv_bfloat16 g_hs_lo[BATCH * SEQ * HID];
__device__ __align__(16) __nv_bfloat16 g_w_hi[3 * HID * HID];
__device__ __align__(16) __nv_bfloat16 g_w_lo[3 * HID * HID];
__device__ __align__(16) __nv_bfloat16 g_qh[BH * SEQ * HDIM];
__device__ __align__(16) __nv_bfloat16 g_ql[BH * SEQ * HDIM];
__device__ __align__(16) __nv_bfloat16 g_kh[BH * SEQ * HDIM];
__device__ __align__(16) __nv_bfloat16 g_kl[BH * SEQ * HDIM];
__device__ __align__(16) __nv_bfloat16 g_vth[BH * HDIM * SEQ];   // V^T [bh][d][s]
__device__ __align__(16) __nv_bfloat16 g_vtl[BH * HDIM * SEQ];

// ---------------- helpers ----------------
__device__ __forceinline__ void cp_async16(void* dst, const void* src) {
    unsigned int d = (unsigned int)__cvta_generic_to_shared(dst);
    asm volatile("cp.async.cg.shared.global [%0], [%1], 16;" :: "r"(d), "l"(src));
}
__device__ __forceinline__ void cp_commit() { asm volatile("cp.async.commit_group;"); }
__device__ __forceinline__ void cp_wait0()  { asm volatile("cp.async.wait_group 0;"); }
__device__ __forceinline__ void cp_wait1()  { asm volatile("cp.async.wait_group 1;"); }

__device__ __forceinline__ void ldsm4(unsigned* r, const void* p) {
    unsigned a = (unsigned)__cvta_generic_to_shared(p);
    asm volatile("ldmatrix.sync.aligned.m8n8.x4.shared.b16 {%0,%1,%2,%3}, [%4];"
                 : "=r"(r[0]), "=r"(r[1]), "=r"(r[2]), "=r"(r[3]) : "r"(a));
}

__device__ __forceinline__ void split_bf16(float v, __nv_bfloat16& hi, __nv_bfloat16& lo) {
    hi = __float2bfloat16_rn(v);
    lo = __float2bfloat16_rn(v - __bfloat162float(hi));
}
__device__ __forceinline__ unsigned pack2h(float a, float b) {
    __nv_bfloat162 p(__float2bfloat16_rn(a), __float2bfloat16_rn(b));
    return *(unsigned*)&p;
}
__device__ __forceinline__ unsigned pack2l(float a, float b) {
    float ra = a - __bfloat162float(__float2bfloat16_rn(a));
    float rb = b - __bfloat162float(__float2bfloat16_rn(b));
    __nv_bfloat162 p(__float2bfloat16_rn(ra), __float2bfloat16_rn(rb));
    return *(unsigned*)&p;
}
__device__ __forceinline__ float quadmax(float v) {
    v = fmaxf(v, __shfl_xor_sync(0xffffffffu, v, 1));
    v = fmaxf(v, __shfl_xor_sync(0xffffffffu, v, 2));
    return v;
}
__device__ __forceinline__ float quadsum(float v) {
    v += __shfl_xor_sync(0xffffffffu, v, 1);
    v += __shfl_xor_sync(0xffffffffu, v, 2);
    return v;
}
__device__ __forceinline__ void mma_bf16(float* c, const unsigned int* A,
                                         unsigned int b0, unsigned int b1) {
    asm volatile("mma.sync.aligned.m16n8k16.row.col.f32.bf16.bf16.f32 "
        "{%0,%1,%2,%3}, {%4,%5,%6,%7}, {%8,%9}, {%0,%1,%2,%3};"
        : "+f"(c[0]), "+f"(c[1]), "+f"(c[2]), "+f"(c[3])
        : "r"(A[0]), "r"(A[1]), "r"(A[2]), "r"(A[3]), "r"(b0), "r"(b1));
}

// ---------------- sinusoid table ----------------
__global__ void init_tab_kernel() {
    int idx = blockIdx.x * blockDim.x + threadIdx.x;
    if (idx >= VOCAB * 32) return;
    int p = idx >> 5, i = idx & 31;
    float div = expf((float)(2 * i) * (-9.210340371976184f / 64.0f));
    float ang = (float)p * div;
    g_tab[p * 64 + 2 * i]     = sinf(ang);
    g_tab[p * 64 + 2 * i + 1] = cosf(ang);
}

__global__ __launch_bounds__(256) void cvt_hs_kernel(const float* __restrict__ hs) {
    int i = (blockIdx.x * blockDim.x + threadIdx.x) * 4;
    if (i >= BATCH * SEQ * HID) return;
    float4 v = *(const float4*)(hs + i);
    __nv_bfloat16 h, l;
    split_bf16(v.x, h, l); g_hs_hi[i + 0] = h; g_hs_lo[i + 0] = l;
    split_bf16(v.y, h, l); g_hs_hi[i + 1] = h; g_hs_lo[i + 1] = l;
    split_bf16(v.z, h, l); g_hs_hi[i + 2] = h; g_hs_lo[i + 2] = l;
    split_bf16(v.w, h, l); g_hs_hi[i + 3] = h; g_hs_lo[i + 3] = l;
}

__global__ __launch_bounds__(256) void cvt_w_kernel(
    const float* __restrict__ Wq, const float* __restrict__ Wk, const float* __restrict__ Wv) {
    int i = (blockIdx.x * blockDim.x + threadIdx.x) * 4;
    if (i >= 3 * HID * HID) return;
    int z = i / (HID * HID), r = i - z * (HID * HID);
    const float* W = (z == 0) ? Wq : (z == 1 ? Wk : Wv);
    float4 v = *(const float4*)(W + r);
    __nv_bfloat16 h, l;
    split_bf16(v.x, h, l); g_w_hi[i + 0] = h; g_w_lo[i + 0] = l;
    split_bf16(v.y, h, l); g_w_hi[i + 1] = h; g_w_lo[i + 1] = l;
    split_bf16(v.z, h, l); g_w_hi[i + 2] = h; g_w_lo[i + 2] = l;
    split_bf16(v.w, h, l); g_w_hi[i + 3] = h; g_w_lo[i + 3] = l;
}

// ---------------- phase 1: QKV projection, BK=64 2-stage + ldmatrix (R8 config) ----------------
#define QKV_AS    (128 * SST2)        // 9216 elems per array
#define QKV_STAGE (4 * QKV_AS)
#define QKV_SMEM  (2 * QKV_STAGE * 2) // 147456 B

__global__ __launch_bounds__(256) void qkv_mma_kernel(
    const float* __restrict__ bq, const float* __restrict__ bk, const float* __restrict__ bv)
{
    extern __shared__ __align__(16) __nv_bfloat16 dsm[];
    int z = blockIdx.z;
    const float* bias = (z == 0) ? bq : (z == 1 ? bk : bv);
    const __nv_bfloat16* gWhi = g_w_hi + (size_t)z * HID * HID;
    const __nv_bfloat16* gWlo = g_w_lo + (size_t)z * HID * HID;

    int m0 = blockIdx.y * 128, n0 = blockIdx.x * 128;
    int t = threadIdx.x;
    int lane = t & 31, warp = t >> 5;
    int wy = warp >> 2, wx = warp & 3;
    int g = lane >> 2, tq = (lane & 3) * 2;
    int arow = lane & 15, acol8 = (lane >> 4) * 8;
    int brow = ((lane >> 4) << 3) + (lane & 7), bcol8 = ((lane >> 3) & 1) * 8;

    float acc[4][4][4] = {};

    auto load_stage = [&](int stg, int k0) {
        __nv_bfloat16* base = dsm + stg * QKV_STAGE;
        #pragma unroll
        for (int u = 0; u < 4; u++) {
            int idx = t + 256 * u;
            int r = idx >> 3, ce = (idx & 7) * 8;
            size_t ga = (size_t)(m0 + r) * HID + k0 + ce;
            size_t gb = (size_t)(n0 + r) * HID + k0 + ce;
            int so = r * SST2 + ce;
            cp_async16(base + 0 * QKV_AS + so, g_hs_hi + ga);
            cp_async16(base + 1 * QKV_AS + so, g_hs_lo + ga);
            cp_async16(base + 2 * QKV_AS + so, gWhi + gb);
            cp_async16(base + 3 * QKV_AS + so, gWlo + gb);
        }
    };

    load_stage(0, 0);
    cp_commit();

    for (int k0 = 0; k0 < HID; k0 += 64) {
        int stg = (k0 >> 6) & 1;
        if (k0 + 64 < HID) { load_stage(stg ^ 1, k0 + 64); cp_commit(); cp_wait1(); }
        else               { cp_wait0(); }
        __syncthreads();
        const __nv_bfloat16* sAhi = dsm + stg * QKV_STAGE;
        const __nv_bfloat16* sAlo = sAhi + QKV_AS;
        const __nv_bfloat16* sBhi = sAlo + QKV_AS;
        const __nv_bfloat16* sBlo = sBhi + QKV_AS;

        #pragma unroll
        for (int kk = 0; kk < 64; kk += 16) {
            unsigned ahi[4][4], alo[4][4];
            #pragma unroll
            for (int mt = 0; mt < 4; mt++) {
                int ab = (wy * 64 + mt * 16 + arow) * SST2 + kk + acol8;
                ldsm4(ahi[mt], sAhi + ab);
                ldsm4(alo[mt], sAlo + ab);
            }
            #pragma unroll
            for (int ntp = 0; ntp < 2; ntp++) {
                int bb = (wx * 32 + ntp * 16 + brow) * SST2 + kk + bcol8;
                unsigned bh[4], bl[4];
                ldsm4(bh, sBhi + bb);
                ldsm4(bl, sBlo + bb);
                #pragma unroll
                for (int mt = 0; mt < 4; mt++) {
                    mma_bf16(acc[mt][2 * ntp],     ahi[mt], bh[0], bh[1]);
                    mma_bf16(acc[mt][2 * ntp],     ahi[mt], bl[0], bl[1]);
                    mma_bf16(acc[mt][2 * ntp],     alo[mt], bh[0], bh[1]);
                    mma_bf16(acc[mt][2 * ntp + 1], ahi[mt], bh[2], bh[3]);
                    mma_bf16(acc[mt][2 * ntp + 1], ahi[mt], bl[2], bl[3]);
                    mma_bf16(acc[mt][2 * ntp + 1], alo[mt], bh[2], bh[3]);
                }
            }
        }
        __syncthreads();
    }

    #pragma unroll
    for (int nt = 0; nt < 4; nt++) {
        int n = n0 + wx * 32 + nt * 8 + tq;
        float2 b2 = *(const float2*)&bias[n];
        int h = n >> 6, d = n & 63;
        #pragma unroll
        for (int mt = 0; mt < 4; mt++) {
            int m = m0 + wy * 64 + mt * 16 + g;
            int b = m >> 10, s = m & (SEQ - 1);
            int bh = b * NHEAD + h;
            float v0 = acc[mt][nt][0] + b2.x, v1 = acc[mt][nt][1] + b2.y;
            float v2 = acc[mt][nt][2] + b2.x, v3 = acc[mt][nt][3] + b2.y;
            __nv_bfloat16 h0, l0, h1, l1, h2, l2, h3, l3;
            split_bf16(v0, h0, l0); split_bf16(v1, h1, l1);
            split_bf16(v2, h2, l2); split_bf16(v3, h3, l3);
            if (z < 2) {
                __nv_bfloat16* ah = (z == 0) ? g_qh : g_kh;
                __nv_bfloat16* al = (z == 0) ? g_ql : g_kl;
                size_t o0 = ((size_t)bh * SEQ + s) * HDIM + d;
                size_t o1 = o0 + 8 * HDIM;
                *(__nv_bfloat162*)(ah + o0) = __nv_bfloat162(h0, h1);
                *(__nv_bfloat162*)(al + o0) = __nv_bfloat162(l0, l1);
                *(__nv_bfloat162*)(ah + o1) = __nv_bfloat162(h2, h3);
                *(__nv_bfloat162*)(al + o1) = __nv_bfloat162(l2, l3);
                if (z == 0) {
                    *(float2*)(g_qkv + o0) = make_float2(v0, v1);
                    *(float2*)(g_qkv + o1) = make_float2(v2, v3);
                }
            } else {
                size_t base = ((size_t)bh * HDIM + d) * SEQ + s;
                g_vth[base] = h0;           g_vtl[base] = l0;
                g_vth[base + SEQ] = h1;     g_vtl[base + SEQ] = l1;
                g_vth[base + 8] = h2;       g_vtl[base + 8] = l2;
                g_vth[base + SEQ + 8] = h3; g_vtl[base + SEQ + 8] = l3;
            }
        }
    }
}

// ---------------- phase 1.5: qrel = Q @ tab^T, broadcast-friendly ----------------
__global__ __launch_bounds__(256) void qrel_kernel() {
    int t = threadIdx.x;
    int row = blockIdx.x * 128 + (t & 127);
    int half = t >> 7;
    const float* Q = g_qkv + (size_t)row * HDIM;
    float q[64];
    #pragma unroll
    for (int d4 = 0; d4 < 16; d4++) {
        float4 v = *(const float4*)(Q + d4 * 4);
        q[d4 * 4 + 0] = v.x; q[d4 * 4 + 1] = v.y;
        q[d4 * 4 + 2] = v.z; q[d4 * 4 + 3] = v.w;
    }
    int c0 = half * 65;
    int cn = half ? 64 : 65;
    float* dst = g_qrel + (size_t)row * VOCAB;
    for (int j = 0; j < cn; j++) {
        int c = c0 + j;
        const float* tr = g_tab + c * 64;
        float s = 0.f;
        #pragma unroll
        for (int d4 = 0; d4 < 16; d4++) {
            float4 tv = *(const float4*)(tr + d4 * 4);
            s += q[d4*4]*tv.x + q[d4*4+1]*tv.y + q[d4*4+2]*tv.z + q[d4*4+3]*tv.w;
        }
        dst[c] = s;
    }
}

// ---------------- phase 2-4 fused: flash attention + rel-pos ----------------
#define FA_QAS   9216                  // 128*72
#define FA_KAS   4608                  // 64*72
#define FA_STAGE (4 * FA_KAS)
#define FA_PSOFF (2 * FA_QAS + 2 * FA_STAGE)
#define FA_SMEM  (FA_PSOFF * 2 + 128 * 132 * 4)

__global__ __launch_bounds__(256) void attn_fused_kernel(
    const float* __restrict__ mask, float* __restrict__ out)
{
    extern __shared__ __align__(16) __nv_bfloat16 dsm[];
    const int bh = blockIdx.y, b = bh >> 4, h = bh & 15;
    const int q0 = blockIdx.x * 128;
    const int t = threadIdx.x, lane = t & 31, w = t >> 5;
    const int g = lane >> 2, tq = (lane & 3) * 2;
    const int arow = lane & 15, acol8 = (lane >> 4) * 8;
    const int brow = ((lane >> 4) << 3) + (lane & 7), bcol8 = ((lane >> 3) & 1) * 8;

    __nv_bfloat16* sQhi = dsm;
    __nv_bfloat16* sQlo = dsm + FA_QAS;
    float* psm = (float*)(dsm + FA_PSOFF);

    for (int i = t; i < 128 * 132; i += 256) psm[i] = -1e30f;

    #pragma unroll
    for (int u = 0; u < 4; u++) {
        int idx = t + 256 * u;
        int r = idx >> 3, ce = (idx & 7) * 8;
        size_t ga = ((size_t)bh * SEQ + q0 + r) * HDIM + ce;
        int so = r * SST2 + ce;
        cp_async16(sQhi + so, g_qh + ga);
        cp_async16(sQlo + so, g_ql + ga);
    }
    auto load_kv = [&](int stg, int kt0) {
        __nv_bfloat16* base = dsm + 2 * FA_QAS + stg * FA_STAGE;
        #pragma unroll
        for (int u = 0; u < 2; u++) {
            int idx = t + 256 * u;
            int r = idx >> 3, ce = (idx & 7) * 8;
            int so = r * SST2 + ce;
            size_t gk = ((size_t)bh * SEQ + kt0 + r) * HDIM + ce;
            size_t gv = ((size_t)bh * HDIM + r) * SEQ + kt0 + ce;
            cp_async16(base + 0 * FA_KAS + so, g_kh + gk);
            cp_async16(base + 1 * FA_KAS + so, g_kl + gk);
            cp_async16(base + 2 * FA_KAS + so, g_vth + gv);
            cp_async16(base + 3 * FA_KAS + so, g_vtl + gv);
        }
    };
    load_kv(0, 0);
    cp_commit();

    const int qg = q0 + w * 16 + g;
    const int qh2 = qg + 8;
    const float* qrg = g_qrel + ((size_t)bh * SEQ + qg) * VOCAB;
    const float* qrh = g_qrel + ((size_t)bh * SEQ + qh2) * VOCAB;
    float* prowg = psm + (w * 16 + g) * 132;
    float* prowh = prowg + 8 * 132;

    float acc[8][4] = {};
    float m_g = -1e30f, m_h = -1e30f;
    float l_g = 0.f, l_h = 0.f, lo_g = 0.f, lo_h = 0.f, hi_g = 0.f, hi_h = 0.f;

    for (int kt = 0; kt < 16; kt++) {
        int kt0 = kt * 64;
        if (kt < 15) { load_kv((kt ^ 1) & 1, kt0 + 64); cp_commit(); cp_wait1(); }
        else         { cp_wait0(); }
        __syncthreads();
        const __nv_bfloat16* stage = dsm + 2 * FA_QAS + (kt & 1) * FA_STAGE;
        const __nv_bfloat16* sKhi = stage;
        const __nv_bfloat16* sKlo = stage + FA_KAS;
        const __nv_bfloat16* sVhi = stage + 2 * FA_KAS;
        const __nv_bfloat16* sVlo = stage + 3 * FA_KAS;

        // ---- S = Q K^T (split, ldmatrix) ----
        float s[8][4] = {};
        #pragma unroll
        for (int kk = 0; kk < 64; kk += 16) {
            unsigned ahi[4], alo[4];
            int ab = (w * 16 + arow) * SST2 + kk + acol8;
            ldsm4(ahi, sQhi + ab);
            ldsm4(alo, sQlo + ab);
            #pragma unroll
            for (int ntp = 0; ntp < 4; ntp++) {
                int bb = (ntp * 16 + brow) * SST2 + kk + bcol8;
                unsigned kh[4], kl[4];
                ldsm4(kh, sKhi + bb);
                ldsm4(kl, sKlo + bb);
                mma_bf16(s[2 * ntp],     ahi, kh[0], kh[1]);
                mma_bf16(s[2 * ntp],     ahi, kl[0], kl[1]);
                mma_bf16(s[2 * ntp],     alo, kh[0], kh[1]);
                mma_bf16(s[2 * ntp + 1], ahi, kh[2], kh[3]);
                mma_bf16(s[2 * ntp + 1], ahi, kl[2], kl[3]);
                mma_bf16(s[2 * ntp + 1], alo, kh[2], kh[3]);
            }
        }

        // ---- scores epilogue: qrel + scale + mask; stash raw s in band ----
        #pragma unroll
        for (int nt = 0; nt < 8; nt++) {
            int k = kt0 + nt * 8 + tq;
            float mk0 = mask[b * SEQ + k], mk1 = mask[b * SEQ + k + 1];
            int c;
            c = k - qg;      c = c < -64 ? -64 : (c > 64 ? 64 : c);
            s[nt][0] = (s[nt][0] + qrg[c + 64]) * 0.125f + mk0;
            c = k + 1 - qg;  c = c < -64 ? -64 : (c > 64 ? 64 : c);
            s[nt][1] = (s[nt][1] + qrg[c + 64]) * 0.125f + mk1;
            c = k - qh2;     c = c < -64 ? -64 : (c > 64 ? 64 : c);
            s[nt][2] = (s[nt][2] + qrh[c + 64]) * 0.125f + mk0;
            c = k + 1 - qh2; c = c < -64 ? -64 : (c > 64 ? 64 : c);
            s[nt][3] = (s[nt][3] + qrh[c + 64]) * 0.125f + mk1;
            int d0 = k - qg, d1 = k + 1 - qg;
            if (d0 > -64 && d0 < 64) prowg[d0 + 64] = s[nt][0];
            if (d1 > -64 && d1 < 64) prowg[d1 + 64] = s[nt][1];
            int e0 = k - qh2, e1 = k + 1 - qh2;
            if (e0 > -64 && e0 < 64) prowh[e0 + 64] = s[nt][2];
            if (e1 > -64 && e1 < 64) prowh[e1 + 64] = s[nt][3];
        }

        // ---- online softmax (registers only) ----
        float tg = -1e30f, th = -1e30f;
        #pragma unroll
        for (int nt = 0; nt < 8; nt++) {
            tg = fmaxf(tg, fmaxf(s[nt][0], s[nt][1]));
            th = fmaxf(th, fmaxf(s[nt][2], s[nt][3]));
        }
        tg = quadmax(tg); th = quadmax(th);
        float mng = fmaxf(m_g, tg), mnh = fmaxf(m_h, th);
        float scg = __expf(m_g - mng), sch = __expf(m_h - mnh);
        if (scg < 1.0f) {
            #pragma unroll
            for (int nt = 0; nt < 8; nt++) { acc[nt][0] *= scg; acc[nt][1] *= scg; }
            l_g *= scg; lo_g *= scg; hi_g *= scg;
        }
        if (sch < 1.0f) {
            #pragma unroll
            for (int nt = 0; nt < 8; nt++) { acc[nt][2] *= sch; acc[nt][3] *= sch; }
            l_h *= sch; lo_h *= sch; hi_h *= sch;
        }
        m_g = mng; m_h = mnh;

        // ---- p = exp, edge sums, pack A-frags ----
        unsigned phi[4][4], plo[4][4];
        #pragma unroll
        for (int nt = 0; nt < 8; nt++) {
            int k = kt0 + nt * 8 + tq;
            float p0 = __expf(s[nt][0] - m_g), p1 = __expf(s[nt][1] - m_g);
            float p2 = __expf(s[nt][2] - m_h), p3 = __expf(s[nt][3] - m_h);
            l_g += p0 + p1; l_h += p2 + p3;
            int d0 = k - qg, d1 = k + 1 - qg;
            if (d0 <= -64) lo_g += p0; else if (d0 >= 64) hi_g += p0;
            if (d1 <= -64) lo_g += p1; else if (d1 >= 64) hi_g += p1;
            int e0 = k - qh2, e1 = k + 1 - qh2;
            if (e0 <= -64) lo_h += p2; else if (e0 >= 64) hi_h += p2;
            if (e1 <= -64) lo_h += p3; else if (e1 >= 64) hi_h += p3;
            int kb = nt >> 1;
            if ((nt & 1) == 0) {
                phi[kb][0] = pack2h(p0, p1); phi[kb][1] = pack2h(p2, p3);
                plo[kb][0] = pack2l(p0, p1); plo[kb][1] = pack2l(p2, p3);
            } else {
                phi[kb][2] = pack2h(p0, p1); phi[kb][3] = pack2h(p2, p3);
                plo[kb][2] = pack2l(p0, p1); plo[kb][3] = pack2l(p2, p3);
            }
        }

        // ---- O += P V (split, ldmatrix B) ----
        #pragma unroll
        for (int kb = 0; kb < 4; kb++) {
            int kk = kb * 16;
            #pragma unroll
            for (int ntp = 0; ntp < 4; ntp++) {
                int bb = (ntp * 16 + brow) * SST2 + kk + bcol8;
                unsigned vh[4], vl[4];
                ldsm4(vh, sVhi + bb);
                ldsm4(vl, sVlo + bb);
                mma_bf16(acc[2 * ntp],     phi[kb], vh[0], vh[1]);
                mma_bf16(acc[2 * ntp],     phi[kb], vl[0], vl[1]);
                mma_bf16(acc[2 * ntp],     plo[kb], vh[0], vh[1]);
                mma_bf16(acc[2 * ntp + 1], phi[kb], vh[2], vh[3]);
                mma_bf16(acc[2 * ntp + 1], phi[kb], vl[2], vl[3]);
                mma_bf16(acc[2 * ntp + 1], plo[kb], vh[2], vh[3]);
            }
        }
        __syncthreads();
    }

    // ---- finalize: row sums, edges, convert band scores -> probs ----
    l_g = quadsum(l_g); l_h = quadsum(l_h);
    lo_g = quadsum(lo_g); lo_h = quadsum(lo_h);
    hi_g = quadsum(hi_g); hi_h = quadsum(hi_h);
    if ((lane & 3) == 0) {
        prowg[0] = lo_g; prowg[128] = hi_g;
        prowh[0] = lo_h; prowh[128] = hi_h;
    }
    {
        int c0 = (lane & 3) * 33; if (c0 == 0) c0 = 1;
        int c1 = (lane & 3) * 33 + 33; if (c1 > 128) c1 = 128;
        for (int c = c0; c < c1; c++) {
            prowg[c] = __expf(prowg[c] - m_g);
            prowh[c] = __expf(prowh[c] - m_h);
        }
    }
    __syncthreads();

    // ---- rel-value epilogue: acc += ps @ tab ----
    float* tabS = (float*)(dsm + 2 * FA_QAS);
    for (int r0 = 0; r0 < VOCAB; r0 += 16) {
        __syncthreads();
        {
            int rr = t >> 4, cc = (t & 15) * 4;
            int r = r0 + rr;
            float4 tv = (r < VOCAB) ? *(const float4*)&g_tab[r * 64 + cc]
                                    : make_float4(0.f, 0.f, 0.f, 0.f);
            *(float4*)&tabS[rr * 68 + cc] = tv;
        }
        __syncthreads();
        #pragma unroll
        for (int rc = 0; rc < 16; rc++) {
            int rr2 = r0 + rc; if (rr2 > 128) rr2 = 128;
            float pg = prowg[rr2];
            float ph = prowh[rr2];
            #pragma unroll
            for (int nt = 0; nt < 8; nt++) {
                int d = nt * 8 + tq;
                float t0 = tabS[rc * 68 + d], t1 = tabS[rc * 68 + d + 1];
                acc[nt][0] += pg * t0; acc[nt][1] += pg * t1;
                acc[nt][2] += ph * t0; acc[nt][3] += ph * t1;
            }
        }
    }

    // ---- normalize + write ----
    float ig = 1.0f / l_g, ih = 1.0f / l_h;
    #pragma unroll
    for (int nt = 0; nt < 8; nt++) {
        int d = nt * 8 + tq;
        *(float2*)(out + ((size_t)(b * SEQ + qg)) * HID + h * 64 + d) =
            make_float2(acc[nt][0] * ig, acc[nt][1] * ig);
        *(float2*)(out + ((size_t)(b * SEQ + qh2)) * HID + h * 64 + d) =
            make_float2(acc[nt][2] * ih, acc[nt][3] * ih);
    }
}

// ---------------- launcher ----------------
extern "C" void kernel_launch(void* const* d_in, const int* in_sizes, int n_in,
                              void* d_out, int out_size) {
    const float* hs   = (const float*)d_in[0];
    const float* mask = (const float*)d_in[1];
    const float* Wq   = (const float*)d_in[2];
    const float* bq   = (const float*)d_in[3];
    const float* Wk   = (const float*)d_in[4];
    const float* bk   = (const float*)d_in[5];
    const float* Wv   = (const float*)d_in[6];
    const float* bv   = (const float*)d_in[7];
    float* out = (float*)d_out;

    cudaFuncSetAttribute(qkv_mma_kernel,    cudaFuncAttributeMaxDynamicSharedMemorySize, QKV_SMEM);
    cudaFuncSetAttribute(attn_fused_kernel, cudaFuncAttributeMaxDynamicSharedMemorySize, FA_SMEM);

    init_tab_kernel<<<(VOCAB * 32 + 127) / 128, 128>>>();
    cvt_hs_kernel<<<(BATCH * SEQ * HID / 4 + 255) / 256, 256>>>(hs);
    cvt_w_kernel<<<(3 * HID * HID / 4 + 255) / 256, 256>>>(Wq, Wk, Wv);
    qkv_mma_kernel<<<dim3(HID / 128, (BATCH * SEQ) / 128, 3), 256, QKV_SMEM>>>(bq, bk, bv);
    qrel_kernel<<<BH * SEQ / 128, 256>>>();
    attn_fused_kernel<<<dim3(SEQ / 128, BH), 256, FA_SMEM>>>(mask, out);
}

// round 11
// speedup vs baseline: 2.8330x; 1.0293x over previous
#include <cuda_runtime.h>
#include <cuda_bf16.h>
#include <cstdint>

#define BATCH 2
#define SEQ   1024
#define HID   1024
#define NHEAD 16
#define HDIM  64
#define BH    (BATCH*NHEAD)      // 32
#define VOCAB 129                // 2*64+1
#define SST2  72                 // bf16 smem stride: conflict-free

// ---------------- scratch ----------------
__device__ __align__(16) float g_qkv[BH * SEQ * HDIM];           // Q fp32 (for qrel)
__device__ __align__(16) float g_qrel[(size_t)BH * SEQ * VOCAB];
__device__ __align__(16) float g_tab[VOCAB * HDIM];

__device__ __align__(16) __nv_bfloat16 g_hs_hi[BATCH * SEQ * HID];
__device__ __align__(16) __nv_bfloat16 g_hs_lo[BATCH * SEQ * HID];
__device__ __align__(16) __nv_bfloat16 g_w_hi[3 * HID * HID];
__device__ __align__(16) __nv_bfloat16 g_w_lo[3 * HID * HID];
__device__ __align__(16) __nv_bfloat16 g_qh[BH * SEQ * HDIM];
__device__ __align__(16) __nv_bfloat16 g_ql[BH * SEQ * HDIM];
__device__ __align__(16) __nv_bfloat16 g_kh[BH * SEQ * HDIM];
__device__ __align__(16) __nv_bfloat16 g_kl[BH * SEQ * HDIM];
__device__ __align__(16) __nv_bfloat16 g_vth[BH * HDIM * SEQ];   // V^T [bh][d][s]
__device__ __align__(16) __nv_bfloat16 g_vtl[BH * HDIM * SEQ];

// ---------------- helpers ----------------
__device__ __forceinline__ void cp_async16(void* dst, const void* src) {
    unsigned int d = (unsigned int)__cvta_generic_to_shared(dst);
    asm volatile("cp.async.cg.shared.global [%0], [%1], 16;" :: "r"(d), "l"(src));
}
__device__ __forceinline__ void cp_commit() { asm volatile("cp.async.commit_group;"); }
__device__ __forceinline__ void cp_wait0()  { asm volatile("cp.async.wait_group 0;"); }
__device__ __forceinline__ void cp_wait1()  { asm volatile("cp.async.wait_group 1;"); }

__device__ __forceinline__ void ldsm4(unsigned* r, const void* p) {
    unsigned a = (unsigned)__cvta_generic_to_shared(p);
    asm volatile("ldmatrix.sync.aligned.m8n8.x4.shared.b16 {%0,%1,%2,%3}, [%4];"
                 : "=r"(r[0]), "=r"(r[1]), "=r"(r[2]), "=r"(r[3]) : "r"(a));
}

__device__ __forceinline__ void split_bf16(float v, __nv_bfloat16& hi, __nv_bfloat16& lo) {
    hi = __float2bfloat16_rn(v);
    lo = __float2bfloat16_rn(v - __bfloat162float(hi));
}
__device__ __forceinline__ unsigned pack2h(float a, float b) {
    __nv_bfloat162 p(__float2bfloat16_rn(a), __float2bfloat16_rn(b));
    return *(unsigned*)&p;
}
__device__ __forceinline__ unsigned pack2l(float a, float b) {
    float ra = a - __bfloat162float(__float2bfloat16_rn(a));
    float rb = b - __bfloat162float(__float2bfloat16_rn(b));
    __nv_bfloat162 p(__float2bfloat16_rn(ra), __float2bfloat16_rn(rb));
    return *(unsigned*)&p;
}
__device__ __forceinline__ float quadmax(float v) {
    v = fmaxf(v, __shfl_xor_sync(0xffffffffu, v, 1));
    v = fmaxf(v, __shfl_xor_sync(0xffffffffu, v, 2));
    return v;
}
__device__ __forceinline__ float quadsum(float v) {
    v += __shfl_xor_sync(0xffffffffu, v, 1);
    v += __shfl_xor_sync(0xffffffffu, v, 2);
    return v;
}
__device__ __forceinline__ void mma_bf16(float* c, const unsigned int* A,
                                         unsigned int b0, unsigned int b1) {
    asm volatile("mma.sync.aligned.m16n8k16.row.col.f32.bf16.bf16.f32 "
        "{%0,%1,%2,%3}, {%4,%5,%6,%7}, {%8,%9}, {%0,%1,%2,%3};"
        : "+f"(c[0]), "+f"(c[1]), "+f"(c[2]), "+f"(c[3])
        : "r"(A[0]), "r"(A[1]), "r"(A[2]), "r"(A[3]), "r"(b0), "r"(b1));
}

// ---------------- sinusoid table ----------------
__global__ void init_tab_kernel() {
    int idx = blockIdx.x * blockDim.x + threadIdx.x;
    if (idx >= VOCAB * 32) return;
    int p = idx >> 5, i = idx & 31;
    float div = expf((float)(2 * i) * (-9.210340371976184f / 64.0f));
    float ang = (float)p * div;
    g_tab[p * 64 + 2 * i]     = sinf(ang);
    g_tab[p * 64 + 2 * i + 1] = cosf(ang);
}

__global__ __launch_bounds__(256) void cvt_hs_kernel(const float* __restrict__ hs) {
    int i = (blockIdx.x * blockDim.x + threadIdx.x) * 4;
    if (i >= BATCH * SEQ * HID) return;
    float4 v = *(const float4*)(hs + i);
    __nv_bfloat16 h, l;
    split_bf16(v.x, h, l); g_hs_hi[i + 0] = h; g_hs_lo[i + 0] = l;
    split_bf16(v.y, h, l); g_hs_hi[i + 1] = h; g_hs_lo[i + 1] = l;
    split_bf16(v.z, h, l); g_hs_hi[i + 2] = h; g_hs_lo[i + 2] = l;
    split_bf16(v.w, h, l); g_hs_hi[i + 3] = h; g_hs_lo[i + 3] = l;
}

__global__ __launch_bounds__(256) void cvt_w_kernel(
    const float* __restrict__ Wq, const float* __restrict__ Wk, const float* __restrict__ Wv) {
    int i = (blockIdx.x * blockDim.x + threadIdx.x) * 4;
    if (i >= 3 * HID * HID) return;
    int z = i / (HID * HID), r = i - z * (HID * HID);
    const float* W = (z == 0) ? Wq : (z == 1 ? Wk : Wv);
    float4 v = *(const float4*)(W + r);
    __nv_bfloat16 h, l;
    split_bf16(v.x, h, l); g_w_hi[i + 0] = h; g_w_lo[i + 0] = l;
    split_bf16(v.y, h, l); g_w_hi[i + 1] = h; g_w_lo[i + 1] = l;
    split_bf16(v.z, h, l); g_w_hi[i + 2] = h; g_w_lo[i + 2] = l;
    split_bf16(v.w, h, l); g_w_hi[i + 3] = h; g_w_lo[i + 3] = l;
}

// ---------------- phase 1: QKV projection, BK=64 2-stage + ldmatrix ----------------
#define QKV_AS    (128 * SST2)        // 9216 elems per array
#define QKV_STAGE (4 * QKV_AS)
#define QKV_SMEM  (2 * QKV_STAGE * 2) // 147456 B

__global__ __launch_bounds__(256) void qkv_mma_kernel(
    const float* __restrict__ bq, const float* __restrict__ bk, const float* __restrict__ bv)
{
    extern __shared__ __align__(16) __nv_bfloat16 dsm[];
    int z = blockIdx.z;
    const float* bias = (z == 0) ? bq : (z == 1 ? bk : bv);
    const __nv_bfloat16* gWhi = g_w_hi + (size_t)z * HID * HID;
    const __nv_bfloat16* gWlo = g_w_lo + (size_t)z * HID * HID;

    int m0 = blockIdx.y * 128, n0 = blockIdx.x * 128;
    int t = threadIdx.x;
    int lane = t & 31, warp = t >> 5;
    int wy = warp >> 2, wx = warp & 3;
    int g = lane >> 2, tq = (lane & 3) * 2;
    int arow = lane & 15, acol8 = (lane >> 4) * 8;
    int brow = ((lane >> 4) << 3) + (lane & 7), bcol8 = ((lane >> 3) & 1) * 8;

    float acc[4][4][4] = {};

    auto load_stage = [&](int stg, int k0) {
        __nv_bfloat16* base = dsm + stg * QKV_STAGE;
        #pragma unroll
        for (int u = 0; u < 4; u++) {
            int idx = t + 256 * u;
            int r = idx >> 3, ce = (idx & 7) * 8;
            size_t ga = (size_t)(m0 + r) * HID + k0 + ce;
            size_t gb = (size_t)(n0 + r) * HID + k0 + ce;
            int so = r * SST2 + ce;
            cp_async16(base + 0 * QKV_AS + so, g_hs_hi + ga);
            cp_async16(base + 1 * QKV_AS + so, g_hs_lo + ga);
            cp_async16(base + 2 * QKV_AS + so, gWhi + gb);
            cp_async16(base + 3 * QKV_AS + so, gWlo + gb);
        }
    };

    load_stage(0, 0);
    cp_commit();

    for (int k0 = 0; k0 < HID; k0 += 64) {
        int stg = (k0 >> 6) & 1;
        if (k0 + 64 < HID) { load_stage(stg ^ 1, k0 + 64); cp_commit(); cp_wait1(); }
        else               { cp_wait0(); }
        __syncthreads();
        const __nv_bfloat16* sAhi = dsm + stg * QKV_STAGE;
        const __nv_bfloat16* sAlo = sAhi + QKV_AS;
        const __nv_bfloat16* sBhi = sAlo + QKV_AS;
        const __nv_bfloat16* sBlo = sBhi + QKV_AS;

        #pragma unroll
        for (int kk = 0; kk < 64; kk += 16) {
            unsigned ahi[4][4], alo[4][4];
            #pragma unroll
            for (int mt = 0; mt < 4; mt++) {
                int ab = (wy * 64 + mt * 16 + arow) * SST2 + kk + acol8;
                ldsm4(ahi[mt], sAhi + ab);
                ldsm4(alo[mt], sAlo + ab);
            }
            #pragma unroll
            for (int ntp = 0; ntp < 2; ntp++) {
                int bb = (wx * 32 + ntp * 16 + brow) * SST2 + kk + bcol8;
                unsigned bh[4], bl[4];
                ldsm4(bh, sBhi + bb);
                ldsm4(bl, sBlo + bb);
                #pragma unroll
                for (int mt = 0; mt < 4; mt++) {
                    mma_bf16(acc[mt][2 * ntp],     ahi[mt], bh[0], bh[1]);
                    mma_bf16(acc[mt][2 * ntp],     ahi[mt], bl[0], bl[1]);
                    mma_bf16(acc[mt][2 * ntp],     alo[mt], bh[0], bh[1]);
                    mma_bf16(acc[mt][2 * ntp + 1], ahi[mt], bh[2], bh[3]);
                    mma_bf16(acc[mt][2 * ntp + 1], ahi[mt], bl[2], bl[3]);
                    mma_bf16(acc[mt][2 * ntp + 1], alo[mt], bh[2], bh[3]);
                }
            }
        }
        __syncthreads();
    }

    #pragma unroll
    for (int nt = 0; nt < 4; nt++) {
        int n = n0 + wx * 32 + nt * 8 + tq;
        float2 b2 = *(const float2*)&bias[n];
        int h = n >> 6, d = n & 63;
        #pragma unroll
        for (int mt = 0; mt < 4; mt++) {
            int m = m0 + wy * 64 + mt * 16 + g;
            int b = m >> 10, s = m & (SEQ - 1);
            int bh = b * NHEAD + h;
            float v0 = acc[mt][nt][0] + b2.x, v1 = acc[mt][nt][1] + b2.y;
            float v2 = acc[mt][nt][2] + b2.x, v3 = acc[mt][nt][3] + b2.y;
            __nv_bfloat16 h0, l0, h1, l1, h2, l2, h3, l3;
            split_bf16(v0, h0, l0); split_bf16(v1, h1, l1);
            split_bf16(v2, h2, l2); split_bf16(v3, h3, l3);
            if (z < 2) {
                __nv_bfloat16* ah = (z == 0) ? g_qh : g_kh;
                __nv_bfloat16* al = (z == 0) ? g_ql : g_kl;
                size_t o0 = ((size_t)bh * SEQ + s) * HDIM + d;
                size_t o1 = o0 + 8 * HDIM;
                *(__nv_bfloat162*)(ah + o0) = __nv_bfloat162(h0, h1);
                *(__nv_bfloat162*)(al + o0) = __nv_bfloat162(l0, l1);
                *(__nv_bfloat162*)(ah + o1) = __nv_bfloat162(h2, h3);
                *(__nv_bfloat162*)(al + o1) = __nv_bfloat162(l2, l3);
                if (z == 0) {
                    *(float2*)(g_qkv + o0) = make_float2(v0, v1);
                    *(float2*)(g_qkv + o1) = make_float2(v2, v3);
                }
            } else {
                size_t base = ((size_t)bh * HDIM + d) * SEQ + s;
                g_vth[base] = h0;           g_vtl[base] = l0;
                g_vth[base + SEQ] = h1;     g_vtl[base + SEQ] = l1;
                g_vth[base + 8] = h2;       g_vtl[base + 8] = l2;
                g_vth[base + SEQ + 8] = h3; g_vtl[base + SEQ + 8] = l3;
            }
        }
    }
}

// ---------------- phase 1.5: qrel = Q @ tab^T, broadcast-friendly ----------------
__global__ __launch_bounds__(256) void qrel_kernel() {
    int t = threadIdx.x;
    int row = blockIdx.x * 128 + (t & 127);
    int half = t >> 7;
    const float* Q = g_qkv + (size_t)row * HDIM;
    float q[64];
    #pragma unroll
    for (int d4 = 0; d4 < 16; d4++) {
        float4 v = *(const float4*)(Q + d4 * 4);
        q[d4 * 4 + 0] = v.x; q[d4 * 4 + 1] = v.y;
        q[d4 * 4 + 2] = v.z; q[d4 * 4 + 3] = v.w;
    }
    int c0 = half * 65;
    int cn = half ? 64 : 65;
    float* dst = g_qrel + (size_t)row * VOCAB;
    for (int j = 0; j < cn; j++) {
        int c = c0 + j;
        const float* tr = g_tab + c * 64;
        float s = 0.f;
        #pragma unroll
        for (int d4 = 0; d4 < 16; d4++) {
            float4 tv = *(const float4*)(tr + d4 * 4);
            s += q[d4*4]*tv.x + q[d4*4+1]*tv.y + q[d4*4+2]*tv.z + q[d4*4+3]*tv.w;
        }
        dst[c] = s;
    }
}

// ---------------- phase 2-4 fused: flash attention + rel-pos ----------------
// Band smem is preloaded with the row's qrel values; epilogue does interior
// read(qrel)->write(score) in smem, clipped dists use two per-row registers.
#define FA_QAS   9216                  // 128*72
#define FA_KAS   4608                  // 64*72
#define FA_STAGE (4 * FA_KAS)
#define FA_PSOFF (2 * FA_QAS + 2 * FA_STAGE)
#define FA_SMEM  (FA_PSOFF * 2 + 128 * 132 * 4 + 4096)

__global__ __launch_bounds__(256) void attn_fused_kernel(
    const float* __restrict__ mask, float* __restrict__ out)
{
    extern __shared__ __align__(16) __nv_bfloat16 dsm[];
    const int bh = blockIdx.y, b = bh >> 4, h = bh & 15;
    const int q0 = blockIdx.x * 128;
    const int t = threadIdx.x, lane = t & 31, w = t >> 5;
    const int g = lane >> 2, tq = (lane & 3) * 2;
    const int arow = lane & 15, acol8 = (lane >> 4) * 8;
    const int brow = ((lane >> 4) << 3) + (lane & 7), bcol8 = ((lane >> 3) & 1) * 8;

    __nv_bfloat16* sQhi = dsm;
    __nv_bfloat16* sQlo = dsm + FA_QAS;
    float* psm = (float*)(dsm + FA_PSOFF);
    float* smask = psm + 128 * 132;

    // preload band with qrel rows (interior values consumed once each)
    {
        size_t qrbase = ((size_t)bh * SEQ + q0) * VOCAB;
        for (int i = t; i < 128 * 132; i += 256) {
            int r = i / 132, c = i - r * 132;
            psm[i] = (c < VOCAB) ? g_qrel[qrbase + (size_t)r * VOCAB + c] : 0.0f;
        }
    }
    // mask row -> smem (4KB)
    cp_async16(smask + t * 4, mask + (size_t)b * SEQ + t * 4);

    #pragma unroll
    for (int u = 0; u < 4; u++) {
        int idx = t + 256 * u;
        int r = idx >> 3, ce = (idx & 7) * 8;
        size_t ga = ((size_t)bh * SEQ + q0 + r) * HDIM + ce;
        int so = r * SST2 + ce;
        cp_async16(sQhi + so, g_qh + ga);
        cp_async16(sQlo + so, g_ql + ga);
    }
    auto load_kv = [&](int stg, int kt0) {
        __nv_bfloat16* base = dsm + 2 * FA_QAS + stg * FA_STAGE;
        #pragma unroll
        for (int u = 0; u < 2; u++) {
            int idx = t + 256 * u;
            int r = idx >> 3, ce = (idx & 7) * 8;
            int so = r * SST2 + ce;
            size_t gk = ((size_t)bh * SEQ + kt0 + r) * HDIM + ce;
            size_t gv = ((size_t)bh * HDIM + r) * SEQ + kt0 + ce;
            cp_async16(base + 0 * FA_KAS + so, g_kh + gk);
            cp_async16(base + 1 * FA_KAS + so, g_kl + gk);
            cp_async16(base + 2 * FA_KAS + so, g_vth + gv);
            cp_async16(base + 3 * FA_KAS + so, g_vtl + gv);
        }
    };
    load_kv(0, 0);
    cp_commit();

    const int qg = q0 + w * 16 + g;
    const int qh2 = qg + 8;
    const float* qrg = g_qrel + ((size_t)bh * SEQ + qg) * VOCAB;
    const float* qrh = g_qrel + ((size_t)bh * SEQ + qh2) * VOCAB;
    const float qr0g = qrg[0], qr128g = qrg[128];
    const float qr0h = qrh[0], qr128h = qrh[128];
    float* prowg = psm + (w * 16 + g) * 132;
    float* prowh = prowg + 8 * 132;

    float acc[8][4] = {};
    float m_g = -1e30f, m_h = -1e30f;
    float l_g = 0.f, l_h = 0.f, lo_g = 0.f, lo_h = 0.f, hi_g = 0.f, hi_h = 0.f;

    for (int kt = 0; kt < 16; kt++) {
        int kt0 = kt * 64;
        if (kt < 15) { load_kv((kt ^ 1) & 1, kt0 + 64); cp_commit(); cp_wait1(); }
        else         { cp_wait0(); }
        __syncthreads();
        const __nv_bfloat16* stage = dsm + 2 * FA_QAS + (kt & 1) * FA_STAGE;
        const __nv_bfloat16* sKhi = stage;
        const __nv_bfloat16* sKlo = stage + FA_KAS;
        const __nv_bfloat16* sVhi = stage + 2 * FA_KAS;
        const __nv_bfloat16* sVlo = stage + 3 * FA_KAS;

        // ---- S = Q K^T (split, ldmatrix) ----
        float s[8][4] = {};
        #pragma unroll
        for (int kk = 0; kk < 64; kk += 16) {
            unsigned ahi[4], alo[4];
            int ab = (w * 16 + arow) * SST2 + kk + acol8;
            ldsm4(ahi, sQhi + ab);
            ldsm4(alo, sQlo + ab);
            #pragma unroll
            for (int ntp = 0; ntp < 4; ntp++) {
                int bb = (ntp * 16 + brow) * SST2 + kk + bcol8;
                unsigned kh[4], kl[4];
                ldsm4(kh, sKhi + bb);
                ldsm4(kl, sKlo + bb);
                mma_bf16(s[2 * ntp],     ahi, kh[0], kh[1]);
                mma_bf16(s[2 * ntp],     ahi, kl[0], kl[1]);
                mma_bf16(s[2 * ntp],     alo, kh[0], kh[1]);
                mma_bf16(s[2 * ntp + 1], ahi, kh[2], kh[3]);
                mma_bf16(s[2 * ntp + 1], ahi, kl[2], kl[3]);
                mma_bf16(s[2 * ntp + 1], alo, kh[2], kh[3]);
            }
        }

        // ---- scores epilogue: qrel (band smem / regs) + scale + mask ----
        #pragma unroll
        for (int nt = 0; nt < 8; nt++) {
            int k = kt0 + nt * 8 + tq;
            float mk0 = smask[k], mk1 = smask[k + 1];
            int d0 = k - qg, d1 = k + 1 - qg;
            if (d0 > -64 && d0 < 64) {
                float sv = (s[nt][0] + prowg[d0 + 64]) * 0.125f + mk0;
                prowg[d0 + 64] = sv; s[nt][0] = sv;
            } else s[nt][0] = (s[nt][0] + (d0 <= -64 ? qr0g : qr128g)) * 0.125f + mk0;
            if (d1 > -64 && d1 < 64) {
                float sv = (s[nt][1] + prowg[d1 + 64]) * 0.125f + mk1;
                prowg[d1 + 64] = sv; s[nt][1] = sv;
            } else s[nt][1] = (s[nt][1] + (d1 <= -64 ? qr0g : qr128g)) * 0.125f + mk1;
            int e0 = k - qh2, e1 = k + 1 - qh2;
            if (e0 > -64 && e0 < 64) {
                float sv = (s[nt][2] + prowh[e0 + 64]) * 0.125f + mk0;
                prowh[e0 + 64] = sv; s[nt][2] = sv;
            } else s[nt][2] = (s[nt][2] + (e0 <= -64 ? qr0h : qr128h)) * 0.125f + mk0;
            if (e1 > -64 && e1 < 64) {
                float sv = (s[nt][3] + prowh[e1 + 64]) * 0.125f + mk1;
                prowh[e1 + 64] = sv; s[nt][3] = sv;
            } else s[nt][3] = (s[nt][3] + (e1 <= -64 ? qr0h : qr128h)) * 0.125f + mk1;
        }

        // ---- online softmax (registers only) ----
        float tg = -1e30f, th = -1e30f;
        #pragma unroll
        for (int nt = 0; nt < 8; nt++) {
            tg = fmaxf(tg, fmaxf(s[nt][0], s[nt][1]));
            th = fmaxf(th, fmaxf(s[nt][2], s[nt][3]));
        }
        tg = quadmax(tg); th = quadmax(th);
        float mng = fmaxf(m_g, tg), mnh = fmaxf(m_h, th);
        float scg = __expf(m_g - mng), sch = __expf(m_h - mnh);
        if (scg < 1.0f) {
            #pragma unroll
            for (int nt = 0; nt < 8; nt++) { acc[nt][0] *= scg; acc[nt][1] *= scg; }
            l_g *= scg; lo_g *= scg; hi_g *= scg;
        }
        if (sch < 1.0f) {
            #pragma unroll
            for (int nt = 0; nt < 8; nt++) { acc[nt][2] *= sch; acc[nt][3] *= sch; }
            l_h *= sch; lo_h *= sch; hi_h *= sch;
        }
        m_g = mng; m_h = mnh;

        // ---- p = exp, edge sums, pack A-frags ----
        unsigned phi[4][4], plo[4][4];
        #pragma unroll
        for (int nt = 0; nt < 8; nt++) {
            int k = kt0 + nt * 8 + tq;
            float p0 = __expf(s[nt][0] - m_g), p1 = __expf(s[nt][1] - m_g);
            float p2 = __expf(s[nt][2] - m_h), p3 = __expf(s[nt][3] - m_h);
            l_g += p0 + p1; l_h += p2 + p3;
            int d0 = k - qg, d1 = k + 1 - qg;
            if (d0 <= -64) lo_g += p0; else if (d0 >= 64) hi_g += p0;
            if (d1 <= -64) lo_g += p1; else if (d1 >= 64) hi_g += p1;
            int e0 = k - qh2, e1 = k + 1 - qh2;
            if (e0 <= -64) lo_h += p2; else if (e0 >= 64) hi_h += p2;
            if (e1 <= -64) lo_h += p3; else if (e1 >= 64) hi_h += p3;
            int kb = nt >> 1;
            if ((nt & 1) == 0) {
                phi[kb][0] = pack2h(p0, p1); phi[kb][1] = pack2h(p2, p3);
                plo[kb][0] = pack2l(p0, p1); plo[kb][1] = pack2l(p2, p3);
            } else {
                phi[kb][2] = pack2h(p0, p1); phi[kb][3] = pack2h(p2, p3);
                plo[kb][2] = pack2l(p0, p1); plo[kb][3] = pack2l(p2, p3);
            }
        }

        // ---- O += P V (split, ldmatrix B) ----
        #pragma unroll
        for (int kb = 0; kb < 4; kb++) {
            int kk = kb * 16;
            #pragma unroll
            for (int ntp = 0; ntp < 4; ntp++) {
                int bb = (ntp * 16 + brow) * SST2 + kk + bcol8;
                unsigned vh[4], vl[4];
                ldsm4(vh, sVhi + bb);
                ldsm4(vl, sVlo + bb);
                mma_bf16(acc[2 * ntp],     phi[kb], vh[0], vh[1]);
                mma_bf16(acc[2 * ntp],     phi[kb], vl[0], vl[1]);
                mma_bf16(acc[2 * ntp],     plo[kb], vh[0], vh[1]);
                mma_bf16(acc[2 * ntp + 1], phi[kb], vh[2], vh[3]);
                mma_bf16(acc[2 * ntp + 1], phi[kb], vl[2], vl[3]);
                mma_bf16(acc[2 * ntp + 1], plo[kb], vh[2], vh[3]);
            }
        }
        __syncthreads();
    }

    // ---- finalize: row sums, edges, convert band scores -> probs (validity-checked) ----
    l_g = quadsum(l_g); l_h = quadsum(l_h);
    lo_g = quadsum(lo_g); lo_h = quadsum(lo_h);
    hi_g = quadsum(hi_g); hi_h = quadsum(hi_h);
    if ((lane & 3) == 0) {
        prowg[0] = lo_g; prowg[128] = hi_g;
        prowh[0] = lo_h; prowh[128] = hi_h;
    }
    {
        int c0 = (lane & 3) * 33; if (c0 == 0) c0 = 1;
        int c1 = (lane & 3) * 33 + 33; if (c1 > 128) c1 = 128;
        for (int c = c0; c < c1; c++) {
            int kg = qg + c - 64;
            int kh2 = qh2 + c - 64;
            prowg[c] = (kg >= 0 && kg < SEQ) ? __expf(prowg[c] - m_g) : 0.0f;
            prowh[c] = (kh2 >= 0 && kh2 < SEQ) ? __expf(prowh[c] - m_h) : 0.0f;
        }
    }
    __syncthreads();

    // ---- rel-value epilogue: acc += ps @ tab ----
    float* tabS = (float*)(dsm + 2 * FA_QAS);
    for (int r0 = 0; r0 < VOCAB; r0 += 16) {
        __syncthreads();
        {
            int rr = t >> 4, cc = (t & 15) * 4;
            int r = r0 + rr;
            float4 tv = (r < VOCAB) ? *(const float4*)&g_tab[r * 64 + cc]
                                    : make_float4(0.f, 0.f, 0.f, 0.f);
            *(float4*)&tabS[rr * 68 + cc] = tv;
        }
        __syncthreads();
        #pragma unroll
        for (int rc = 0; rc < 16; rc++) {
            int rr2 = r0 + rc; if (rr2 > 128) rr2 = 128;
            float pg = prowg[rr2];
            float ph = prowh[rr2];
            #pragma unroll
            for (int nt = 0; nt < 8; nt++) {
                int d = nt * 8 + tq;
                float t0 = tabS[rc * 68 + d], t1 = tabS[rc * 68 + d + 1];
                acc[nt][0] += pg * t0; acc[nt][1] += pg * t1;
                acc[nt][2] += ph * t0; acc[nt][3] += ph * t1;
            }
        }
    }

    // ---- normalize + write ----
    float ig = 1.0f / l_g, ih = 1.0f / l_h;
    #pragma unroll
    for (int nt = 0; nt < 8; nt++) {
        int d = nt * 8 + tq;
        *(float2*)(out + ((size_t)(b * SEQ + qg)) * HID + h * 64 + d) =
            make_float2(acc[nt][0] * ig, acc[nt][1] * ig);
        *(float2*)(out + ((size_t)(b * SEQ + qh2)) * HID + h * 64 + d) =
            make_float2(acc[nt][2] * ih, acc[nt][3] * ih);
    }
}

// ---------------- launcher ----------------
extern "C" void kernel_launch(void* const* d_in, const int* in_sizes, int n_in,
                              void* d_out, int out_size) {
    const float* hs   = (const float*)d_in[0];
    const float* mask = (const float*)d_in[1];
    const float* Wq   = (const float*)d_in[2];
    const float* bq   = (const float*)d_in[3];
    const float* Wk   = (const float*)d_in[4];
    const float* bk   = (const float*)d_in[5];
    const float* Wv   = (const float*)d_in[6];
    const float* bv   = (const float*)d_in[7];
    float* out = (float*)d_out;

    cudaFuncSetAttribute(qkv_mma_kernel,    cudaFuncAttributeMaxDynamicSharedMemorySize, QKV_SMEM);
    cudaFuncSetAttribute(attn_fused_kernel, cudaFuncAttributeMaxDynamicSharedMemorySize, FA_SMEM);

    init_tab_kernel<<<(VOCAB * 32 + 127) / 128, 128>>>();
    cvt_hs_kernel<<<(BATCH * SEQ * HID / 4 + 255) / 256, 256>>>(hs);
    cvt_w_kernel<<<(3 * HID * HID / 4 + 255) / 256, 256>>>(Wq, Wk, Wv);
    qkv_mma_kernel<<<dim3(HID / 128, (BATCH * SEQ) / 128, 3), 256, QKV_SMEM>>>(bq, bk, bv);
    qrel_kernel<<<BH * SEQ / 128, 256>>>();
    attn_fused_kernel<<<dim3(SEQ / 128, BH), 256, FA_SMEM>>>(mask, out);
}

// round 12
// speedup vs baseline: 2.8648x; 1.0112x over previous
#include <cuda_runtime.h>
#include <cuda_bf16.h>
#include <cstdint>

#define BATCH 2
#define SEQ   1024
#define HID   1024
#define NHEAD 16
#define HDIM  64
#define BH    (BATCH*NHEAD)      // 32
#define VOCAB 129                // 2*64+1
#define SSTR  40                 // bf16 smem stride (BK=32 tiles): conflict-free
#define SST2  72                 // bf16 smem stride (64-col tiles): conflict-free

// ---------------- scratch ----------------
__device__ __align__(16) float g_qkv[BH * SEQ * HDIM];           // Q fp32 (for qrel)
__device__ __align__(16) float g_qrel[(size_t)BH * SEQ * VOCAB];
__device__ __align__(16) float g_tab[VOCAB * HDIM];

__device__ __align__(16) __nv_bfloat16 g_hs_hi[BATCH * SEQ * HID];
__device__ __align__(16) __nv_bfloat16 g_hs_lo[BATCH * SEQ * HID];
__device__ __align__(16) __nv_bfloat16 g_w_hi[3 * HID * HID];
__device__ __align__(16) __nv_bfloat16 g_w_lo[3 * HID * HID];
__device__ __align__(16) __nv_bfloat16 g_qh[BH * SEQ * HDIM];
__device__ __align__(16) __nv_bfloat16 g_ql[BH * SEQ * HDIM];
__device__ __align__(16) __nv_bfloat16 g_kh[BH * SEQ * HDIM];
__device__ __align__(16) __nv_bfloat16 g_kl[BH * SEQ * HDIM];
__device__ __align__(16) __nv_bfloat16 g_vth[BH * HDIM * SEQ];   // V^T [bh][d][s]
__device__ __align__(16) __nv_bfloat16 g_vtl[BH * HDIM * SEQ];

// ---------------- helpers ----------------
__device__ __forceinline__ void cp_async16(void* dst, const void* src) {
    unsigned int d = (unsigned int)__cvta_generic_to_shared(dst);
    asm volatile("cp.async.cg.shared.global [%0], [%1], 16;" :: "r"(d), "l"(src));
}
__device__ __forceinline__ void cp_commit() { asm volatile("cp.async.commit_group;"); }
__device__ __forceinline__ void cp_wait0()  { asm volatile("cp.async.wait_group 0;"); }
__device__ __forceinline__ void cp_wait1()  { asm volatile("cp.async.wait_group 1;"); }

__device__ __forceinline__ void ldsm4(unsigned* r, const void* p) {
    unsigned a = (unsigned)__cvta_generic_to_shared(p);
    asm volatile("ldmatrix.sync.aligned.m8n8.x4.shared.b16 {%0,%1,%2,%3}, [%4];"
                 : "=r"(r[0]), "=r"(r[1]), "=r"(r[2]), "=r"(r[3]) : "r"(a));
}

__device__ __forceinline__ void split_bf16(float v, __nv_bfloat16& hi, __nv_bfloat16& lo) {
    hi = __float2bfloat16_rn(v);
    lo = __float2bfloat16_rn(v - __bfloat162float(hi));
}
__device__ __forceinline__ unsigned pack2h(float a, float b) {
    __nv_bfloat162 p(__float2bfloat16_rn(a), __float2bfloat16_rn(b));
    return *(unsigned*)&p;
}
__device__ __forceinline__ unsigned pack2l(float a, float b) {
    float ra = a - __bfloat162float(__float2bfloat16_rn(a));
    float rb = b - __bfloat162float(__float2bfloat16_rn(b));
    __nv_bfloat162 p(__float2bfloat16_rn(ra), __float2bfloat16_rn(rb));
    return *(unsigned*)&p;
}
__device__ __forceinline__ float quadmax(float v) {
    v = fmaxf(v, __shfl_xor_sync(0xffffffffu, v, 1));
    v = fmaxf(v, __shfl_xor_sync(0xffffffffu, v, 2));
    return v;
}
__device__ __forceinline__ float quadsum(float v) {
    v += __shfl_xor_sync(0xffffffffu, v, 1);
    v += __shfl_xor_sync(0xffffffffu, v, 2);
    return v;
}
__device__ __forceinline__ void mma_bf16(float* c, const unsigned int* A,
                                         unsigned int b0, unsigned int b1) {
    asm volatile("mma.sync.aligned.m16n8k16.row.col.f32.bf16.bf16.f32 "
        "{%0,%1,%2,%3}, {%4,%5,%6,%7}, {%8,%9}, {%0,%1,%2,%3};"
        : "+f"(c[0]), "+f"(c[1]), "+f"(c[2]), "+f"(c[3])
        : "r"(A[0]), "r"(A[1]), "r"(A[2]), "r"(A[3]), "r"(b0), "r"(b1));
}

// ---------------- sinusoid table ----------------
__global__ void init_tab_kernel() {
    int idx = blockIdx.x * blockDim.x + threadIdx.x;
    if (idx >= VOCAB * 32) return;
    int p = idx >> 5, i = idx & 31;
    float div = expf((float)(2 * i) * (-9.210340371976184f / 64.0f));
    float ang = (float)p * div;
    g_tab[p * 64 + 2 * i]     = sinf(ang);
    g_tab[p * 64 + 2 * i + 1] = cosf(ang);
}

__global__ __launch_bounds__(256) void cvt_hs_kernel(const float* __restrict__ hs) {
    int i = (blockIdx.x * blockDim.x + threadIdx.x) * 4;
    if (i >= BATCH * SEQ * HID) return;
    float4 v = *(const float4*)(hs + i);
    __nv_bfloat16 h, l;
    split_bf16(v.x, h, l); g_hs_hi[i + 0] = h; g_hs_lo[i + 0] = l;
    split_bf16(v.y, h, l); g_hs_hi[i + 1] = h; g_hs_lo[i + 1] = l;
    split_bf16(v.z, h, l); g_hs_hi[i + 2] = h; g_hs_lo[i + 2] = l;
    split_bf16(v.w, h, l); g_hs_hi[i + 3] = h; g_hs_lo[i + 3] = l;
}

__global__ __launch_bounds__(256) void cvt_w_kernel(
    const float* __restrict__ Wq, const float* __restrict__ Wk, const float* __restrict__ Wv) {
    int i = (blockIdx.x * blockDim.x + threadIdx.x) * 4;
    if (i >= 3 * HID * HID) return;
    int z = i / (HID * HID), r = i - z * (HID * HID);
    const float* W = (z == 0) ? Wq : (z == 1 ? Wk : Wv);
    float4 v = *(const float4*)(W + r);
    __nv_bfloat16 h, l;
    split_bf16(v.x, h, l); g_w_hi[i + 0] = h; g_w_lo[i + 0] = l;
    split_bf16(v.y, h, l); g_w_hi[i + 1] = h; g_w_lo[i + 1] = l;
    split_bf16(v.z, h, l); g_w_hi[i + 2] = h; g_w_lo[i + 2] = l;
    split_bf16(v.w, h, l); g_w_hi[i + 3] = h; g_w_lo[i + 3] = l;
}

// ---------------- phase 1: QKV projection, BK=32 2-stage, 2 CTAs/SM ----------------
#define QKV_AS    (128 * SSTR)        // 5120 elems per array
#define QKV_STAGE (4 * QKV_AS)        // 20480 elems
#define QKV_SMEM  (2 * QKV_STAGE * 2) // 81920 B -> two CTAs per SM

__global__ __launch_bounds__(256, 2) void qkv_mma_kernel(
    const float* __restrict__ bq, const float* __restrict__ bk, const float* __restrict__ bv)
{
    extern __shared__ __align__(16) __nv_bfloat16 dsm[];
    int z = blockIdx.z;
    const float* bias = (z == 0) ? bq : (z == 1 ? bk : bv);
    const __nv_bfloat16* gWhi = g_w_hi + (size_t)z * HID * HID;
    const __nv_bfloat16* gWlo = g_w_lo + (size_t)z * HID * HID;

    int m0 = blockIdx.y * 128, n0 = blockIdx.x * 128;
    int t = threadIdx.x;
    int lane = t & 31, warp = t >> 5;
    int wy = warp >> 2, wx = warp & 3;
    int g = lane >> 2, tq = (lane & 3) * 2;
    int arow = lane & 15, acol8 = (lane >> 4) * 8;
    int brow = ((lane >> 4) << 3) + (lane & 7), bcol8 = ((lane >> 3) & 1) * 8;

    float acc[4][4][4] = {};

    auto load_stage = [&](int stg, int k0) {
        __nv_bfloat16* base = dsm + stg * QKV_STAGE;
        #pragma unroll
        for (int u = 0; u < 2; u++) {
            int idx = t + 256 * u;
            int r = idx >> 2, ce = (idx & 3) * 8;
            size_t ga = (size_t)(m0 + r) * HID + k0 + ce;
            size_t gb = (size_t)(n0 + r) * HID + k0 + ce;
            int so = r * SSTR + ce;
            cp_async16(base + 0 * QKV_AS + so, g_hs_hi + ga);
            cp_async16(base + 1 * QKV_AS + so, g_hs_lo + ga);
            cp_async16(base + 2 * QKV_AS + so, gWhi + gb);
            cp_async16(base + 3 * QKV_AS + so, gWlo + gb);
        }
    };

    load_stage(0, 0);
    cp_commit();

    for (int k0 = 0; k0 < HID; k0 += 32) {
        int stg = (k0 >> 5) & 1;
        if (k0 + 32 < HID) { load_stage(stg ^ 1, k0 + 32); cp_commit(); cp_wait1(); }
        else               { cp_wait0(); }
        __syncthreads();
        const __nv_bfloat16* sAhi = dsm + stg * QKV_STAGE;
        const __nv_bfloat16* sAlo = sAhi + QKV_AS;
        const __nv_bfloat16* sBhi = sAlo + QKV_AS;
        const __nv_bfloat16* sBlo = sBhi + QKV_AS;

        #pragma unroll
        for (int kk = 0; kk < 32; kk += 16) {
            unsigned ahi[4][4], alo[4][4];
            #pragma unroll
            for (int mt = 0; mt < 4; mt++) {
                int ab = (wy * 64 + mt * 16 + arow) * SSTR + kk + acol8;
                ldsm4(ahi[mt], sAhi + ab);
                ldsm4(alo[mt], sAlo + ab);
            }
            #pragma unroll
            for (int ntp = 0; ntp < 2; ntp++) {
                int bb = (wx * 32 + ntp * 16 + brow) * SSTR + kk + bcol8;
                unsigned bh[4], bl[4];
                ldsm4(bh, sBhi + bb);
                ldsm4(bl, sBlo + bb);
                #pragma unroll
                for (int mt = 0; mt < 4; mt++) {
                    mma_bf16(acc[mt][2 * ntp],     ahi[mt], bh[0], bh[1]);
                    mma_bf16(acc[mt][2 * ntp],     ahi[mt], bl[0], bl[1]);
                    mma_bf16(acc[mt][2 * ntp],     alo[mt], bh[0], bh[1]);
                    mma_bf16(acc[mt][2 * ntp + 1], ahi[mt], bh[2], bh[3]);
                    mma_bf16(acc[mt][2 * ntp + 1], ahi[mt], bl[2], bl[3]);
                    mma_bf16(acc[mt][2 * ntp + 1], alo[mt], bh[2], bh[3]);
                }
            }
        }
        __syncthreads();
    }

    #pragma unroll
    for (int nt = 0; nt < 4; nt++) {
        int n = n0 + wx * 32 + nt * 8 + tq;
        float2 b2 = *(const float2*)&bias[n];
        int h = n >> 6, d = n & 63;
        #pragma unroll
        for (int mt = 0; mt < 4; mt++) {
            int m = m0 + wy * 64 + mt * 16 + g;
            int b = m >> 10, s = m & (SEQ - 1);
            int bh = b * NHEAD + h;
            float v0 = acc[mt][nt][0] + b2.x, v1 = acc[mt][nt][1] + b2.y;
            float v2 = acc[mt][nt][2] + b2.x, v3 = acc[mt][nt][3] + b2.y;
            __nv_bfloat16 h0, l0, h1, l1, h2, l2, h3, l3;
            split_bf16(v0, h0, l0); split_bf16(v1, h1, l1);
            split_bf16(v2, h2, l2); split_bf16(v3, h3, l3);
            if (z < 2) {
                __nv_bfloat16* ah = (z == 0) ? g_qh : g_kh;
                __nv_bfloat16* al = (z == 0) ? g_ql : g_kl;
                size_t o0 = ((size_t)bh * SEQ + s) * HDIM + d;
                size_t o1 = o0 + 8 * HDIM;
                *(__nv_bfloat162*)(ah + o0) = __nv_bfloat162(h0, h1);
                *(__nv_bfloat162*)(al + o0) = __nv_bfloat162(l0, l1);
                *(__nv_bfloat162*)(ah + o1) = __nv_bfloat162(h2, h3);
                *(__nv_bfloat162*)(al + o1) = __nv_bfloat162(l2, l3);
                if (z == 0) {
                    *(float2*)(g_qkv + o0) = make_float2(v0, v1);
                    *(float2*)(g_qkv + o1) = make_float2(v2, v3);
                }
            } else {
                size_t base = ((size_t)bh * HDIM + d) * SEQ + s;
                g_vth[base] = h0;           g_vtl[base] = l0;
                g_vth[base + SEQ] = h1;     g_vtl[base + SEQ] = l1;
                g_vth[base + 8] = h2;       g_vtl[base + 8] = l2;
                g_vth[base + SEQ + 8] = h3; g_vtl[base + SEQ + 8] = l3;
            }
        }
    }
}

// ---------------- phase 1.5: qrel = Q @ tab^T, broadcast-friendly ----------------
__global__ __launch_bounds__(256) void qrel_kernel() {
    int t = threadIdx.x;
    int row = blockIdx.x * 128 + (t & 127);
    int half = t >> 7;
    const float* Q = g_qkv + (size_t)row * HDIM;
    float q[64];
    #pragma unroll
    for (int d4 = 0; d4 < 16; d4++) {
        float4 v = *(const float4*)(Q + d4 * 4);
        q[d4 * 4 + 0] = v.x; q[d4 * 4 + 1] = v.y;
        q[d4 * 4 + 2] = v.z; q[d4 * 4 + 3] = v.w;
    }
    int c0 = half * 65;
    int cn = half ? 64 : 65;
    float* dst = g_qrel + (size_t)row * VOCAB;
    for (int j = 0; j < cn; j++) {
        int c = c0 + j;
        const float* tr = g_tab + c * 64;
        float s = 0.f;
        #pragma unroll
        for (int d4 = 0; d4 < 16; d4++) {
            float4 tv = *(const float4*)(tr + d4 * 4);
            s += q[d4*4]*tv.x + q[d4*4+1]*tv.y + q[d4*4+2]*tv.z + q[d4*4+3]*tv.w;
        }
        dst[c] = s;
    }
}

// ---------------- phase 2-4 fused: flash attention + rel-pos ----------------
#define FA_QAS   9216                  // 128*72
#define FA_KAS   4608                  // 64*72
#define FA_STAGE (4 * FA_KAS)
#define FA_PSOFF (2 * FA_QAS + 2 * FA_STAGE)
#define FA_SMEM  (FA_PSOFF * 2 + 128 * 132 * 4 + 4096)

__global__ __launch_bounds__(256) void attn_fused_kernel(
    const float* __restrict__ mask, float* __restrict__ out)
{
    extern __shared__ __align__(16) __nv_bfloat16 dsm[];
    const int bh = blockIdx.y, b = bh >> 4, h = bh & 15;
    const int q0 = blockIdx.x * 128;
    const int t = threadIdx.x, lane = t & 31, w = t >> 5;
    const int g = lane >> 2, tq = (lane & 3) * 2;
    const int arow = lane & 15, acol8 = (lane >> 4) * 8;
    const int brow = ((lane >> 4) << 3) + (lane & 7), bcol8 = ((lane >> 3) & 1) * 8;

    __nv_bfloat16* sQhi = dsm;
    __nv_bfloat16* sQlo = dsm + FA_QAS;
    float* psm = (float*)(dsm + FA_PSOFF);
    float* smask = psm + 128 * 132;

    {
        size_t qrbase = ((size_t)bh * SEQ + q0) * VOCAB;
        for (int i = t; i < 128 * 132; i += 256) {
            int r = i / 132, c = i - r * 132;
            psm[i] = (c < VOCAB) ? g_qrel[qrbase + (size_t)r * VOCAB + c] : 0.0f;
        }
    }
    cp_async16(smask + t * 4, mask + (size_t)b * SEQ + t * 4);

    #pragma unroll
    for (int u = 0; u < 4; u++) {
        int idx = t + 256 * u;
        int r = idx >> 3, ce = (idx & 7) * 8;
        size_t ga = ((size_t)bh * SEQ + q0 + r) * HDIM + ce;
        int so = r * SST2 + ce;
        cp_async16(sQhi + so, g_qh + ga);
        cp_async16(sQlo + so, g_ql + ga);
    }
    auto load_kv = [&](int stg, int kt0) {
        __nv_bfloat16* base = dsm + 2 * FA_QAS + stg * FA_STAGE;
        #pragma unroll
        for (int u = 0; u < 2; u++) {
            int idx = t + 256 * u;
            int r = idx >> 3, ce = (idx & 7) * 8;
            int so = r * SST2 + ce;
            size_t gk = ((size_t)bh * SEQ + kt0 + r) * HDIM + ce;
            size_t gv = ((size_t)bh * HDIM + r) * SEQ + kt0 + ce;
            cp_async16(base + 0 * FA_KAS + so, g_kh + gk);
            cp_async16(base + 1 * FA_KAS + so, g_kl + gk);
            cp_async16(base + 2 * FA_KAS + so, g_vth + gv);
            cp_async16(base + 3 * FA_KAS + so, g_vtl + gv);
        }
    };
    load_kv(0, 0);
    cp_commit();

    const int qg = q0 + w * 16 + g;
    const int qh2 = qg + 8;
    const float* qrg = g_qrel + ((size_t)bh * SEQ + qg) * VOCAB;
    const float* qrh = g_qrel + ((size_t)bh * SEQ + qh2) * VOCAB;
    const float qr0g = qrg[0], qr128g = qrg[128];
    const float qr0h = qrh[0], qr128h = qrh[128];
    float* prowg = psm + (w * 16 + g) * 132;
    float* prowh = prowg + 8 * 132;

    float acc[8][4] = {};
    float m_g = -1e30f, m_h = -1e30f;
    float l_g = 0.f, l_h = 0.f, lo_g = 0.f, lo_h = 0.f, hi_g = 0.f, hi_h = 0.f;

    for (int kt = 0; kt < 16; kt++) {
        int kt0 = kt * 64;
        if (kt < 15) { load_kv((kt ^ 1) & 1, kt0 + 64); cp_commit(); cp_wait1(); }
        else         { cp_wait0(); }
        __syncthreads();
        const __nv_bfloat16* stage = dsm + 2 * FA_QAS + (kt & 1) * FA_STAGE;
        const __nv_bfloat16* sKhi = stage;
        const __nv_bfloat16* sKlo = stage + FA_KAS;
        const __nv_bfloat16* sVhi = stage + 2 * FA_KAS;
        const __nv_bfloat16* sVlo = stage + 3 * FA_KAS;

        float s[8][4] = {};
        #pragma unroll
        for (int kk = 0; kk < 64; kk += 16) {
            unsigned ahi[4], alo[4];
            int ab = (w * 16 + arow) * SST2 + kk + acol8;
            ldsm4(ahi, sQhi + ab);
            ldsm4(alo, sQlo + ab);
            #pragma unroll
            for (int ntp = 0; ntp < 4; ntp++) {
                int bb = (ntp * 16 + brow) * SST2 + kk + bcol8;
                unsigned kh[4], kl[4];
                ldsm4(kh, sKhi + bb);
                ldsm4(kl, sKlo + bb);
                mma_bf16(s[2 * ntp],     ahi, kh[0], kh[1]);
                mma_bf16(s[2 * ntp],     ahi, kl[0], kl[1]);
                mma_bf16(s[2 * ntp],     alo, kh[0], kh[1]);
                mma_bf16(s[2 * ntp + 1], ahi, kh[2], kh[3]);
                mma_bf16(s[2 * ntp + 1], ahi, kl[2], kl[3]);
                mma_bf16(s[2 * ntp + 1], alo, kh[2], kh[3]);
            }
        }

        #pragma unroll
        for (int nt = 0; nt < 8; nt++) {
            int k = kt0 + nt * 8 + tq;
            float mk0 = smask[k], mk1 = smask[k + 1];
            int d0 = k - qg, d1 = k + 1 - qg;
            if (d0 > -64 && d0 < 64) {
                float sv = (s[nt][0] + prowg[d0 + 64]) * 0.125f + mk0;
                prowg[d0 + 64] = sv; s[nt][0] = sv;
            } else s[nt][0] = (s[nt][0] + (d0 <= -64 ? qr0g : qr128g)) * 0.125f + mk0;
            if (d1 > -64 && d1 < 64) {
                float sv = (s[nt][1] + prowg[d1 + 64]) * 0.125f + mk1;
                prowg[d1 + 64] = sv; s[nt][1] = sv;
            } else s[nt][1] = (s[nt][1] + (d1 <= -64 ? qr0g : qr128g)) * 0.125f + mk1;
            int e0 = k - qh2, e1 = k + 1 - qh2;
            if (e0 > -64 && e0 < 64) {
                float sv = (s[nt][2] + prowh[e0 + 64]) * 0.125f + mk0;
                prowh[e0 + 64] = sv; s[nt][2] = sv;
            } else s[nt][2] = (s[nt][2] + (e0 <= -64 ? qr0h : qr128h)) * 0.125f + mk0;
            if (e1 > -64 && e1 < 64) {
                float sv = (s[nt][3] + prowh[e1 + 64]) * 0.125f + mk1;
                prowh[e1 + 64] = sv; s[nt][3] = sv;
            } else s[nt][3] = (s[nt][3] + (e1 <= -64 ? qr0h : qr128h)) * 0.125f + mk1;
        }

        float tg = -1e30f, th = -1e30f;
        #pragma unroll
        for (int nt = 0; nt < 8; nt++) {
            tg = fmaxf(tg, fmaxf(s[nt][0], s[nt][1]));
            th = fmaxf(th, fmaxf(s[nt][2], s[nt][3]));
        }
        tg = quadmax(tg); th = quadmax(th);
        float mng = fmaxf(m_g, tg), mnh = fmaxf(m_h, th);
        float scg = __expf(m_g - mng), sch = __expf(m_h - mnh);
        if (scg < 1.0f) {
            #pragma unroll
            for (int nt = 0; nt < 8; nt++) { acc[nt][0] *= scg; acc[nt][1] *= scg; }
            l_g *= scg; lo_g *= scg; hi_g *= scg;
        }
        if (sch < 1.0f) {
            #pragma unroll
            for (int nt = 0; nt < 8; nt++) { acc[nt][2] *= sch; acc[nt][3] *= sch; }
            l_h *= sch; lo_h *= sch; hi_h *= sch;
        }
        m_g = mng; m_h = mnh;

        unsigned phi[4][4], plo[4][4];
        #pragma unroll
        for (int nt = 0; nt < 8; nt++) {
            int k = kt0 + nt * 8 + tq;
            float p0 = __expf(s[nt][0] - m_g), p1 = __expf(s[nt][1] - m_g);
            float p2 = __expf(s[nt][2] - m_h), p3 = __expf(s[nt][3] - m_h);
            l_g += p0 + p1; l_h += p2 + p3;
            int d0 = k - qg, d1 = k + 1 - qg;
            if (d0 <= -64) lo_g += p0; else if (d0 >= 64) hi_g += p0;
            if (d1 <= -64) lo_g += p1; else if (d1 >= 64) hi_g += p1;
            int e0 = k - qh2, e1 = k + 1 - qh2;
            if (e0 <= -64) lo_h += p2; else if (e0 >= 64) hi_h += p2;
            if (e1 <= -64) lo_h += p3; else if (e1 >= 64) hi_h += p3;
            int kb = nt >> 1;
            if ((nt & 1) == 0) {
                phi[kb][0] = pack2h(p0, p1); phi[kb][1] = pack2h(p2, p3);
                plo[kb][0] = pack2l(p0, p1); plo[kb][1] = pack2l(p2, p3);
            } else {
                phi[kb][2] = pack2h(p0, p1); phi[kb][3] = pack2h(p2, p3);
                plo[kb][2] = pack2l(p0, p1); plo[kb][3] = pack2l(p2, p3);
            }
        }

        #pragma unroll
        for (int kb = 0; kb < 4; kb++) {
            int kk = kb * 16;
            #pragma unroll
            for (int ntp = 0; ntp < 4; ntp++) {
                int bb = (ntp * 16 + brow) * SST2 + kk + bcol8;
                unsigned vh[4], vl[4];
                ldsm4(vh, sVhi + bb);
                ldsm4(vl, sVlo + bb);
                mma_bf16(acc[2 * ntp],     phi[kb], vh[0], vh[1]);
                mma_bf16(acc[2 * ntp],     phi[kb], vl[0], vl[1]);
                mma_bf16(acc[2 * ntp],     plo[kb], vh[0], vh[1]);
                mma_bf16(acc[2 * ntp + 1], phi[kb], vh[2], vh[3]);
                mma_bf16(acc[2 * ntp + 1], phi[kb], vl[2], vl[3]);
                mma_bf16(acc[2 * ntp + 1], plo[kb], vh[2], vh[3]);
            }
        }
        __syncthreads();
    }

    l_g = quadsum(l_g); l_h = quadsum(l_h);
    lo_g = quadsum(lo_g); lo_h = quadsum(lo_h);
    hi_g = quadsum(hi_g); hi_h = quadsum(hi_h);
    if ((lane & 3) == 0) {
        prowg[0] = lo_g; prowg[128] = hi_g;
        prowh[0] = lo_h; prowh[128] = hi_h;
    }
    {
        int c0 = (lane & 3) * 33; if (c0 == 0) c0 = 1;
        int c1 = (lane & 3) * 33 + 33; if (c1 > 128) c1 = 128;
        for (int c = c0; c < c1; c++) {
            int kg = qg + c - 64;
            int kh2 = qh2 + c - 64;
            prowg[c] = (kg >= 0 && kg < SEQ) ? __expf(prowg[c] - m_g) : 0.0f;
            prowh[c] = (kh2 >= 0 && kh2 < SEQ) ? __expf(prowh[c] - m_h) : 0.0f;
        }
    }
    __syncthreads();

    float* tabS = (float*)(dsm + 2 * FA_QAS);
    for (int r0 = 0; r0 < VOCAB; r0 += 16) {
        __syncthreads();
        {
            int rr = t >> 4, cc = (t & 15) * 4;
            int r = r0 + rr;
            float4 tv = (r < VOCAB) ? *(const float4*)&g_tab[r * 64 + cc]
                                    : make_float4(0.f, 0.f, 0.f, 0.f);
            *(float4*)&tabS[rr * 68 + cc] = tv;
        }
        __syncthreads();
        #pragma unroll
        for (int rc = 0; rc < 16; rc++) {
            int rr2 = r0 + rc; if (rr2 > 128) rr2 = 128;
            float pg = prowg[rr2];
            float ph = prowh[rr2];
            #pragma unroll
            for (int nt = 0; nt < 8; nt++) {
                int d = nt * 8 + tq;
                float t0 = tabS[rc * 68 + d], t1 = tabS[rc * 68 + d + 1];
                acc[nt][0] += pg * t0; acc[nt][1] += pg * t1;
                acc[nt][2] += ph * t0; acc[nt][3] += ph * t1;
            }
        }
    }

    float ig = 1.0f / l_g, ih = 1.0f / l_h;
    #pragma unroll
    for (int nt = 0; nt < 8; nt++) {
        int d = nt * 8 + tq;
        *(float2*)(out + ((size_t)(b * SEQ + qg)) * HID + h * 64 + d) =
            make_float2(acc[nt][0] * ig, acc[nt][1] * ig);
        *(float2*)(out + ((size_t)(b * SEQ + qh2)) * HID + h * 64 + d) =
            make_float2(acc[nt][2] * ih, acc[nt][3] * ih);
    }
}

// ---------------- launcher ----------------
extern "C" void kernel_launch(void* const* d_in, const int* in_sizes, int n_in,
                              void* d_out, int out_size) {
    const float* hs   = (const float*)d_in[0];
    const float* mask = (const float*)d_in[1];
    const float* Wq   = (const float*)d_in[2];
    const float* bq   = (const float*)d_in[3];
    const float* Wk   = (const float*)d_in[4];
    const float* bk   = (const float*)d_in[5];
    const float* Wv   = (const float*)d_in[6];
    const float* bv   = (const float*)d_in[7];
    float* out = (float*)d_out;

    cudaFuncSetAttribute(qkv_mma_kernel,    cudaFuncAttributeMaxDynamicSharedMemorySize, QKV_SMEM);
    cudaFuncSetAttribute(attn_fused_kernel, cudaFuncAttributeMaxDynamicSharedMemorySize, FA_SMEM);

    init_tab_kernel<<<(VOCAB * 32 + 127) / 128, 128>>>();
    cvt_hs_kernel<<<(BATCH * SEQ * HID / 4 + 255) / 256, 256>>>(hs);
    cvt_w_kernel<<<(3 * HID * HID / 4 + 255) / 256, 256>>>(Wq, Wk, Wv);
    qkv_mma_kernel<<<dim3(HID / 128, (BATCH * SEQ) / 128, 3), 256, QKV_SMEM>>>(bq, bk, bv);
    qrel_kernel<<<BH * SEQ / 128, 256>>>();
    attn_fused_kernel<<<dim3(SEQ / 128, BH), 256, FA_SMEM>>>(mask, out);
}

// round 13
// speedup vs baseline: 3.4562x; 1.2064x over previous
#include <cuda_runtime.h>
#include <cuda_bf16.h>
#include <cstdint>

#define BATCH 2
#define SEQ   1024
#define HID   1024
#define NHEAD 16
#define HDIM  64
#define BH    (BATCH*NHEAD)      // 32
#define VOCAB 129                // 2*64+1
#define TABP  144                // tab rows padded for MMA
#define SSTR  40                 // bf16 smem stride (BK=32 tiles): conflict-free
#define SST2  72                 // bf16 smem stride (64-col tiles): conflict-free

// ---------------- scratch ----------------
__device__ __align__(16) float g_tab[VOCAB * HDIM];
__device__ __align__(16) __nv_bfloat16 g_tab_hi[TABP * HDIM];
__device__ __align__(16) __nv_bfloat16 g_tab_lo[TABP * HDIM];

__device__ __align__(16) __nv_bfloat16 g_hs_hi[BATCH * SEQ * HID];
__device__ __align__(16) __nv_bfloat16 g_hs_lo[BATCH * SEQ * HID];
__device__ __align__(16) __nv_bfloat16 g_w_hi[3 * HID * HID];
__device__ __align__(16) __nv_bfloat16 g_w_lo[3 * HID * HID];
__device__ __align__(16) __nv_bfloat16 g_qh[BH * SEQ * HDIM];
__device__ __align__(16) __nv_bfloat16 g_ql[BH * SEQ * HDIM];
__device__ __align__(16) __nv_bfloat16 g_kh[BH * SEQ * HDIM];
__device__ __align__(16) __nv_bfloat16 g_kl[BH * SEQ * HDIM];
__device__ __align__(16) __nv_bfloat16 g_vth[BH * HDIM * SEQ];   // V^T [bh][d][s]
__device__ __align__(16) __nv_bfloat16 g_vtl[BH * HDIM * SEQ];

// ---------------- helpers ----------------
__device__ __forceinline__ void cp_async16(void* dst, const void* src) {
    unsigned int d = (unsigned int)__cvta_generic_to_shared(dst);
    asm volatile("cp.async.cg.shared.global [%0], [%1], 16;" :: "r"(d), "l"(src));
}
__device__ __forceinline__ void cp_commit() { asm volatile("cp.async.commit_group;"); }
__device__ __forceinline__ void cp_wait0()  { asm volatile("cp.async.wait_group 0;"); }
__device__ __forceinline__ void cp_wait1()  { asm volatile("cp.async.wait_group 1;"); }

__device__ __forceinline__ void ldsm4(unsigned* r, const void* p) {
    unsigned a = (unsigned)__cvta_generic_to_shared(p);
    asm volatile("ldmatrix.sync.aligned.m8n8.x4.shared.b16 {%0,%1,%2,%3}, [%4];"
                 : "=r"(r[0]), "=r"(r[1]), "=r"(r[2]), "=r"(r[3]) : "r"(a));
}

__device__ __forceinline__ void split_bf16(float v, __nv_bfloat16& hi, __nv_bfloat16& lo) {
    hi = __float2bfloat16_rn(v);
    lo = __float2bfloat16_rn(v - __bfloat162float(hi));
}
__device__ __forceinline__ unsigned pack2h(float a, float b) {
    __nv_bfloat162 p(__float2bfloat16_rn(a), __float2bfloat16_rn(b));
    return *(unsigned*)&p;
}
__device__ __forceinline__ unsigned pack2l(float a, float b) {
    float ra = a - __bfloat162float(__float2bfloat16_rn(a));
    float rb = b - __bfloat162float(__float2bfloat16_rn(b));
    __nv_bfloat162 p(__float2bfloat16_rn(ra), __float2bfloat16_rn(rb));
    return *(unsigned*)&p;
}
__device__ __forceinline__ float quadmax(float v) {
    v = fmaxf(v, __shfl_xor_sync(0xffffffffu, v, 1));
    v = fmaxf(v, __shfl_xor_sync(0xffffffffu, v, 2));
    return v;
}
__device__ __forceinline__ float quadsum(float v) {
    v += __shfl_xor_sync(0xffffffffu, v, 1);
    v += __shfl_xor_sync(0xffffffffu, v, 2);
    return v;
}
__device__ __forceinline__ void mma_bf16(float* c, const unsigned int* A,
                                         unsigned int b0, unsigned int b1) {
    asm volatile("mma.sync.aligned.m16n8k16.row.col.f32.bf16.bf16.f32 "
        "{%0,%1,%2,%3}, {%4,%5,%6,%7}, {%8,%9}, {%0,%1,%2,%3};"
        : "+f"(c[0]), "+f"(c[1]), "+f"(c[2]), "+f"(c[3])
        : "r"(A[0]), "r"(A[1]), "r"(A[2]), "r"(A[3]), "r"(b0), "r"(b1));
}

// ---------------- sinusoid table (float + padded bf16 hi/lo) ----------------
__global__ void init_tab_kernel() {
    int idx = blockIdx.x * blockDim.x + threadIdx.x;
    if (idx >= TABP * 32) return;
    int p = idx >> 5, i = idx & 31;
    if (p < VOCAB) {
        float div = expf((float)(2 * i) * (-9.210340371976184f / 64.0f));
        float ang = (float)p * div;
        float sv = sinf(ang), cv = cosf(ang);
        g_tab[p * 64 + 2 * i]     = sv;
        g_tab[p * 64 + 2 * i + 1] = cv;
        __nv_bfloat16 h, l;
        split_bf16(sv, h, l); g_tab_hi[p * 64 + 2 * i] = h;     g_tab_lo[p * 64 + 2 * i] = l;
        split_bf16(cv, h, l); g_tab_hi[p * 64 + 2 * i + 1] = h; g_tab_lo[p * 64 + 2 * i + 1] = l;
    } else {
        g_tab_hi[p * 64 + 2 * i] = __float2bfloat16_rn(0.f);
        g_tab_hi[p * 64 + 2 * i + 1] = __float2bfloat16_rn(0.f);
        g_tab_lo[p * 64 + 2 * i] = __float2bfloat16_rn(0.f);
        g_tab_lo[p * 64 + 2 * i + 1] = __float2bfloat16_rn(0.f);
    }
}

__global__ __launch_bounds__(256) void cvt_hs_kernel(const float* __restrict__ hs) {
    int i = (blockIdx.x * blockDim.x + threadIdx.x) * 4;
    if (i >= BATCH * SEQ * HID) return;
    float4 v = *(const float4*)(hs + i);
    __nv_bfloat16 h, l;
    split_bf16(v.x, h, l); g_hs_hi[i + 0] = h; g_hs_lo[i + 0] = l;
    split_bf16(v.y, h, l); g_hs_hi[i + 1] = h; g_hs_lo[i + 1] = l;
    split_bf16(v.z, h, l); g_hs_hi[i + 2] = h; g_hs_lo[i + 2] = l;
    split_bf16(v.w, h, l); g_hs_hi[i + 3] = h; g_hs_lo[i + 3] = l;
}

__global__ __launch_bounds__(256) void cvt_w_kernel(
    const float* __restrict__ Wq, const float* __restrict__ Wk, const float* __restrict__ Wv) {
    int i = (blockIdx.x * blockDim.x + threadIdx.x) * 4;
    if (i >= 3 * HID * HID) return;
    int z = i / (HID * HID), r = i - z * (HID * HID);
    const float* W = (z == 0) ? Wq : (z == 1 ? Wk : Wv);
    float4 v = *(const float4*)(W + r);
    __nv_bfloat16 h, l;
    split_bf16(v.x, h, l); g_w_hi[i + 0] = h; g_w_lo[i + 0] = l;
    split_bf16(v.y, h, l); g_w_hi[i + 1] = h; g_w_lo[i + 1] = l;
    split_bf16(v.z, h, l); g_w_hi[i + 2] = h; g_w_lo[i + 2] = l;
    split_bf16(v.w, h, l); g_w_hi[i + 3] = h; g_w_lo[i + 3] = l;
}

// ---------------- phase 1: QKV projection, BK=32 2-stage, 2 CTAs/SM ----------------
#define QKV_AS    (128 * SSTR)        // 5120 elems per array
#define QKV_STAGE (4 * QKV_AS)        // 20480 elems
#define QKV_SMEM  (2 * QKV_STAGE * 2) // 81920 B

__global__ __launch_bounds__(256, 2) void qkv_mma_kernel(
    const float* __restrict__ bq, const float* __restrict__ bk, const float* __restrict__ bv)
{
    extern __shared__ __align__(16) __nv_bfloat16 dsm[];
    int z = blockIdx.z;
    const float* bias = (z == 0) ? bq : (z == 1 ? bk : bv);
    const __nv_bfloat16* gWhi = g_w_hi + (size_t)z * HID * HID;
    const __nv_bfloat16* gWlo = g_w_lo + (size_t)z * HID * HID;

    int m0 = blockIdx.y * 128, n0 = blockIdx.x * 128;
    int t = threadIdx.x;
    int lane = t & 31, warp = t >> 5;
    int wy = warp >> 2, wx = warp & 3;
    int g = lane >> 2, tq = (lane & 3) * 2;
    int arow = lane & 15, acol8 = (lane >> 4) * 8;
    int brow = ((lane >> 4) << 3) + (lane & 7), bcol8 = ((lane >> 3) & 1) * 8;

    float acc[4][4][4] = {};

    auto load_stage = [&](int stg, int k0) {
        __nv_bfloat16* base = dsm + stg * QKV_STAGE;
        #pragma unroll
        for (int u = 0; u < 2; u++) {
            int idx = t + 256 * u;
            int r = idx >> 2, ce = (idx & 3) * 8;
            size_t ga = (size_t)(m0 + r) * HID + k0 + ce;
            size_t gb = (size_t)(n0 + r) * HID + k0 + ce;
            int so = r * SSTR + ce;
            cp_async16(base + 0 * QKV_AS + so, g_hs_hi + ga);
            cp_async16(base + 1 * QKV_AS + so, g_hs_lo + ga);
            cp_async16(base + 2 * QKV_AS + so, gWhi + gb);
            cp_async16(base + 3 * QKV_AS + so, gWlo + gb);
        }
    };

    load_stage(0, 0);
    cp_commit();

    for (int k0 = 0; k0 < HID; k0 += 32) {
        int stg = (k0 >> 5) & 1;
        if (k0 + 32 < HID) { load_stage(stg ^ 1, k0 + 32); cp_commit(); cp_wait1(); }
        else               { cp_wait0(); }
        __syncthreads();
        const __nv_bfloat16* sAhi = dsm + stg * QKV_STAGE;
        const __nv_bfloat16* sAlo = sAhi + QKV_AS;
        const __nv_bfloat16* sBhi = sAlo + QKV_AS;
        const __nv_bfloat16* sBlo = sBhi + QKV_AS;

        #pragma unroll
        for (int kk = 0; kk < 32; kk += 16) {
            unsigned ahi[4][4], alo[4][4];
            #pragma unroll
            for (int mt = 0; mt < 4; mt++) {
                int ab = (wy * 64 + mt * 16 + arow) * SSTR + kk + acol8;
                ldsm4(ahi[mt], sAhi + ab);
                ldsm4(alo[mt], sAlo + ab);
            }
            #pragma unroll
            for (int ntp = 0; ntp < 2; ntp++) {
                int bb = (wx * 32 + ntp * 16 + brow) * SSTR + kk + bcol8;
                unsigned bh[4], bl[4];
                ldsm4(bh, sBhi + bb);
                ldsm4(bl, sBlo + bb);
                #pragma unroll
                for (int mt = 0; mt < 4; mt++) {
                    mma_bf16(acc[mt][2 * ntp],     ahi[mt], bh[0], bh[1]);
                    mma_bf16(acc[mt][2 * ntp],     ahi[mt], bl[0], bl[1]);
                    mma_bf16(acc[mt][2 * ntp],     alo[mt], bh[0], bh[1]);
                    mma_bf16(acc[mt][2 * ntp + 1], ahi[mt], bh[2], bh[3]);
                    mma_bf16(acc[mt][2 * ntp + 1], ahi[mt], bl[2], bl[3]);
                    mma_bf16(acc[mt][2 * ntp + 1], alo[mt], bh[2], bh[3]);
                }
            }
        }
        __syncthreads();
    }

    #pragma unroll
    for (int nt = 0; nt < 4; nt++) {
        int n = n0 + wx * 32 + nt * 8 + tq;
        float2 b2 = *(const float2*)&bias[n];
        int h = n >> 6, d = n & 63;
        #pragma unroll
        for (int mt = 0; mt < 4; mt++) {
            int m = m0 + wy * 64 + mt * 16 + g;
            int b = m >> 10, s = m & (SEQ - 1);
            int bh = b * NHEAD + h;
            float v0 = acc[mt][nt][0] + b2.x, v1 = acc[mt][nt][1] + b2.y;
            float v2 = acc[mt][nt][2] + b2.x, v3 = acc[mt][nt][3] + b2.y;
            __nv_bfloat16 h0, l0, h1, l1, h2, l2, h3, l3;
            split_bf16(v0, h0, l0); split_bf16(v1, h1, l1);
            split_bf16(v2, h2, l2); split_bf16(v3, h3, l3);
            if (z < 2) {
                __nv_bfloat16* ah = (z == 0) ? g_qh : g_kh;
                __nv_bfloat16* al = (z == 0) ? g_ql : g_kl;
                size_t o0 = ((size_t)bh * SEQ + s) * HDIM + d;
                size_t o1 = o0 + 8 * HDIM;
                *(__nv_bfloat162*)(ah + o0) = __nv_bfloat162(h0, h1);
                *(__nv_bfloat162*)(al + o0) = __nv_bfloat162(l0, l1);
                *(__nv_bfloat162*)(ah + o1) = __nv_bfloat162(h2, h3);
                *(__nv_bfloat162*)(al + o1) = __nv_bfloat162(l2, l3);
            } else {
                size_t base = ((size_t)bh * HDIM + d) * SEQ + s;
                g_vth[base] = h0;           g_vtl[base] = l0;
                g_vth[base + SEQ] = h1;     g_vtl[base + SEQ] = l1;
                g_vth[base + 8] = h2;       g_vtl[base + 8] = l2;
                g_vth[base + SEQ + 8] = h3; g_vtl[base + SEQ + 8] = l3;
            }
        }
    }
}

// ---------------- phase 2-4 fused: flash attention + rel-pos ----------------
// qrel computed in-kernel via split MMA vs tab (staged in KV buffers pre-loop).
#define FA_QAS   9216                  // 128*72
#define FA_KAS   4608                  // 64*72
#define FA_STAGE (4 * FA_KAS)
#define FA_PSOFF (2 * FA_QAS + 2 * FA_STAGE)
#define FA_SMEM  (FA_PSOFF * 2 + 128 * 132 * 4 + 4096)

__global__ __launch_bounds__(256) void attn_fused_kernel(
    const float* __restrict__ mask, float* __restrict__ out)
{
    extern __shared__ __align__(16) __nv_bfloat16 dsm[];
    const int bh = blockIdx.y, b = bh >> 4, h = bh & 15;
    const int q0 = blockIdx.x * 128;
    const int t = threadIdx.x, lane = t & 31, w = t >> 5;
    const int g = lane >> 2, tq = (lane & 3) * 2;
    const int arow = lane & 15, acol8 = (lane >> 4) * 8;
    const int brow = ((lane >> 4) << 3) + (lane & 7), bcol8 = ((lane >> 3) & 1) * 8;

    __nv_bfloat16* sQhi = dsm;
    __nv_bfloat16* sQlo = dsm + FA_QAS;
    float* psm = (float*)(dsm + FA_PSOFF);
    float* smask = psm + 128 * 132;

    // mask row -> smem
    cp_async16(smask + t * 4, mask + (size_t)b * SEQ + t * 4);

    // Q tile hi/lo
    #pragma unroll
    for (int u = 0; u < 4; u++) {
        int idx = t + 256 * u;
        int r = idx >> 3, ce = (idx & 7) * 8;
        size_t ga = ((size_t)bh * SEQ + q0 + r) * HDIM + ce;
        int so = r * SST2 + ce;
        cp_async16(sQhi + so, g_qh + ga);
        cp_async16(sQlo + so, g_ql + ga);
    }
    // tab hi/lo -> KV stage area (consumed before load_kv overwrites)
    __nv_bfloat16* sTabHi = dsm + 2 * FA_QAS;
    __nv_bfloat16* sTabLo = sTabHi + TABP * SST2;
    #pragma unroll
    for (int u = 0; u < 5; u++) {
        int idx = t + 256 * u;
        if (idx < TABP * 8) {
            int r = idx >> 3, ce = (idx & 7) * 8;
            cp_async16(sTabHi + r * SST2 + ce, g_tab_hi + r * 64 + ce);
            cp_async16(sTabLo + r * SST2 + ce, g_tab_lo + r * 64 + ce);
        }
    }
    cp_commit();
    cp_wait0();
    __syncthreads();

    float* prowg = psm + (w * 16 + g) * 132;
    float* prowh = prowg + 8 * 132;

    // ---- qrel = Q @ tab^T (split MMA) -> band ----
    #pragma unroll
    for (int ntp = 0; ntp < 9; ntp++) {
        float d0[4] = {}, d1[4] = {};
        #pragma unroll
        for (int kk = 0; kk < 64; kk += 16) {
            unsigned ahi[4], alo[4];
            int ab = (w * 16 + arow) * SST2 + kk + acol8;
            ldsm4(ahi, sQhi + ab);
            ldsm4(alo, sQlo + ab);
            int bb = (ntp * 16 + brow) * SST2 + kk + bcol8;
            unsigned th4[4], tl4[4];
            ldsm4(th4, sTabHi + bb);
            ldsm4(tl4, sTabLo + bb);
            mma_bf16(d0, ahi, th4[0], th4[1]);
            mma_bf16(d0, ahi, tl4[0], tl4[1]);
            mma_bf16(d0, alo, th4[0], th4[1]);
            mma_bf16(d1, ahi, th4[2], th4[3]);
            mma_bf16(d1, ahi, tl4[2], tl4[3]);
            mma_bf16(d1, alo, th4[2], th4[3]);
        }
        int c0 = ntp * 16 + tq, c1 = ntp * 16 + 8 + tq;
        if (c0 < 132) {
            prowg[c0] = d0[0]; prowg[c0 + 1] = d0[1];
            prowh[c0] = d0[2]; prowh[c0 + 1] = d0[3];
        }
        if (c1 < 132) {
            prowg[c1] = d1[0]; prowg[c1 + 1] = d1[1];
            prowh[c1] = d1[2]; prowh[c1 + 1] = d1[3];
        }
    }
    __syncthreads();

    const int qg = q0 + w * 16 + g;
    const int qh2 = qg + 8;
    const float qr0g = prowg[0], qr128g = prowg[128];
    const float qr0h = prowh[0], qr128h = prowh[128];

    auto load_kv = [&](int stg, int kt0) {
        __nv_bfloat16* base = dsm + 2 * FA_QAS + stg * FA_STAGE;
        #pragma unroll
        for (int u = 0; u < 2; u++) {
            int idx = t + 256 * u;
            int r = idx >> 3, ce = (idx & 7) * 8;
            int so = r * SST2 + ce;
            size_t gk = ((size_t)bh * SEQ + kt0 + r) * HDIM + ce;
            size_t gv = ((size_t)bh * HDIM + r) * SEQ + kt0 + ce;
            cp_async16(base + 0 * FA_KAS + so, g_kh + gk);
            cp_async16(base + 1 * FA_KAS + so, g_kl + gk);
            cp_async16(base + 2 * FA_KAS + so, g_vth + gv);
            cp_async16(base + 3 * FA_KAS + so, g_vtl + gv);
        }
    };
    load_kv(0, 0);
    cp_commit();

    float acc[8][4] = {};
    float m_g = -1e30f, m_h = -1e30f;
    float l_g = 0.f, l_h = 0.f, lo_g = 0.f, lo_h = 0.f, hi_g = 0.f, hi_h = 0.f;

    for (int kt = 0; kt < 16; kt++) {
        int kt0 = kt * 64;
        if (kt < 15) { load_kv((kt ^ 1) & 1, kt0 + 64); cp_commit(); cp_wait1(); }
        else         { cp_wait0(); }
        __syncthreads();
        const __nv_bfloat16* stage = dsm + 2 * FA_QAS + (kt & 1) * FA_STAGE;
        const __nv_bfloat16* sKhi = stage;
        const __nv_bfloat16* sKlo = stage + FA_KAS;
        const __nv_bfloat16* sVhi = stage + 2 * FA_KAS;
        const __nv_bfloat16* sVlo = stage + 3 * FA_KAS;

        float s[8][4] = {};
        #pragma unroll
        for (int kk = 0; kk < 64; kk += 16) {
            unsigned ahi[4], alo[4];
            int ab = (w * 16 + arow) * SST2 + kk + acol8;
            ldsm4(ahi, sQhi + ab);
            ldsm4(alo, sQlo + ab);
            #pragma unroll
            for (int ntp = 0; ntp < 4; ntp++) {
                int bb = (ntp * 16 + brow) * SST2 + kk + bcol8;
                unsigned kh[4], kl[4];
                ldsm4(kh, sKhi + bb);
                ldsm4(kl, sKlo + bb);
                mma_bf16(s[2 * ntp],     ahi, kh[0], kh[1]);
                mma_bf16(s[2 * ntp],     ahi, kl[0], kl[1]);
                mma_bf16(s[2 * ntp],     alo, kh[0], kh[1]);
                mma_bf16(s[2 * ntp + 1], ahi, kh[2], kh[3]);
                mma_bf16(s[2 * ntp + 1], ahi, kl[2], kl[3]);
                mma_bf16(s[2 * ntp + 1], alo, kh[2], kh[3]);
            }
        }

        #pragma unroll
        for (int nt = 0; nt < 8; nt++) {
            int k = kt0 + nt * 8 + tq;
            float mk0 = smask[k], mk1 = smask[k + 1];
            int d0 = k - qg, d1 = k + 1 - qg;
            if (d0 > -64 && d0 < 64) {
                float sv = (s[nt][0] + prowg[d0 + 64]) * 0.125f + mk0;
                prowg[d0 + 64] = sv; s[nt][0] = sv;
            } else s[nt][0] = (s[nt][0] + (d0 <= -64 ? qr0g : qr128g)) * 0.125f + mk0;
            if (d1 > -64 && d1 < 64) {
                float sv = (s[nt][1] + prowg[d1 + 64]) * 0.125f + mk1;
                prowg[d1 + 64] = sv; s[nt][1] = sv;
            } else s[nt][1] = (s[nt][1] + (d1 <= -64 ? qr0g : qr128g)) * 0.125f + mk1;
            int e0 = k - qh2, e1 = k + 1 - qh2;
            if (e0 > -64 && e0 < 64) {
                float sv = (s[nt][2] + prowh[e0 + 64]) * 0.125f + mk0;
                prowh[e0 + 64] = sv; s[nt][2] = sv;
            } else s[nt][2] = (s[nt][2] + (e0 <= -64 ? qr0h : qr128h)) * 0.125f + mk0;
            if (e1 > -64 && e1 < 64) {
                float sv = (s[nt][3] + prowh[e1 + 64]) * 0.125f + mk1;
                prowh[e1 + 64] = sv; s[nt][3] = sv;
            } else s[nt][3] = (s[nt][3] + (e1 <= -64 ? qr0h : qr128h)) * 0.125f + mk1;
        }

        float tg = -1e30f, th = -1e30f;
        #pragma unroll
        for (int nt = 0; nt < 8; nt++) {
            tg = fmaxf(tg, fmaxf(s[nt][0], s[nt][1]));
            th = fmaxf(th, fmaxf(s[nt][2], s[nt][3]));
        }
        tg = quadmax(tg); th = quadmax(th);
        float mng = fmaxf(m_g, tg), mnh = fmaxf(m_h, th);
        float scg = __expf(m_g - mng), sch = __expf(m_h - mnh);
        if (scg < 1.0f) {
            #pragma unroll
            for (int nt = 0; nt < 8; nt++) { acc[nt][0] *= scg; acc[nt][1] *= scg; }
            l_g *= scg; lo_g *= scg; hi_g *= scg;
        }
        if (sch < 1.0f) {
            #pragma unroll
            for (int nt = 0; nt < 8; nt++) { acc[nt][2] *= sch; acc[nt][3] *= sch; }
            l_h *= sch; lo_h *= sch; hi_h *= sch;
        }
        m_g = mng; m_h = mnh;

        unsigned phi[4][4], plo[4][4];
        #pragma unroll
        for (int nt = 0; nt < 8; nt++) {
            int k = kt0 + nt * 8 + tq;
            float p0 = __expf(s[nt][0] - m_g), p1 = __expf(s[nt][1] - m_g);
            float p2 = __expf(s[nt][2] - m_h), p3 = __expf(s[nt][3] - m_h);
            l_g += p0 + p1; l_h += p2 + p3;
            int d0 = k - qg, d1 = k + 1 - qg;
            if (d0 <= -64) lo_g += p0; else if (d0 >= 64) hi_g += p0;
            if (d1 <= -64) lo_g += p1; else if (d1 >= 64) hi_g += p1;
            int e0 = k - qh2, e1 = k + 1 - qh2;
            if (e0 <= -64) lo_h += p2; else if (e0 >= 64) hi_h += p2;
            if (e1 <= -64) lo_h += p3; else if (e1 >= 64) hi_h += p3;
            int kb = nt >> 1;
            if ((nt & 1) == 0) {
                phi[kb][0] = pack2h(p0, p1); phi[kb][1] = pack2h(p2, p3);
                plo[kb][0] = pack2l(p0, p1); plo[kb][1] = pack2l(p2, p3);
            } else {
                phi[kb][2] = pack2h(p0, p1); phi[kb][3] = pack2h(p2, p3);
                plo[kb][2] = pack2l(p0, p1); plo[kb][3] = pack2l(p2, p3);
            }
        }

        #pragma unroll
        for (int kb = 0; kb < 4; kb++) {
            int kk = kb * 16;
            #pragma unroll
            for (int ntp = 0; ntp < 4; ntp++) {
                int bb = (ntp * 16 + brow) * SST2 + kk + bcol8;
                unsigned vh[4], vl[4];
                ldsm4(vh, sVhi + bb);
                ldsm4(vl, sVlo + bb);
                mma_bf16(acc[2 * ntp],     phi[kb], vh[0], vh[1]);
                mma_bf16(acc[2 * ntp],     phi[kb], vl[0], vl[1]);
                mma_bf16(acc[2 * ntp],     plo[kb], vh[0], vh[1]);
                mma_bf16(acc[2 * ntp + 1], phi[kb], vh[2], vh[3]);
                mma_bf16(acc[2 * ntp + 1], phi[kb], vl[2], vl[3]);
                mma_bf16(acc[2 * ntp + 1], plo[kb], vh[2], vh[3]);
            }
        }
        __syncthreads();
    }

    l_g = quadsum(l_g); l_h = quadsum(l_h);
    lo_g = quadsum(lo_g); lo_h = quadsum(lo_h);
    hi_g = quadsum(hi_g); hi_h = quadsum(hi_h);
    if ((lane & 3) == 0) {
        prowg[0] = lo_g; prowg[128] = hi_g;
        prowh[0] = lo_h; prowh[128] = hi_h;
    }
    {
        int c0 = (lane & 3) * 33; if (c0 == 0) c0 = 1;
        int c1 = (lane & 3) * 33 + 33; if (c1 > 128) c1 = 128;
        for (int c = c0; c < c1; c++) {
            int kg = qg + c - 64;
            int kh2 = qh2 + c - 64;
            prowg[c] = (kg >= 0 && kg < SEQ) ? __expf(prowg[c] - m_g) : 0.0f;
            prowh[c] = (kh2 >= 0 && kh2 < SEQ) ? __expf(prowh[c] - m_h) : 0.0f;
        }
    }
    __syncthreads();

    float* tabS = (float*)(dsm + 2 * FA_QAS);
    for (int r0 = 0; r0 < VOCAB; r0 += 16) {
        __syncthreads();
        {
            int rr = t >> 4, cc = (t & 15) * 4;
            int r = r0 + rr;
            float4 tv = (r < VOCAB) ? *(const float4*)&g_tab[r * 64 + cc]
                                    : make_float4(0.f, 0.f, 0.f, 0.f);
            *(float4*)&tabS[rr * 68 + cc] = tv;
        }
        __syncthreads();
        #pragma unroll
        for (int rc = 0; rc < 16; rc++) {
            int rr2 = r0 + rc; if (rr2 > 128) rr2 = 128;
            float pg = prowg[rr2];
            float ph = prowh[rr2];
            #pragma unroll
            for (int nt = 0; nt < 8; nt++) {
                int d = nt * 8 + tq;
                float t0 = tabS[rc * 68 + d], t1 = tabS[rc * 68 + d + 1];
                acc[nt][0] += pg * t0; acc[nt][1] += pg * t1;
                acc[nt][2] += ph * t0; acc[nt][3] += ph * t1;
            }
        }
    }

    float ig = 1.0f / l_g, ih = 1.0f / l_h;
    #pragma unroll
    for (int nt = 0; nt < 8; nt++) {
        int d = nt * 8 + tq;
        *(float2*)(out + ((size_t)(b * SEQ + qg)) * HID + h * 64 + d) =
            make_float2(acc[nt][0] * ig, acc[nt][1] * ig);
        *(float2*)(out + ((size_t)(b * SEQ + qh2)) * HID + h * 64 + d) =
            make_float2(acc[nt][2] * ih, acc[nt][3] * ih);
    }
}

// ---------------- launcher ----------------
extern "C" void kernel_launch(void* const* d_in, const int* in_sizes, int n_in,
                              void* d_out, int out_size) {
    const float* hs   = (const float*)d_in[0];
    const float* mask = (const float*)d_in[1];
    const float* Wq   = (const float*)d_in[2];
    const float* bq   = (const float*)d_in[3];
    const float* Wk   = (const float*)d_in[4];
    const float* bk   = (const float*)d_in[5];
    const float* Wv   = (const float*)d_in[6];
    const float* bv   = (const float*)d_in[7];
    float* out = (float*)d_out;

    cudaFuncSetAttribute(qkv_mma_kernel,    cudaFuncAttributeMaxDynamicSharedMemorySize, QKV_SMEM);
    cudaFuncSetAttribute(attn_fused_kernel, cudaFuncAttributeMaxDynamicSharedMemorySize, FA_SMEM);

    init_tab_kernel<<<(TABP * 32 + 127) / 128, 128>>>();
    cvt_hs_kernel<<<(BATCH * SEQ * HID / 4 + 255) / 256, 256>>>(hs);
    cvt_w_kernel<<<(3 * HID * HID / 4 + 255) / 256, 256>>>(Wq, Wk, Wv);
    qkv_mma_kernel<<<dim3(HID / 128, (BATCH * SEQ) / 128, 3), 256, QKV_SMEM>>>(bq, bk, bv);
    attn_fused_kernel<<<dim3(SEQ / 128, BH), 256, FA_SMEM>>>(mask, out);
}

// round 15
// speedup vs baseline: 3.5241x; 1.0197x over previous
#include <cuda_runtime.h>
#include <cuda_bf16.h>
#include <cstdint>

#define BATCH 2
#define SEQ   1024
#define HID   1024
#define NHEAD 16
#define HDIM  64
#define BH    (BATCH*NHEAD)      // 32
#define VOCAB 129                // 2*64+1
#define TABP  144                // tab rows padded for MMA
#define SSTR  40                 // bf16 smem stride (BK=32 tiles): conflict-free
#define SST2  72                 // bf16 smem stride (64-col tiles): conflict-free

// ---------------- scratch ----------------
__device__ __align__(16) float g_tab[VOCAB * HDIM];
__device__ __align__(16) __nv_bfloat16 g_tab_hi[TABP * HDIM];
__device__ __align__(16) __nv_bfloat16 g_tab_lo[TABP * HDIM];

__device__ __align__(16) __nv_bfloat16 g_hs_hi[BATCH * SEQ * HID];
__device__ __align__(16) __nv_bfloat16 g_hs_lo[BATCH * SEQ * HID];
__device__ __align__(16) __nv_bfloat16 g_w_hi[3 * HID * HID];
__device__ __align__(16) __nv_bfloat16 g_w_lo[3 * HID * HID];
__device__ __align__(16) __nv_bfloat16 g_qh[BH * SEQ * HDIM];
__device__ __align__(16) __nv_bfloat16 g_ql[BH * SEQ * HDIM];
__device__ __align__(16) __nv_bfloat16 g_kh[BH * SEQ * HDIM];
__device__ __align__(16) __nv_bfloat16 g_kl[BH * SEQ * HDIM];
__device__ __align__(16) __nv_bfloat16 g_vth[BH * HDIM * SEQ];   // V^T [bh][d][s]
__device__ __align__(16) __nv_bfloat16 g_vtl[BH * HDIM * SEQ];

// ---------------- helpers ----------------
__device__ __forceinline__ void cp_async16(void* dst, const void* src) {
    unsigned int d = (unsigned int)__cvta_generic_to_shared(dst);
    asm volatile("cp.async.cg.shared.global [%0], [%1], 16;" :: "r"(d), "l"(src));
}
__device__ __forceinline__ void cp_commit() { asm volatile("cp.async.commit_group;"); }
__device__ __forceinline__ void cp_wait0()  { asm volatile("cp.async.wait_group 0;"); }
__device__ __forceinline__ void cp_wait1()  { asm volatile("cp.async.wait_group 1;"); }

__device__ __forceinline__ void ldsm4(unsigned* r, const void* p) {
    unsigned a = (unsigned)__cvta_generic_to_shared(p);
    asm volatile("ldmatrix.sync.aligned.m8n8.x4.shared.b16 {%0,%1,%2,%3}, [%4];"
                 : "=r"(r[0]), "=r"(r[1]), "=r"(r[2]), "=r"(r[3]) : "r"(a));
}

__device__ __forceinline__ void split_bf16(float v, __nv_bfloat16& hi, __nv_bfloat16& lo) {
    hi = __float2bfloat16_rn(v);
    lo = __float2bfloat16_rn(v - __bfloat162float(hi));
}
__device__ __forceinline__ unsigned pack2h(float a, float b) {
    __nv_bfloat162 p(__float2bfloat16_rn(a), __float2bfloat16_rn(b));
    return *(unsigned*)&p;
}
__device__ __forceinline__ unsigned pack2l(float a, float b) {
    float ra = a - __bfloat162float(__float2bfloat16_rn(a));
    float rb = b - __bfloat162float(__float2bfloat16_rn(b));
    __nv_bfloat162 p(__float2bfloat16_rn(ra), __float2bfloat16_rn(rb));
    return *(unsigned*)&p;
}
__device__ __forceinline__ float quadmax(float v) {
    v = fmaxf(v, __shfl_xor_sync(0xffffffffu, v, 1));
    v = fmaxf(v, __shfl_xor_sync(0xffffffffu, v, 2));
    return v;
}
__device__ __forceinline__ float quadsum(float v) {
    v += __shfl_xor_sync(0xffffffffu, v, 1);
    v += __shfl_xor_sync(0xffffffffu, v, 2);
    return v;
}
__device__ __forceinline__ void mma_bf16(float* c, const unsigned int* A,
                                         unsigned int b0, unsigned int b1) {
    asm volatile("mma.sync.aligned.m16n8k16.row.col.f32.bf16.bf16.f32 "
        "{%0,%1,%2,%3}, {%4,%5,%6,%7}, {%8,%9}, {%0,%1,%2,%3};"
        : "+f"(c[0]), "+f"(c[1]), "+f"(c[2]), "+f"(c[3])
        : "r"(A[0]), "r"(A[1]), "r"(A[2]), "r"(A[3]), "r"(b0), "r"(b1));
}

// ---------------- merged prep: tab init + hs/w split conversion ----------------
#define HS_BLKS 2048              // (BATCH*SEQ*HID/4)/256
#define W_BLKS  3072              // (3*HID*HID/4)/256
#define TAB_BLKS 18               // ceil(TABP*32/256)

__global__ __launch_bounds__(256) void prep_kernel(
    const float* __restrict__ hs,
    const float* __restrict__ Wq, const float* __restrict__ Wk, const float* __restrict__ Wv)
{
    int blk = blockIdx.x;
    int t = threadIdx.x;
    if (blk < HS_BLKS) {
        int i = (blk * 256 + t) * 4;
        float4 v = *(const float4*)(hs + i);
        __nv_bfloat16 h, l;
        split_bf16(v.x, h, l); g_hs_hi[i + 0] = h; g_hs_lo[i + 0] = l;
        split_bf16(v.y, h, l); g_hs_hi[i + 1] = h; g_hs_lo[i + 1] = l;
        split_bf16(v.z, h, l); g_hs_hi[i + 2] = h; g_hs_lo[i + 2] = l;
        split_bf16(v.w, h, l); g_hs_hi[i + 3] = h; g_hs_lo[i + 3] = l;
    } else if (blk < HS_BLKS + W_BLKS) {
        int i = ((blk - HS_BLKS) * 256 + t) * 4;
        int z = i / (HID * HID), r = i - z * (HID * HID);
        const float* W = (z == 0) ? Wq : (z == 1 ? Wk : Wv);
        float4 v = *(const float4*)(W + r);
        __nv_bfloat16 h, l;
        split_bf16(v.x, h, l); g_w_hi[i + 0] = h; g_w_lo[i + 0] = l;
        split_bf16(v.y, h, l); g_w_hi[i + 1] = h; g_w_lo[i + 1] = l;
        split_bf16(v.z, h, l); g_w_hi[i + 2] = h; g_w_lo[i + 2] = l;
        split_bf16(v.w, h, l); g_w_hi[i + 3] = h; g_w_lo[i + 3] = l;
    } else {
        int idx = (blk - HS_BLKS - W_BLKS) * 256 + t;
        if (idx >= TABP * 32) return;
        int p = idx >> 5, i = idx & 31;
        if (p < VOCAB) {
            float div = expf((float)(2 * i) * (-9.210340371976184f / 64.0f));
            float ang = (float)p * div;
            float sv = sinf(ang), cv = cosf(ang);
            g_tab[p * 64 + 2 * i]     = sv;
            g_tab[p * 64 + 2 * i + 1] = cv;
            __nv_bfloat16 h, l;
            split_bf16(sv, h, l); g_tab_hi[p * 64 + 2 * i] = h;     g_tab_lo[p * 64 + 2 * i] = l;
            split_bf16(cv, h, l); g_tab_hi[p * 64 + 2 * i + 1] = h; g_tab_lo[p * 64 + 2 * i + 1] = l;
        } else {
            g_tab_hi[p * 64 + 2 * i] = __float2bfloat16_rn(0.f);
            g_tab_hi[p * 64 + 2 * i + 1] = __float2bfloat16_rn(0.f);
            g_tab_lo[p * 64 + 2 * i] = __float2bfloat16_rn(0.f);
            g_tab_lo[p * 64 + 2 * i + 1] = __float2bfloat16_rn(0.f);
        }
    }
}

// ---------------- phase 1: QKV projection, BK=32 2-stage, 2 CTAs/SM ----------------
#define QKV_AS    (128 * SSTR)        // 5120 elems per array
#define QKV_STAGE (4 * QKV_AS)        // 20480 elems
#define QKV_SMEM  (2 * QKV_STAGE * 2) // 81920 B

__global__ __launch_bounds__(256, 2) void qkv_mma_kernel(
    const float* __restrict__ bq, const float* __restrict__ bk, const float* __restrict__ bv)
{
    extern __shared__ __align__(16) __nv_bfloat16 dsm[];
    int z = blockIdx.z;
    const float* bias = (z == 0) ? bq : (z == 1 ? bk : bv);
    const __nv_bfloat16* gWhi = g_w_hi + (size_t)z * HID * HID;
    const __nv_bfloat16* gWlo = g_w_lo + (size_t)z * HID * HID;

    int m0 = blockIdx.y * 128, n0 = blockIdx.x * 128;
    int t = threadIdx.x;
    int lane = t & 31, warp = t >> 5;
    int wy = warp >> 2, wx = warp & 3;
    int g = lane >> 2, tq = (lane & 3) * 2;
    int arow = lane & 15, acol8 = (lane >> 4) * 8;
    int brow = ((lane >> 4) << 3) + (lane & 7), bcol8 = ((lane >> 3) & 1) * 8;

    float acc[4][4][4] = {};

    auto load_stage = [&](int stg, int k0) {
        __nv_bfloat16* base = dsm + stg * QKV_STAGE;
        #pragma unroll
        for (int u = 0; u < 2; u++) {
            int idx = t + 256 * u;
            int r = idx >> 2, ce = (idx & 3) * 8;
            size_t ga = (size_t)(m0 + r) * HID + k0 + ce;
            size_t gb = (size_t)(n0 + r) * HID + k0 + ce;
            int so = r * SSTR + ce;
            cp_async16(base + 0 * QKV_AS + so, g_hs_hi + ga);
            cp_async16(base + 1 * QKV_AS + so, g_hs_lo + ga);
            cp_async16(base + 2 * QKV_AS + so, gWhi + gb);
            cp_async16(base + 3 * QKV_AS + so, gWlo + gb);
        }
    };

    load_stage(0, 0);
    cp_commit();

    for (int k0 = 0; k0 < HID; k0 += 32) {
        int stg = (k0 >> 5) & 1;
        if (k0 + 32 < HID) { load_stage(stg ^ 1, k0 + 32); cp_commit(); cp_wait1(); }
        else               { cp_wait0(); }
        __syncthreads();
        const __nv_bfloat16* sAhi = dsm + stg * QKV_STAGE;
        const __nv_bfloat16* sAlo = sAhi + QKV_AS;
        const __nv_bfloat16* sBhi = sAlo + QKV_AS;
        const __nv_bfloat16* sBlo = sBhi + QKV_AS;

        #pragma unroll
        for (int kk = 0; kk < 32; kk += 16) {
            unsigned ahi[4][4], alo[4][4];
            #pragma unroll
            for (int mt = 0; mt < 4; mt++) {
                int ab = (wy * 64 + mt * 16 + arow) * SSTR + kk + acol8;
                ldsm4(ahi[mt], sAhi + ab);
                ldsm4(alo[mt], sAlo + ab);
            }
            #pragma unroll
            for (int ntp = 0; ntp < 2; ntp++) {
                int bb = (wx * 32 + ntp * 16 + brow) * SSTR + kk + bcol8;
                unsigned bh[4], bl[4];
                ldsm4(bh, sBhi + bb);
                ldsm4(bl, sBlo + bb);
                #pragma unroll
                for (int mt = 0; mt < 4; mt++) {
                    mma_bf16(acc[mt][2 * ntp],     ahi[mt], bh[0], bh[1]);
                    mma_bf16(acc[mt][2 * ntp],     ahi[mt], bl[0], bl[1]);
                    mma_bf16(acc[mt][2 * ntp],     alo[mt], bh[0], bh[1]);
                    mma_bf16(acc[mt][2 * ntp + 1], ahi[mt], bh[2], bh[3]);
                    mma_bf16(acc[mt][2 * ntp + 1], ahi[mt], bl[2], bl[3]);
                    mma_bf16(acc[mt][2 * ntp + 1], alo[mt], bh[2], bh[3]);
                }
            }
        }
        __syncthreads();
    }

    #pragma unroll
    for (int nt = 0; nt < 4; nt++) {
        int n = n0 + wx * 32 + nt * 8 + tq;
        float2 b2 = *(const float2*)&bias[n];
        int h = n >> 6, d = n & 63;
        #pragma unroll
        for (int mt = 0; mt < 4; mt++) {
            int m = m0 + wy * 64 + mt * 16 + g;
            int b = m >> 10, s = m & (SEQ - 1);
            int bh = b * NHEAD + h;
            float v0 = acc[mt][nt][0] + b2.x, v1 = acc[mt][nt][1] + b2.y;
            float v2 = acc[mt][nt][2] + b2.x, v3 = acc[mt][nt][3] + b2.y;
            __nv_bfloat16 h0, l0, h1, l1, h2, l2, h3, l3;
            split_bf16(v0, h0, l0); split_bf16(v1, h1, l1);
            split_bf16(v2, h2, l2); split_bf16(v3, h3, l3);
            if (z < 2) {
                __nv_bfloat16* ah = (z == 0) ? g_qh : g_kh;
                __nv_bfloat16* al = (z == 0) ? g_ql : g_kl;
                size_t o0 = ((size_t)bh * SEQ + s) * HDIM + d;
                size_t o1 = o0 + 8 * HDIM;
                *(__nv_bfloat162*)(ah + o0) = __nv_bfloat162(h0, h1);
                *(__nv_bfloat162*)(al + o0) = __nv_bfloat162(l0, l1);
                *(__nv_bfloat162*)(ah + o1) = __nv_bfloat162(h2, h3);
                *(__nv_bfloat162*)(al + o1) = __nv_bfloat162(l2, l3);
            } else {
                size_t base = ((size_t)bh * HDIM + d) * SEQ + s;
                g_vth[base] = h0;           g_vtl[base] = l0;
                g_vth[base + SEQ] = h1;     g_vtl[base + SEQ] = l1;
                g_vth[base + 8] = h2;       g_vtl[base + 8] = l2;
                g_vth[base + SEQ + 8] = h3; g_vtl[base + SEQ + 8] = l3;
            }
        }
    }
}

// ---------------- phase 2-4 fused: flash attention + rel-pos ----------------
#define FA_QAS   9216                  // 128*72
#define FA_KAS   4608                  // 64*72
#define FA_STAGE (4 * FA_KAS)
#define FA_PSOFF (2 * FA_QAS + 2 * FA_STAGE)
#define FA_SMEM  (FA_PSOFF * 2 + 128 * 132 * 4 + 4096)

__global__ __launch_bounds__(256) void attn_fused_kernel(
    const float* __restrict__ mask, float* __restrict__ out)
{
    extern __shared__ __align__(16) __nv_bfloat16 dsm[];
    const int bh = blockIdx.y, b = bh >> 4, h = bh & 15;
    const int q0 = blockIdx.x * 128;
    const int t = threadIdx.x, lane = t & 31, w = t >> 5;
    const int g = lane >> 2, tq = (lane & 3) * 2;
    const int arow = lane & 15, acol8 = (lane >> 4) * 8;
    const int brow = ((lane >> 4) << 3) + (lane & 7), bcol8 = ((lane >> 3) & 1) * 8;

    __nv_bfloat16* sQhi = dsm;
    __nv_bfloat16* sQlo = dsm + FA_QAS;
    float* psm = (float*)(dsm + FA_PSOFF);
    float* smask = psm + 128 * 132;

    cp_async16(smask + t * 4, mask + (size_t)b * SEQ + t * 4);

    #pragma unroll
    for (int u = 0; u < 4; u++) {
        int idx = t + 256 * u;
        int r = idx >> 3, ce = (idx & 7) * 8;
        size_t ga = ((size_t)bh * SEQ + q0 + r) * HDIM + ce;
        int so = r * SST2 + ce;
        cp_async16(sQhi + so, g_qh + ga);
        cp_async16(sQlo + so, g_ql + ga);
    }
    __nv_bfloat16* sTabHi = dsm + 2 * FA_QAS;
    __nv_bfloat16* sTabLo = sTabHi + TABP * SST2;
    #pragma unroll
    for (int u = 0; u < 5; u++) {
        int idx = t + 256 * u;
        if (idx < TABP * 8) {
            int r = idx >> 3, ce = (idx & 7) * 8;
            cp_async16(sTabHi + r * SST2 + ce, g_tab_hi + r * 64 + ce);
            cp_async16(sTabLo + r * SST2 + ce, g_tab_lo + r * 64 + ce);
        }
    }
    cp_commit();
    cp_wait0();
    __syncthreads();

    float* prowg = psm + (w * 16 + g) * 132;
    float* prowh = prowg + 8 * 132;

    // ---- hoist Q fragments (loop-invariant across qrel + all kt) ----
    unsigned qfh[4][4], qfl[4][4];
    #pragma unroll
    for (int kk4 = 0; kk4 < 4; kk4++) {
        int ab = (w * 16 + arow) * SST2 + kk4 * 16 + acol8;
        ldsm4(qfh[kk4], sQhi + ab);
        ldsm4(qfl[kk4], sQlo + ab);
    }

    // ---- qrel = Q @ tab^T (split MMA) -> band ----
    #pragma unroll
    for (int ntp = 0; ntp < 9; ntp++) {
        float d0[4] = {}, d1[4] = {};
        #pragma unroll
        for (int kk4 = 0; kk4 < 4; kk4++) {
            int bb = (ntp * 16 + brow) * SST2 + kk4 * 16 + bcol8;
            unsigned th4[4], tl4[4];
            ldsm4(th4, sTabHi + bb);
            ldsm4(tl4, sTabLo + bb);
            mma_bf16(d0, qfh[kk4], th4[0], th4[1]);
            mma_bf16(d0, qfh[kk4], tl4[0], tl4[1]);
            mma_bf16(d0, qfl[kk4], th4[0], th4[1]);
            mma_bf16(d1, qfh[kk4], th4[2], th4[3]);
            mma_bf16(d1, qfh[kk4], tl4[2], tl4[3]);
            mma_bf16(d1, qfl[kk4], th4[2], th4[3]);
        }
        int c0 = ntp * 16 + tq, c1 = ntp * 16 + 8 + tq;
        if (c0 < 132) {
            prowg[c0] = d0[0]; prowg[c0 + 1] = d0[1];
            prowh[c0] = d0[2]; prowh[c0 + 1] = d0[3];
        }
        if (c1 < 132) {
            prowg[c1] = d1[0]; prowg[c1 + 1] = d1[1];
            prowh[c1] = d1[2]; prowh[c1 + 1] = d1[3];
        }
    }
    __syncthreads();

    const int qg = q0 + w * 16 + g;
    const int qh2 = qg + 8;
    const float qr0g = prowg[0], qr128g = prowg[128];
    const float qr0h = prowh[0], qr128h = prowh[128];

    auto load_kv = [&](int stg, int kt0) {
        __nv_bfloat16* base = dsm + 2 * FA_QAS + stg * FA_STAGE;
        #pragma unroll
        for (int u = 0; u < 2; u++) {
            int idx = t + 256 * u;
            int r = idx >> 3, ce = (idx & 7) * 8;
            int so = r * SST2 + ce;
            size_t gk = ((size_t)bh * SEQ + kt0 + r) * HDIM + ce;
            size_t gv = ((size_t)bh * HDIM + r) * SEQ + kt0 + ce;
            cp_async16(base + 0 * FA_KAS + so, g_kh + gk);
            cp_async16(base + 1 * FA_KAS + so, g_kl + gk);
            cp_async16(base + 2 * FA_KAS + so, g_vth + gv);
            cp_async16(base + 3 * FA_KAS + so, g_vtl + gv);
        }
    };
    load_kv(0, 0);
    cp_commit();

    float acc[8][4] = {};
    float m_g = -1e30f, m_h = -1e30f;
    float l_g = 0.f, l_h = 0.f, lo_g = 0.f, lo_h = 0.f, hi_g = 0.f, hi_h = 0.f;

    for (int kt = 0; kt < 16; kt++) {
        int kt0 = kt * 64;
        if (kt < 15) { load_kv((kt ^ 1) & 1, kt0 + 64); cp_commit(); cp_wait1(); }
        else         { cp_wait0(); }
        __syncthreads();
        const __nv_bfloat16* stage = dsm + 2 * FA_QAS + (kt & 1) * FA_STAGE;
        const __nv_bfloat16* sKhi = stage;
        const __nv_bfloat16* sKlo = stage + FA_KAS;
        const __nv_bfloat16* sVhi = stage + 2 * FA_KAS;
        const __nv_bfloat16* sVlo = stage + 3 * FA_KAS;

        float s[8][4] = {};
        #pragma unroll
        for (int kk4 = 0; kk4 < 4; kk4++) {
            #pragma unroll
            for (int ntp = 0; ntp < 4; ntp++) {
                int bb = (ntp * 16 + brow) * SST2 + kk4 * 16 + bcol8;
                unsigned kh[4], kl[4];
                ldsm4(kh, sKhi + bb);
                ldsm4(kl, sKlo + bb);
                mma_bf16(s[2 * ntp],     qfh[kk4], kh[0], kh[1]);
                mma_bf16(s[2 * ntp],     qfh[kk4], kl[0], kl[1]);
                mma_bf16(s[2 * ntp],     qfl[kk4], kh[0], kh[1]);
                mma_bf16(s[2 * ntp + 1], qfh[kk4], kh[2], kh[3]);
                mma_bf16(s[2 * ntp + 1], qfh[kk4], kl[2], kl[3]);
                mma_bf16(s[2 * ntp + 1], qfl[kk4], kh[2], kh[3]);
            }
        }

        #pragma unroll
        for (int nt = 0; nt < 8; nt++) {
            int k = kt0 + nt * 8 + tq;
            float mk0 = smask[k], mk1 = smask[k + 1];
            int d0 = k - qg, d1 = k + 1 - qg;
            if (d0 > -64 && d0 < 64) {
                float sv = (s[nt][0] + prowg[d0 + 64]) * 0.125f + mk0;
                prowg[d0 + 64] = sv; s[nt][0] = sv;
            } else s[nt][0] = (s[nt][0] + (d0 <= -64 ? qr0g : qr128g)) * 0.125f + mk0;
            if (d1 > -64 && d1 < 64) {
                float sv = (s[nt][1] + prowg[d1 + 64]) * 0.125f + mk1;
                prowg[d1 + 64] = sv; s[nt][1] = sv;
            } else s[nt][1] = (s[nt][1] + (d1 <= -64 ? qr0g : qr128g)) * 0.125f + mk1;
            int e0 = k - qh2, e1 = k + 1 - qh2;
            if (e0 > -64 && e0 < 64) {
                float sv = (s[nt][2] + prowh[e0 + 64]) * 0.125f + mk0;
                prowh[e0 + 64] = sv; s[nt][2] = sv;
            } else s[nt][2] = (s[nt][2] + (e0 <= -64 ? qr0h : qr128h)) * 0.125f + mk0;
            if (e1 > -64 && e1 < 64) {
                float sv = (s[nt][3] + prowh[e1 + 64]) * 0.125f + mk1;
                prowh[e1 + 64] = sv; s[nt][3] = sv;
            } else s[nt][3] = (s[nt][3] + (e1 <= -64 ? qr0h : qr128h)) * 0.125f + mk1;
        }

        float tg = -1e30f, th = -1e30f;
        #pragma unroll
        for (int nt = 0; nt < 8; nt++) {
            tg = fmaxf(tg, fmaxf(s[nt][0], s[nt][1]));
            th = fmaxf(th, fmaxf(s[nt][2], s[nt][3]));
        }
        tg = quadmax(tg); th = quadmax(th);
        float mng = fmaxf(m_g, tg), mnh = fmaxf(m_h, th);
        float scg = __expf(m_g - mng), sch = __expf(m_h - mnh);
        if (scg < 1.0f) {
            #pragma unroll
            for (int nt = 0; nt < 8; nt++) { acc[nt][0] *= scg; acc[nt][1] *= scg; }
            l_g *= scg; lo_g *= scg; hi_g *= scg;
        }
        if (sch < 1.0f) {
            #pragma unroll
            for (int nt = 0; nt < 8; nt++) { acc[nt][2] *= sch; acc[nt][3] *= sch; }
            l_h *= sch; lo_h *= sch; hi_h *= sch;
        }
        m_g = mng; m_h = mnh;

        unsigned phi[4][4], plo[4][4];
        #pragma unroll
        for (int nt = 0; nt < 8; nt++) {
            int k = kt0 + nt * 8 + tq;
            float p0 = __expf(s[nt][0] - m_g), p1 = __expf(s[nt][1] - m_g);
            float p2 = __expf(s[nt][2] - m_h), p3 = __expf(s[nt][3] - m_h);
            l_g += p0 + p1; l_h += p2 + p3;
            int d0 = k - qg, d1 = k + 1 - qg;
            if (d0 <= -64) lo_g += p0; else if (d0 >= 64) hi_g += p0;
            if (d1 <= -64) lo_g += p1; else if (d1 >= 64) hi_g += p1;
            int e0 = k - qh2, e1 = k + 1 - qh2;
            if (e0 <= -64) lo_h += p2; else if (e0 >= 64) hi_h += p2;
            if (e1 <= -64) lo_h += p3; else if (e1 >= 64) hi_h += p3;
            int kb = nt >> 1;
            if ((nt & 1) == 0) {
                phi[kb][0] = pack2h(p0, p1); phi[kb][1] = pack2h(p2, p3);
                plo[kb][0] = pack2l(p0, p1); plo[kb][1] = pack2l(p2, p3);
            } else {
                phi[kb][2] = pack2h(p0, p1); phi[kb][3] = pack2h(p2, p3);
                plo[kb][2] = pack2l(p0, p1); plo[kb][3] = pack2l(p2, p3);
            }
        }

        #pragma unroll
        for (int kb = 0; kb < 4; kb++) {
            int kk = kb * 16;
            #pragma unroll
            for (int ntp = 0; ntp < 4; ntp++) {
                int bb = (ntp * 16 + brow) * SST2 + kk + bcol8;
                unsigned vh[4], vl[4];
                ldsm4(vh, sVhi + bb);
                ldsm4(vl, sVlo + bb);
                mma_bf16(acc[2 * ntp],     phi[kb], vh[0], vh[1]);
                mma_bf16(acc[2 * ntp],     phi[kb], vl[0], vl[1]);
                mma_bf16(acc[2 * ntp],     plo[kb], vh[0], vh[1]);
                mma_bf16(acc[2 * ntp + 1], phi[kb], vh[2], vh[3]);
                mma_bf16(acc[2 * ntp + 1], phi[kb], vl[2], vl[3]);
                mma_bf16(acc[2 * ntp + 1], plo[kb], vh[2], vh[3]);
            }
        }
        __syncthreads();
    }

    l_g = quadsum(l_g); l_h = quadsum(l_h);
    lo_g = quadsum(lo_g); lo_h = quadsum(lo_h);
    hi_g = quadsum(hi_g); hi_h = quadsum(hi_h);
    if ((lane & 3) == 0) {
        prowg[0] = lo_g; prowg[128] = hi_g;
        prowh[0] = lo_h; prowh[128] = hi_h;
    }
    {
        int c0 = (lane & 3) * 33; if (c0 == 0) c0 = 1;
        int c1 = (lane & 3) * 33 + 33; if (c1 > 128) c1 = 128;
        for (int c = c0; c < c1; c++) {
            int kg = qg + c - 64;
            int kh2 = qh2 + c - 64;
            prowg[c] = (kg >= 0 && kg < SEQ) ? __expf(prowg[c] - m_g) : 0.0f;
            prowh[c] = (kh2 >= 0 && kh2 < SEQ) ? __expf(prowh[c] - m_h) : 0.0f;
        }
    }
    __syncthreads();

    float* tabS = (float*)(dsm + 2 * FA_QAS);
    for (int r0 = 0; r0 < VOCAB; r0 += 16) {
        __syncthreads();
        {
            int rr = t >> 4, cc = (t & 15) * 4;
            int r = r0 + rr;
            float4 tv = (r < VOCAB) ? *(const float4*)&g_tab[r * 64 + cc]
                                    : make_float4(0.f, 0.f, 0.f, 0.f);
            *(float4*)&tabS[rr * 68 + cc] = tv;
        }
        __syncthreads();
        #pragma unroll
        for (int rc = 0; rc < 16; rc++) {
            int rr2 = r0 + rc; if (rr2 > 128) rr2 = 128;
            float pg = prowg[rr2];
            float ph = prowh[rr2];
            #pragma unroll
            for (int nt = 0; nt < 8; nt++) {
                int d = nt * 8 + tq;
                float t0 = tabS[rc * 68 + d], t1 = tabS[rc * 68 + d + 1];
                acc[nt][0] += pg * t0; acc[nt][1] += pg * t1;
                acc[nt][2] += ph * t0; acc[nt][3] += ph * t1;
            }
        }
    }

    float ig = 1.0f / l_g, ih = 1.0f / l_h;
    #pragma unroll
    for (int nt = 0; nt < 8; nt++) {
        int d = nt * 8 + tq;
        *(float2*)(out + ((size_t)(b * SEQ + qg)) * HID + h * 64 + d) =
            make_float2(acc[nt][0] * ig, acc[nt][1] * ig);
        *(float2*)(out + ((size_t)(b * SEQ + qh2)) * HID + h * 64 + d) =
            make_float2(acc[nt][2] * ih, acc[nt][3] * ih);
    }
}

// ---------------- launcher ----------------
extern "C" void kernel_launch(void* const* d_in, const int* in_sizes, int n_in,
                              void* d_out, int out_size) {
    const float* hs   = (const float*)d_in[0];
    const float* mask = (const float*)d_in[1];
    const float* Wq   = (const float*)d_in[2];
    const float* bq   = (const float*)d_in[3];
    const float* Wk   = (const float*)d_in[4];
    const float* bk   = (const float*)d_in[5];
    const float* Wv   = (const float*)d_in[6];
    const float* bv   = (const float*)d_in[7];
    float* out = (float*)d_out;

    cudaFuncSetAttribute(qkv_mma_kernel,    cudaFuncAttributeMaxDynamicSharedMemorySize, QKV_SMEM);
    cudaFuncSetAttribute(attn_fused_kernel, cudaFuncAttributeMaxDynamicSharedMemorySize, FA_SMEM);

    prep_kernel<<<HS_BLKS + W_BLKS + TAB_BLKS, 256>>>(hs, Wq, Wk, Wv);
    qkv_mma_kernel<<<dim3(HID / 128, (BATCH * SEQ) / 128, 3), 256, QKV_SMEM>>>(bq, bk, bv);
    attn_fused_kernel<<<dim3(SEQ / 128, BH), 256, FA_SMEM>>>(mask, out);
}

// round 16
// speedup vs baseline: 4.0388x; 1.1461x over previous
#include <cuda_runtime.h>
#include <cuda_bf16.h>
#include <cuda_fp16.h>
#include <cstdint>

#define BATCH 2
#define SEQ   1024
#define HID   1024
#define NHEAD 16
#define HDIM  64
#define BH    (BATCH*NHEAD)      // 32
#define VOCAB 129                // 2*64+1
#define TABP  144                // tab rows padded for MMA
#define SSTR  40                 // half smem stride (BK=32 tiles): conflict-free
#define SST2  72                 // bf16 smem stride (64-col tiles): conflict-free

// ---------------- scratch ----------------
__device__ __align__(16) float g_tab[VOCAB * HDIM];
__device__ __align__(16) __nv_bfloat16 g_tab_hi[TABP * HDIM];
__device__ __align__(16) __nv_bfloat16 g_tab_lo[TABP * HDIM];

__device__ __align__(16) __half g_hs_hi[BATCH * SEQ * HID];
__device__ __align__(16) __half g_hs_lo[BATCH * SEQ * HID];
__device__ __align__(16) __half g_w_hi[3 * HID * HID];        // W truncated to fp16
__device__ __align__(16) __nv_bfloat16 g_qh[BH * SEQ * HDIM];
__device__ __align__(16) __nv_bfloat16 g_ql[BH * SEQ * HDIM];
__device__ __align__(16) __nv_bfloat16 g_kh[BH * SEQ * HDIM];
__device__ __align__(16) __nv_bfloat16 g_kl[BH * SEQ * HDIM];
__device__ __align__(16) __nv_bfloat16 g_vth[BH * HDIM * SEQ];   // V^T [bh][d][s]
__device__ __align__(16) __nv_bfloat16 g_vtl[BH * HDIM * SEQ];

// ---------------- helpers ----------------
__device__ __forceinline__ void cp_async16(void* dst, const void* src) {
    unsigned int d = (unsigned int)__cvta_generic_to_shared(dst);
    asm volatile("cp.async.cg.shared.global [%0], [%1], 16;" :: "r"(d), "l"(src));
}
__device__ __forceinline__ void cp_commit() { asm volatile("cp.async.commit_group;"); }
__device__ __forceinline__ void cp_wait0()  { asm volatile("cp.async.wait_group 0;"); }
__device__ __forceinline__ void cp_wait1()  { asm volatile("cp.async.wait_group 1;"); }

__device__ __forceinline__ void ldsm4(unsigned* r, const void* p) {
    unsigned a = (unsigned)__cvta_generic_to_shared(p);
    asm volatile("ldmatrix.sync.aligned.m8n8.x4.shared.b16 {%0,%1,%2,%3}, [%4];"
                 : "=r"(r[0]), "=r"(r[1]), "=r"(r[2]), "=r"(r[3]) : "r"(a));
}

__device__ __forceinline__ void split_bf16(float v, __nv_bfloat16& hi, __nv_bfloat16& lo) {
    hi = __float2bfloat16_rn(v);
    lo = __float2bfloat16_rn(v - __bfloat162float(hi));
}
__device__ __forceinline__ void split_f16(float v, __half& hi, __half& lo) {
    hi = __float2half_rn(v);
    lo = __float2half_rn(v - __half2float(hi));
}
__device__ __forceinline__ unsigned pack2h(float a, float b) {
    __nv_bfloat162 p(__float2bfloat16_rn(a), __float2bfloat16_rn(b));
    return *(unsigned*)&p;
}
__device__ __forceinline__ unsigned pack2l(float a, float b) {
    float ra = a - __bfloat162float(__float2bfloat16_rn(a));
    float rb = b - __bfloat162float(__float2bfloat16_rn(b));
    __nv_bfloat162 p(__float2bfloat16_rn(ra), __float2bfloat16_rn(rb));
    return *(unsigned*)&p;
}
__device__ __forceinline__ float quadmax(float v) {
    v = fmaxf(v, __shfl_xor_sync(0xffffffffu, v, 1));
    v = fmaxf(v, __shfl_xor_sync(0xffffffffu, v, 2));
    return v;
}
__device__ __forceinline__ float quadsum(float v) {
    v += __shfl_xor_sync(0xffffffffu, v, 1);
    v += __shfl_xor_sync(0xffffffffu, v, 2);
    return v;
}
__device__ __forceinline__ void mma_bf16(float* c, const unsigned int* A,
                                         unsigned int b0, unsigned int b1) {
    asm volatile("mma.sync.aligned.m16n8k16.row.col.f32.bf16.bf16.f32 "
        "{%0,%1,%2,%3}, {%4,%5,%6,%7}, {%8,%9}, {%0,%1,%2,%3};"
        : "+f"(c[0]), "+f"(c[1]), "+f"(c[2]), "+f"(c[3])
        : "r"(A[0]), "r"(A[1]), "r"(A[2]), "r"(A[3]), "r"(b0), "r"(b1));
}
__device__ __forceinline__ void mma_f16(float* c, const unsigned int* A,
                                        unsigned int b0, unsigned int b1) {
    asm volatile("mma.sync.aligned.m16n8k16.row.col.f32.f16.f16.f32 "
        "{%0,%1,%2,%3}, {%4,%5,%6,%7}, {%8,%9}, {%0,%1,%2,%3};"
        : "+f"(c[0]), "+f"(c[1]), "+f"(c[2]), "+f"(c[3])
        : "r"(A[0]), "r"(A[1]), "r"(A[2]), "r"(A[3]), "r"(b0), "r"(b1));
}

// ---------------- merged prep: tab init + hs/w conversion ----------------
#define HS_BLKS 2048              // (BATCH*SEQ*HID/4)/256
#define W_BLKS  3072              // (3*HID*HID/4)/256
#define TAB_BLKS 18               // ceil(TABP*32/256)

__global__ __launch_bounds__(256) void prep_kernel(
    const float* __restrict__ hs,
    const float* __restrict__ Wq, const float* __restrict__ Wk, const float* __restrict__ Wv)
{
    int blk = blockIdx.x;
    int t = threadIdx.x;
    if (blk < HS_BLKS) {
        int i = (blk * 256 + t) * 4;
        float4 v = *(const float4*)(hs + i);
        __half h, l;
        split_f16(v.x, h, l); g_hs_hi[i + 0] = h; g_hs_lo[i + 0] = l;
        split_f16(v.y, h, l); g_hs_hi[i + 1] = h; g_hs_lo[i + 1] = l;
        split_f16(v.z, h, l); g_hs_hi[i + 2] = h; g_hs_lo[i + 2] = l;
        split_f16(v.w, h, l); g_hs_hi[i + 3] = h; g_hs_lo[i + 3] = l;
    } else if (blk < HS_BLKS + W_BLKS) {
        int i = ((blk - HS_BLKS) * 256 + t) * 4;
        int z = i / (HID * HID), r = i - z * (HID * HID);
        const float* W = (z == 0) ? Wq : (z == 1 ? Wk : Wv);
        float4 v = *(const float4*)(W + r);
        g_w_hi[i + 0] = __float2half_rn(v.x);
        g_w_hi[i + 1] = __float2half_rn(v.y);
        g_w_hi[i + 2] = __float2half_rn(v.z);
        g_w_hi[i + 3] = __float2half_rn(v.w);
    } else {
        int idx = (blk - HS_BLKS - W_BLKS) * 256 + t;
        if (idx >= TABP * 32) return;
        int p = idx >> 5, i = idx & 31;
        if (p < VOCAB) {
            float div = expf((float)(2 * i) * (-9.210340371976184f / 64.0f));
            float ang = (float)p * div;
            float sv = sinf(ang), cv = cosf(ang);
            g_tab[p * 64 + 2 * i]     = sv;
            g_tab[p * 64 + 2 * i + 1] = cv;
            __nv_bfloat16 h, l;
            split_bf16(sv, h, l); g_tab_hi[p * 64 + 2 * i] = h;     g_tab_lo[p * 64 + 2 * i] = l;
            split_bf16(cv, h, l); g_tab_hi[p * 64 + 2 * i + 1] = h; g_tab_lo[p * 64 + 2 * i + 1] = l;
        } else {
            g_tab_hi[p * 64 + 2 * i] = __float2bfloat16_rn(0.f);
            g_tab_hi[p * 64 + 2 * i + 1] = __float2bfloat16_rn(0.f);
            g_tab_lo[p * 64 + 2 * i] = __float2bfloat16_rn(0.f);
            g_tab_lo[p * 64 + 2 * i + 1] = __float2bfloat16_rn(0.f);
        }
    }
}

// ---------------- phase 1: QKV projection, fp16 2-term, BK=32 2-stage, 2 CTAs/SM ----------------
#define QKV_AS    (128 * SSTR)        // 5120 elems per array
#define QKV_STAGE (3 * QKV_AS)        // 15360 elems (Ahi, Alo, Bhi)
#define QKV_SMEM  (2 * QKV_STAGE * 2) // 61440 B

__global__ __launch_bounds__(256, 2) void qkv_mma_kernel(
    const float* __restrict__ bq, const float* __restrict__ bk, const float* __restrict__ bv)
{
    extern __shared__ __align__(16) __half dsmh[];
    int z = blockIdx.z;
    const float* bias = (z == 0) ? bq : (z == 1 ? bk : bv);
    const __half* gWhi = g_w_hi + (size_t)z * HID * HID;

    int m0 = blockIdx.y * 128, n0 = blockIdx.x * 128;
    int t = threadIdx.x;
    int lane = t & 31, warp = t >> 5;
    int wy = warp >> 2, wx = warp & 3;
    int g = lane >> 2, tq = (lane & 3) * 2;
    int arow = lane & 15, acol8 = (lane >> 4) * 8;
    int brow = ((lane >> 4) << 3) + (lane & 7), bcol8 = ((lane >> 3) & 1) * 8;

    float acc[4][4][4] = {};

    auto load_stage = [&](int stg, int k0) {
        __half* base = dsmh + stg * QKV_STAGE;
        #pragma unroll
        for (int u = 0; u < 2; u++) {
            int idx = t + 256 * u;
            int r = idx >> 2, ce = (idx & 3) * 8;
            size_t ga = (size_t)(m0 + r) * HID + k0 + ce;
            size_t gb = (size_t)(n0 + r) * HID + k0 + ce;
            int so = r * SSTR + ce;
            cp_async16(base + 0 * QKV_AS + so, g_hs_hi + ga);
            cp_async16(base + 1 * QKV_AS + so, g_hs_lo + ga);
            cp_async16(base + 2 * QKV_AS + so, gWhi + gb);
        }
    };

    load_stage(0, 0);
    cp_commit();

    for (int k0 = 0; k0 < HID; k0 += 32) {
        int stg = (k0 >> 5) & 1;
        if (k0 + 32 < HID) { load_stage(stg ^ 1, k0 + 32); cp_commit(); cp_wait1(); }
        else               { cp_wait0(); }
        __syncthreads();
        const __half* sAhi = dsmh + stg * QKV_STAGE;
        const __half* sAlo = sAhi + QKV_AS;
        const __half* sBhi = sAlo + QKV_AS;

        #pragma unroll
        for (int kk = 0; kk < 32; kk += 16) {
            unsigned ahi[4][4], alo[4][4];
            #pragma unroll
            for (int mt = 0; mt < 4; mt++) {
                int ab = (wy * 64 + mt * 16 + arow) * SSTR + kk + acol8;
                ldsm4(ahi[mt], sAhi + ab);
                ldsm4(alo[mt], sAlo + ab);
            }
            #pragma unroll
            for (int ntp = 0; ntp < 2; ntp++) {
                int bb = (wx * 32 + ntp * 16 + brow) * SSTR + kk + bcol8;
                unsigned bh[4];
                ldsm4(bh, sBhi + bb);
                #pragma unroll
                for (int mt = 0; mt < 4; mt++) {
                    mma_f16(acc[mt][2 * ntp],     ahi[mt], bh[0], bh[1]);
                    mma_f16(acc[mt][2 * ntp],     alo[mt], bh[0], bh[1]);
                    mma_f16(acc[mt][2 * ntp + 1], ahi[mt], bh[2], bh[3]);
                    mma_f16(acc[mt][2 * ntp + 1], alo[mt], bh[2], bh[3]);
                }
            }
        }
        __syncthreads();
    }

    #pragma unroll
    for (int nt = 0; nt < 4; nt++) {
        int n = n0 + wx * 32 + nt * 8 + tq;
        float2 b2 = *(const float2*)&bias[n];
        int h = n >> 6, d = n & 63;
        #pragma unroll
        for (int mt = 0; mt < 4; mt++) {
            int m = m0 + wy * 64 + mt * 16 + g;
            int b = m >> 10, s = m & (SEQ - 1);
            int bh = b * NHEAD + h;
            float v0 = acc[mt][nt][0] + b2.x, v1 = acc[mt][nt][1] + b2.y;
            float v2 = acc[mt][nt][2] + b2.x, v3 = acc[mt][nt][3] + b2.y;
            __nv_bfloat16 h0, l0, h1, l1, h2, l2, h3, l3;
            split_bf16(v0, h0, l0); split_bf16(v1, h1, l1);
            split_bf16(v2, h2, l2); split_bf16(v3, h3, l3);
            if (z < 2) {
                __nv_bfloat16* ah = (z == 0) ? g_qh : g_kh;
                __nv_bfloat16* al = (z == 0) ? g_ql : g_kl;
                size_t o0 = ((size_t)bh * SEQ + s) * HDIM + d;
                size_t o1 = o0 + 8 * HDIM;
                *(__nv_bfloat162*)(ah + o0) = __nv_bfloat162(h0, h1);
                *(__nv_bfloat162*)(al + o0) = __nv_bfloat162(l0, l1);
                *(__nv_bfloat162*)(ah + o1) = __nv_bfloat162(h2, h3);
                *(__nv_bfloat162*)(al + o1) = __nv_bfloat162(l2, l3);
            } else {
                size_t base = ((size_t)bh * HDIM + d) * SEQ + s;
                g_vth[base] = h0;           g_vtl[base] = l0;
                g_vth[base + SEQ] = h1;     g_vtl[base + SEQ] = l1;
                g_vth[base + 8] = h2;       g_vtl[base + 8] = l2;
                g_vth[base + SEQ + 8] = h3; g_vtl[base + SEQ + 8] = l3;
            }
        }
    }
}

// ---------------- phase 2-4 fused: flash attention + rel-pos ----------------
#define FA_QAS   9216                  // 128*72
#define FA_KAS   4608                  // 64*72
#define FA_STAGE (4 * FA_KAS)
#define FA_PSOFF (2 * FA_QAS + 2 * FA_STAGE)
#define FA_SMEM  (FA_PSOFF * 2 + 128 * 132 * 4 + 4096)

__global__ __launch_bounds__(256) void attn_fused_kernel(
    const float* __restrict__ mask, float* __restrict__ out)
{
    extern __shared__ __align__(16) __nv_bfloat16 dsm[];
    const int bh = blockIdx.y, b = bh >> 4, h = bh & 15;
    const int q0 = blockIdx.x * 128;
    const int t = threadIdx.x, lane = t & 31, w = t >> 5;
    const int g = lane >> 2, tq = (lane & 3) * 2;
    const int arow = lane & 15, acol8 = (lane >> 4) * 8;
    const int brow = ((lane >> 4) << 3) + (lane & 7), bcol8 = ((lane >> 3) & 1) * 8;

    __nv_bfloat16* sQhi = dsm;
    __nv_bfloat16* sQlo = dsm + FA_QAS;
    float* psm = (float*)(dsm + FA_PSOFF);
    float* smask = psm + 128 * 132;

    cp_async16(smask + t * 4, mask + (size_t)b * SEQ + t * 4);

    #pragma unroll
    for (int u = 0; u < 4; u++) {
        int idx = t + 256 * u;
        int r = idx >> 3, ce = (idx & 7) * 8;
        size_t ga = ((size_t)bh * SEQ + q0 + r) * HDIM + ce;
        int so = r * SST2 + ce;
        cp_async16(sQhi + so, g_qh + ga);
        cp_async16(sQlo + so, g_ql + ga);
    }
    __nv_bfloat16* sTabHi = dsm + 2 * FA_QAS;
    __nv_bfloat16* sTabLo = sTabHi + TABP * SST2;
    #pragma unroll
    for (int u = 0; u < 5; u++) {
        int idx = t + 256 * u;
        if (idx < TABP * 8) {
            int r = idx >> 3, ce = (idx & 7) * 8;
            cp_async16(sTabHi + r * SST2 + ce, g_tab_hi + r * 64 + ce);
            cp_async16(sTabLo + r * SST2 + ce, g_tab_lo + r * 64 + ce);
        }
    }
    cp_commit();
    cp_wait0();
    __syncthreads();

    float* prowg = psm + (w * 16 + g) * 132;
    float* prowh = prowg + 8 * 132;

    // ---- hoist Q fragments (loop-invariant across qrel + all kt) ----
    unsigned qfh[4][4], qfl[4][4];
    #pragma unroll
    for (int kk4 = 0; kk4 < 4; kk4++) {
        int ab = (w * 16 + arow) * SST2 + kk4 * 16 + acol8;
        ldsm4(qfh[kk4], sQhi + ab);
        ldsm4(qfl[kk4], sQlo + ab);
    }

    // ---- qrel = Q @ tab^T (split MMA) -> band ----
    #pragma unroll
    for (int ntp = 0; ntp < 9; ntp++) {
        float d0[4] = {}, d1[4] = {};
        #pragma unroll
        for (int kk4 = 0; kk4 < 4; kk4++) {
            int bb = (ntp * 16 + brow) * SST2 + kk4 * 16 + bcol8;
            unsigned th4[4], tl4[4];
            ldsm4(th4, sTabHi + bb);
            ldsm4(tl4, sTabLo + bb);
            mma_bf16(d0, qfh[kk4], th4[0], th4[1]);
            mma_bf16(d0, qfh[kk4], tl4[0], tl4[1]);
            mma_bf16(d0, qfl[kk4], th4[0], th4[1]);
            mma_bf16(d1, qfh[kk4], th4[2], th4[3]);
            mma_bf16(d1, qfh[kk4], tl4[2], tl4[3]);
            mma_bf16(d1, qfl[kk4], th4[2], th4[3]);
        }
        int c0 = ntp * 16 + tq, c1 = ntp * 16 + 8 + tq;
        if (c0 < 132) {
            prowg[c0] = d0[0]; prowg[c0 + 1] = d0[1];
            prowh[c0] = d0[2]; prowh[c0 + 1] = d0[3];
        }
        if (c1 < 132) {
            prowg[c1] = d1[0]; prowg[c1 + 1] = d1[1];
            prowh[c1] = d1[2]; prowh[c1 + 1] = d1[3];
        }
    }
    __syncthreads();

    const int qg = q0 + w * 16 + g;
    const int qh2 = qg + 8;
    const float qr0g = prowg[0], qr128g = prowg[128];
    const float qr0h = prowh[0], qr128h = prowh[128];

    auto load_kv = [&](int stg, int kt0) {
        __nv_bfloat16* base = dsm + 2 * FA_QAS + stg * FA_STAGE;
        #pragma unroll
        for (int u = 0; u < 2; u++) {
            int idx = t + 256 * u;
            int r = idx >> 3, ce = (idx & 7) * 8;
            int so = r * SST2 + ce;
            size_t gk = ((size_t)bh * SEQ + kt0 + r) * HDIM + ce;
            size_t gv = ((size_t)bh * HDIM + r) * SEQ + kt0 + ce;
            cp_async16(base + 0 * FA_KAS + so, g_kh + gk);
            cp_async16(base + 1 * FA_KAS + so, g_kl + gk);
            cp_async16(base + 2 * FA_KAS + so, g_vth + gv);
            cp_async16(base + 3 * FA_KAS + so, g_vtl + gv);
        }
    };
    load_kv(0, 0);
    cp_commit();

    float acc[8][4] = {};
    float m_g = -1e30f, m_h = -1e30f;
    float l_g = 0.f, l_h = 0.f, lo_g = 0.f, lo_h = 0.f, hi_g = 0.f, hi_h = 0.f;

    for (int kt = 0; kt < 16; kt++) {
        int kt0 = kt * 64;
        if (kt < 15) { load_kv((kt ^ 1) & 1, kt0 + 64); cp_commit(); cp_wait1(); }
        else         { cp_wait0(); }
        __syncthreads();
        const __nv_bfloat16* stage = dsm + 2 * FA_QAS + (kt & 1) * FA_STAGE;
        const __nv_bfloat16* sKhi = stage;
        const __nv_bfloat16* sKlo = stage + FA_KAS;
        const __nv_bfloat16* sVhi = stage + 2 * FA_KAS;
        const __nv_bfloat16* sVlo = stage + 3 * FA_KAS;

        float s[8][4] = {};
        #pragma unroll
        for (int kk4 = 0; kk4 < 4; kk4++) {
            #pragma unroll
            for (int ntp = 0; ntp < 4; ntp++) {
                int bb = (ntp * 16 + brow) * SST2 + kk4 * 16 + bcol8;
                unsigned kh[4], kl[4];
                ldsm4(kh, sKhi + bb);
                ldsm4(kl, sKlo + bb);
                mma_bf16(s[2 * ntp],     qfh[kk4], kh[0], kh[1]);
                mma_bf16(s[2 * ntp],     qfh[kk4], kl[0], kl[1]);
                mma_bf16(s[2 * ntp],     qfl[kk4], kh[0], kh[1]);
                mma_bf16(s[2 * ntp + 1], qfh[kk4], kh[2], kh[3]);
                mma_bf16(s[2 * ntp + 1], qfh[kk4], kl[2], kl[3]);
                mma_bf16(s[2 * ntp + 1], qfl[kk4], kh[2], kh[3]);
            }
        }

        #pragma unroll
        for (int nt = 0; nt < 8; nt++) {
            int k = kt0 + nt * 8 + tq;
            float mk0 = smask[k], mk1 = smask[k + 1];
            int d0 = k - qg, d1 = k + 1 - qg;
            if (d0 > -64 && d0 < 64) {
                float sv = (s[nt][0] + prowg[d0 + 64]) * 0.125f + mk0;
                prowg[d0 + 64] = sv; s[nt][0] = sv;
            } else s[nt][0] = (s[nt][0] + (d0 <= -64 ? qr0g : qr128g)) * 0.125f + mk0;
            if (d1 > -64 && d1 < 64) {
                float sv = (s[nt][1] + prowg[d1 + 64]) * 0.125f + mk1;
                prowg[d1 + 64] = sv; s[nt][1] = sv;
            } else s[nt][1] = (s[nt][1] + (d1 <= -64 ? qr0g : qr128g)) * 0.125f + mk1;
            int e0 = k - qh2, e1 = k + 1 - qh2;
            if (e0 > -64 && e0 < 64) {
                float sv = (s[nt][2] + prowh[e0 + 64]) * 0.125f + mk0;
                prowh[e0 + 64] = sv; s[nt][2] = sv;
            } else s[nt][2] = (s[nt][2] + (e0 <= -64 ? qr0h : qr128h)) * 0.125f + mk0;
            if (e1 > -64 && e1 < 64) {
                float sv = (s[nt][3] + prowh[e1 + 64]) * 0.125f + mk1;
                prowh[e1 + 64] = sv; s[nt][3] = sv;
            } else s[nt][3] = (s[nt][3] + (e1 <= -64 ? qr0h : qr128h)) * 0.125f + mk1;
        }

        float tg = -1e30f, th = -1e30f;
        #pragma unroll
        for (int nt = 0; nt < 8; nt++) {
            tg = fmaxf(tg, fmaxf(s[nt][0], s[nt][1]));
            th = fmaxf(th, fmaxf(s[nt][2], s[nt][3]));
        }
        tg = quadmax(tg); th = quadmax(th);
        float mng = fmaxf(m_g, tg), mnh = fmaxf(m_h, th);
        float scg = __expf(m_g - mng), sch = __expf(m_h - mnh);
        if (scg < 1.0f) {
            #pragma unroll
            for (int nt = 0; nt < 8; nt++) { acc[nt][0] *= scg; acc[nt][1] *= scg; }
            l_g *= scg; lo_g *= scg; hi_g *= scg;
        }
        if (sch < 1.0f) {
            #pragma unroll
            for (int nt = 0; nt < 8; nt++) { acc[nt][2] *= sch; acc[nt][3] *= sch; }
            l_h *= sch; lo_h *= sch; hi_h *= sch;
        }
        m_g = mng; m_h = mnh;

        unsigned phi[4][4], plo[4][4];
        #pragma unroll
        for (int nt = 0; nt < 8; nt++) {
            int k = kt0 + nt * 8 + tq;
            float p0 = __expf(s[nt][0] - m_g), p1 = __expf(s[nt][1] - m_g);
            float p2 = __expf(s[nt][2] - m_h), p3 = __expf(s[nt][3] - m_h);
            l_g += p0 + p1; l_h += p2 + p3;
            int d0 = k - qg, d1 = k + 1 - qg;
            if (d0 <= -64) lo_g += p0; else if (d0 >= 64) hi_g += p0;
            if (d1 <= -64) lo_g += p1; else if (d1 >= 64) hi_g += p1;
            int e0 = k - qh2, e1 = k + 1 - qh2;
            if (e0 <= -64) lo_h += p2; else if (e0 >= 64) hi_h += p2;
            if (e1 <= -64) lo_h += p3; else if (e1 >= 64) hi_h += p3;
            int kb = nt >> 1;
            if ((nt & 1) == 0) {
                phi[kb][0] = pack2h(p0, p1); phi[kb][1] = pack2h(p2, p3);
                plo[kb][0] = pack2l(p0, p1); plo[kb][1] = pack2l(p2, p3);
            } else {
                phi[kb][2] = pack2h(p0, p1); phi[kb][3] = pack2h(p2, p3);
                plo[kb][2] = pack2l(p0, p1); plo[kb][3] = pack2l(p2, p3);
            }
        }

        #pragma unroll
        for (int kb = 0; kb < 4; kb++) {
            int kk = kb * 16;
            #pragma unroll
            for (int ntp = 0; ntp < 4; ntp++) {
                int bb = (ntp * 16 + brow) * SST2 + kk + bcol8;
                unsigned vh[4], vl[4];
                ldsm4(vh, sVhi + bb);
                ldsm4(vl, sVlo + bb);
                mma_bf16(acc[2 * ntp],     phi[kb], vh[0], vh[1]);
                mma_bf16(acc[2 * ntp],     phi[kb], vl[0], vl[1]);
                mma_bf16(acc[2 * ntp],     plo[kb], vh[0], vh[1]);
                mma_bf16(acc[2 * ntp + 1], phi[kb], vh[2], vh[3]);
                mma_bf16(acc[2 * ntp + 1], phi[kb], vl[2], vl[3]);
                mma_bf16(acc[2 * ntp + 1], plo[kb], vh[2], vh[3]);
            }
        }
        __syncthreads();
    }

    l_g = quadsum(l_g); l_h = quadsum(l_h);
    lo_g = quadsum(lo_g); lo_h = quadsum(lo_h);
    hi_g = quadsum(hi_g); hi_h = quadsum(hi_h);
    if ((lane & 3) == 0) {
        prowg[0] = lo_g; prowg[128] = hi_g;
        prowh[0] = lo_h; prowh[128] = hi_h;
    }
    {
        int c0 = (lane & 3) * 33; if (c0 == 0) c0 = 1;
        int c1 = (lane & 3) * 33 + 33; if (c1 > 128) c1 = 128;
        for (int c = c0; c < c1; c++) {
            int kg = qg + c - 64;
            int kh2 = qh2 + c - 64;
            prowg[c] = (kg >= 0 && kg < SEQ) ? __expf(prowg[c] - m_g) : 0.0f;
            prowh[c] = (kh2 >= 0 && kh2 < SEQ) ? __expf(prowh[c] - m_h) : 0.0f;
        }
    }
    __syncthreads();

    float* tabS = (float*)(dsm + 2 * FA_QAS);
    for (int r0 = 0; r0 < VOCAB; r0 += 16) {
        __syncthreads();
        {
            int rr = t >> 4, cc = (t & 15) * 4;
            int r = r0 + rr;
            float4 tv = (r < VOCAB) ? *(const float4*)&g_tab[r * 64 + cc]
                                    : make_float4(0.f, 0.f, 0.f, 0.f);
            *(float4*)&tabS[rr * 68 + cc] = tv;
        }
        __syncthreads();
        #pragma unroll
        for (int rc = 0; rc < 16; rc++) {
            int rr2 = r0 + rc; if (rr2 > 128) rr2 = 128;
            float pg = prowg[rr2];
            float ph = prowh[rr2];
            #pragma unroll
            for (int nt = 0; nt < 8; nt++) {
                int d = nt * 8 + tq;
                float t0 = tabS[rc * 68 + d], t1 = tabS[rc * 68 + d + 1];
                acc[nt][0] += pg * t0; acc[nt][1] += pg * t1;
                acc[nt][2] += ph * t0; acc[nt][3] += ph * t1;
            }
        }
    }

    float ig = 1.0f / l_g, ih = 1.0f / l_h;
    #pragma unroll
    for (int nt = 0; nt < 8; nt++) {
        int d = nt * 8 + tq;
        *(float2*)(out + ((size_t)(b * SEQ + qg)) * HID + h * 64 + d) =
            make_float2(acc[nt][0] * ig, acc[nt][1] * ig);
        *(float2*)(out + ((size_t)(b * SEQ + qh2)) * HID + h * 64 + d) =
            make_float2(acc[nt][2] * ih, acc[nt][3] * ih);
    }
}

// ---------------- launcher ----------------
extern "C" void kernel_launch(void* const* d_in, const int* in_sizes, int n_in,
                              void* d_out, int out_size) {
    const float* hs   = (const float*)d_in[0];
    const float* mask = (const float*)d_in[1];
    const float* Wq   = (const float*)d_in[2];
    const float* bq   = (const float*)d_in[3];
    const float* Wk   = (const float*)d_in[4];
    const float* bk   = (const float*)d_in[5];
    const float* Wv   = (const float*)d_in[6];
    const float* bv   = (const float*)d_in[7];
    float* out = (float*)d_out;

    cudaFuncSetAttribute(qkv_mma_kernel,    cudaFuncAttributeMaxDynamicSharedMemorySize, QKV_SMEM);
    cudaFuncSetAttribute(attn_fused_kernel, cudaFuncAttributeMaxDynamicSharedMemorySize, FA_SMEM);

    prep_kernel<<<HS_BLKS + W_BLKS + TAB_BLKS, 256>>>(hs, Wq, Wk, Wv);
    qkv_mma_kernel<<<dim3(HID / 128, (BATCH * SEQ) / 128, 3), 256, QKV_SMEM>>>(bq, bk, bv);
    attn_fused_kernel<<<dim3(SEQ / 128, BH), 256, FA_SMEM>>>(mask, out);
}

// round 17
// speedup vs baseline: 4.5948x; 1.1377x over previous
#include <cuda_runtime.h>
#include <cuda_bf16.h>
#include <cuda_fp16.h>
#include <cstdint>

#define BATCH 2
#define SEQ   1024
#define HID   1024
#define NHEAD 16
#define HDIM  64
#define BH    (BATCH*NHEAD)      // 32
#define VOCAB 129                // 2*64+1
#define TABP  144                // tab rows padded for MMA
#define SSTR  40                 // half smem stride (BK=32 tiles): conflict-free
#define SST2  72                 // half smem stride (64-col tiles): conflict-free

// ---------------- scratch ----------------
__device__ __align__(16) float g_tab[VOCAB * HDIM];
__device__ __align__(16) __half g_tab_h[TABP * HDIM];         // single fp16 tab

__device__ __align__(16) __half g_hs_hi[BATCH * SEQ * HID];
__device__ __align__(16) __half g_hs_lo[BATCH * SEQ * HID];
__device__ __align__(16) __half g_w_hi[3 * HID * HID];        // W truncated to fp16
__device__ __align__(16) __half g_qh[BH * SEQ * HDIM];        // Q fp16 hi
__device__ __align__(16) __half g_ql[BH * SEQ * HDIM];        // Q fp16 lo
__device__ __align__(16) __half g_kh[BH * SEQ * HDIM];        // K fp16 (single)
__device__ __align__(16) __half g_vth[BH * HDIM * SEQ];       // V^T fp16 (single)

// ---------------- helpers ----------------
__device__ __forceinline__ void cp_async16(void* dst, const void* src) {
    unsigned int d = (unsigned int)__cvta_generic_to_shared(dst);
    asm volatile("cp.async.cg.shared.global [%0], [%1], 16;" :: "r"(d), "l"(src));
}
__device__ __forceinline__ void cp_commit() { asm volatile("cp.async.commit_group;"); }
__device__ __forceinline__ void cp_wait0()  { asm volatile("cp.async.wait_group 0;"); }
__device__ __forceinline__ void cp_wait1()  { asm volatile("cp.async.wait_group 1;"); }

__device__ __forceinline__ void ldsm4(unsigned* r, const void* p) {
    unsigned a = (unsigned)__cvta_generic_to_shared(p);
    asm volatile("ldmatrix.sync.aligned.m8n8.x4.shared.b16 {%0,%1,%2,%3}, [%4];"
                 : "=r"(r[0]), "=r"(r[1]), "=r"(r[2]), "=r"(r[3]) : "r"(a));
}

__device__ __forceinline__ void split_f16(float v, __half& hi, __half& lo) {
    hi = __float2half_rn(v);
    lo = __float2half_rn(v - __half2float(hi));
}
__device__ __forceinline__ unsigned pack2h_f16(float a, float b) {
    __half2 p(__float2half_rn(a), __float2half_rn(b));
    return *(unsigned*)&p;
}
__device__ __forceinline__ unsigned pack2l_f16(float a, float b) {
    float ra = a - __half2float(__float2half_rn(a));
    float rb = b - __half2float(__float2half_rn(b));
    __half2 p(__float2half_rn(ra), __float2half_rn(rb));
    return *(unsigned*)&p;
}
__device__ __forceinline__ float quadmax(float v) {
    v = fmaxf(v, __shfl_xor_sync(0xffffffffu, v, 1));
    v = fmaxf(v, __shfl_xor_sync(0xffffffffu, v, 2));
    return v;
}
__device__ __forceinline__ float quadsum(float v) {
    v += __shfl_xor_sync(0xffffffffu, v, 1);
    v += __shfl_xor_sync(0xffffffffu, v, 2);
    return v;
}
__device__ __forceinline__ void mma_f16(float* c, const unsigned int* A,
                                        unsigned int b0, unsigned int b1) {
    asm volatile("mma.sync.aligned.m16n8k16.row.col.f32.f16.f16.f32 "
        "{%0,%1,%2,%3}, {%4,%5,%6,%7}, {%8,%9}, {%0,%1,%2,%3};"
        : "+f"(c[0]), "+f"(c[1]), "+f"(c[2]), "+f"(c[3])
        : "r"(A[0]), "r"(A[1]), "r"(A[2]), "r"(A[3]), "r"(b0), "r"(b1));
}

// ---------------- merged prep ----------------
#define HS_BLKS 2048
#define W_BLKS  3072
#define TAB_BLKS 18

__global__ __launch_bounds__(256) void prep_kernel(
    const float* __restrict__ hs,
    const float* __restrict__ Wq, const float* __restrict__ Wk, const float* __restrict__ Wv)
{
    int blk = blockIdx.x;
    int t = threadIdx.x;
    if (blk < HS_BLKS) {
        int i = (blk * 256 + t) * 4;
        float4 v = *(const float4*)(hs + i);
        __half h, l;
        split_f16(v.x, h, l); g_hs_hi[i + 0] = h; g_hs_lo[i + 0] = l;
        split_f16(v.y, h, l); g_hs_hi[i + 1] = h; g_hs_lo[i + 1] = l;
        split_f16(v.z, h, l); g_hs_hi[i + 2] = h; g_hs_lo[i + 2] = l;
        split_f16(v.w, h, l); g_hs_hi[i + 3] = h; g_hs_lo[i + 3] = l;
    } else if (blk < HS_BLKS + W_BLKS) {
        int i = ((blk - HS_BLKS) * 256 + t) * 4;
        int z = i / (HID * HID), r = i - z * (HID * HID);
        const float* W = (z == 0) ? Wq : (z == 1 ? Wk : Wv);
        float4 v = *(const float4*)(W + r);
        g_w_hi[i + 0] = __float2half_rn(v.x);
        g_w_hi[i + 1] = __float2half_rn(v.y);
        g_w_hi[i + 2] = __float2half_rn(v.z);
        g_w_hi[i + 3] = __float2half_rn(v.w);
    } else {
        int idx = (blk - HS_BLKS - W_BLKS) * 256 + t;
        if (idx >= TABP * 32) return;
        int p = idx >> 5, i = idx & 31;
        if (p < VOCAB) {
            float div = expf((float)(2 * i) * (-9.210340371976184f / 64.0f));
            float ang = (float)p * div;
            float sv = sinf(ang), cv = cosf(ang);
            g_tab[p * 64 + 2 * i]     = sv;
            g_tab[p * 64 + 2 * i + 1] = cv;
            g_tab_h[p * 64 + 2 * i]     = __float2half_rn(sv);
            g_tab_h[p * 64 + 2 * i + 1] = __float2half_rn(cv);
        } else {
            g_tab_h[p * 64 + 2 * i]     = __float2half_rn(0.f);
            g_tab_h[p * 64 + 2 * i + 1] = __float2half_rn(0.f);
        }
    }
}

// ---------------- phase 1: QKV projection, fp16 2-term, BK=32 2-stage, 2 CTAs/SM ----------------
#define QKV_AS    (128 * SSTR)
#define QKV_STAGE (3 * QKV_AS)
#define QKV_SMEM  (2 * QKV_STAGE * 2)

__global__ __launch_bounds__(256, 2) void qkv_mma_kernel(
    const float* __restrict__ bq, const float* __restrict__ bk, const float* __restrict__ bv)
{
    extern __shared__ __align__(16) __half dsmh[];
    int z = blockIdx.z;
    const float* bias = (z == 0) ? bq : (z == 1 ? bk : bv);
    const __half* gWhi = g_w_hi + (size_t)z * HID * HID;

    int m0 = blockIdx.y * 128, n0 = blockIdx.x * 128;
    int t = threadIdx.x;
    int lane = t & 31, warp = t >> 5;
    int wy = warp >> 2, wx = warp & 3;
    int g = lane >> 2, tq = (lane & 3) * 2;
    int arow = lane & 15, acol8 = (lane >> 4) * 8;
    int brow = ((lane >> 4) << 3) + (lane & 7), bcol8 = ((lane >> 3) & 1) * 8;

    float acc[4][4][4] = {};

    auto load_stage = [&](int stg, int k0) {
        __half* base = dsmh + stg * QKV_STAGE;
        #pragma unroll
        for (int u = 0; u < 2; u++) {
            int idx = t + 256 * u;
            int r = idx >> 2, ce = (idx & 3) * 8;
            size_t ga = (size_t)(m0 + r) * HID + k0 + ce;
            size_t gb = (size_t)(n0 + r) * HID + k0 + ce;
            int so = r * SSTR + ce;
            cp_async16(base + 0 * QKV_AS + so, g_hs_hi + ga);
            cp_async16(base + 1 * QKV_AS + so, g_hs_lo + ga);
            cp_async16(base + 2 * QKV_AS + so, gWhi + gb);
        }
    };

    load_stage(0, 0);
    cp_commit();

    for (int k0 = 0; k0 < HID; k0 += 32) {
        int stg = (k0 >> 5) & 1;
        if (k0 + 32 < HID) { load_stage(stg ^ 1, k0 + 32); cp_commit(); cp_wait1(); }
        else               { cp_wait0(); }
        __syncthreads();
        const __half* sAhi = dsmh + stg * QKV_STAGE;
        const __half* sAlo = sAhi + QKV_AS;
        const __half* sBhi = sAlo + QKV_AS;

        #pragma unroll
        for (int kk = 0; kk < 32; kk += 16) {
            unsigned ahi[4][4], alo[4][4];
            #pragma unroll
            for (int mt = 0; mt < 4; mt++) {
                int ab = (wy * 64 + mt * 16 + arow) * SSTR + kk + acol8;
                ldsm4(ahi[mt], sAhi + ab);
                ldsm4(alo[mt], sAlo + ab);
            }
            #pragma unroll
            for (int ntp = 0; ntp < 2; ntp++) {
                int bb = (wx * 32 + ntp * 16 + brow) * SSTR + kk + bcol8;
                unsigned bh[4];
                ldsm4(bh, sBhi + bb);
                #pragma unroll
                for (int mt = 0; mt < 4; mt++) {
                    mma_f16(acc[mt][2 * ntp],     ahi[mt], bh[0], bh[1]);
                    mma_f16(acc[mt][2 * ntp],     alo[mt], bh[0], bh[1]);
                    mma_f16(acc[mt][2 * ntp + 1], ahi[mt], bh[2], bh[3]);
                    mma_f16(acc[mt][2 * ntp + 1], alo[mt], bh[2], bh[3]);
                }
            }
        }
        __syncthreads();
    }

    #pragma unroll
    for (int nt = 0; nt < 4; nt++) {
        int n = n0 + wx * 32 + nt * 8 + tq;
        float2 b2 = *(const float2*)&bias[n];
        int h = n >> 6, d = n & 63;
        #pragma unroll
        for (int mt = 0; mt < 4; mt++) {
            int m = m0 + wy * 64 + mt * 16 + g;
            int b = m >> 10, s = m & (SEQ - 1);
            int bh = b * NHEAD + h;
            float v0 = acc[mt][nt][0] + b2.x, v1 = acc[mt][nt][1] + b2.y;
            float v2 = acc[mt][nt][2] + b2.x, v3 = acc[mt][nt][3] + b2.y;
            if (z == 0) {
                __half h0, l0, h1, l1, h2, l2, h3, l3;
                split_f16(v0, h0, l0); split_f16(v1, h1, l1);
                split_f16(v2, h2, l2); split_f16(v3, h3, l3);
                size_t o0 = ((size_t)bh * SEQ + s) * HDIM + d;
                size_t o1 = o0 + 8 * HDIM;
                *(__half2*)(g_qh + o0) = __half2(h0, h1);
                *(__half2*)(g_ql + o0) = __half2(l0, l1);
                *(__half2*)(g_qh + o1) = __half2(h2, h3);
                *(__half2*)(g_ql + o1) = __half2(l2, l3);
            } else if (z == 1) {
                size_t o0 = ((size_t)bh * SEQ + s) * HDIM + d;
                size_t o1 = o0 + 8 * HDIM;
                *(__half2*)(g_kh + o0) = __half2(__float2half_rn(v0), __float2half_rn(v1));
                *(__half2*)(g_kh + o1) = __half2(__float2half_rn(v2), __float2half_rn(v3));
            } else {
                size_t base = ((size_t)bh * HDIM + d) * SEQ + s;
                g_vth[base] = __float2half_rn(v0);
                g_vth[base + SEQ] = __float2half_rn(v1);
                g_vth[base + 8] = __float2half_rn(v2);
                g_vth[base + SEQ + 8] = __float2half_rn(v3);
            }
        }
    }
}

// ---------------- phase 2-4 fused: flash attention + rel-pos (fp16 2-term) ----------------
#define FA_QAS   9216                  // 128*72 halfs
#define FA_KAS   4608                  // 64*72 halfs
#define FA_STAGE (2 * FA_KAS)          // K + V^T only
#define FA_PSOFF (2 * FA_QAS + 2 * FA_STAGE)
#define FA_SMEM  (FA_PSOFF * 2 + 128 * 132 * 4 + 4096)   // 73728 + 67584 + 4096

__global__ __launch_bounds__(256) void attn_fused_kernel(
    const float* __restrict__ mask, float* __restrict__ out)
{
    extern __shared__ __align__(16) __half dsmh[];
    const int bh = blockIdx.y, b = bh >> 4, h = bh & 15;
    const int q0 = blockIdx.x * 128;
    const int t = threadIdx.x, lane = t & 31, w = t >> 5;
    const int g = lane >> 2, tq = (lane & 3) * 2;
    const int arow = lane & 15, acol8 = (lane >> 4) * 8;
    const int brow = ((lane >> 4) << 3) + (lane & 7), bcol8 = ((lane >> 3) & 1) * 8;

    __half* sQhi = dsmh;
    __half* sQlo = dsmh + FA_QAS;
    float* psm = (float*)(dsmh + FA_PSOFF);
    float* smask = psm + 128 * 132;

    cp_async16(smask + t * 4, mask + (size_t)b * SEQ + t * 4);

    #pragma unroll
    for (int u = 0; u < 4; u++) {
        int idx = t + 256 * u;
        int r = idx >> 3, ce = (idx & 7) * 8;
        size_t ga = ((size_t)bh * SEQ + q0 + r) * HDIM + ce;
        int so = r * SST2 + ce;
        cp_async16(sQhi + so, g_qh + ga);
        cp_async16(sQlo + so, g_ql + ga);
    }
    __half* sTab = dsmh + 2 * FA_QAS;      // consumed before KV stage 1 reuse? stage area = 2*FA_STAGE = 18432 >= TABP*SST2=10368
    #pragma unroll
    for (int u = 0; u < 5; u++) {
        int idx = t + 256 * u;
        if (idx < TABP * 8) {
            int r = idx >> 3, ce = (idx & 7) * 8;
            cp_async16(sTab + r * SST2 + ce, g_tab_h + r * 64 + ce);
        }
    }
    cp_commit();
    cp_wait0();
    __syncthreads();

    float* prowg = psm + (w * 16 + g) * 132;
    float* prowh = prowg + 8 * 132;

    // ---- hoist Q fragments ----
    unsigned qfh[4][4], qfl[4][4];
    #pragma unroll
    for (int kk4 = 0; kk4 < 4; kk4++) {
        int ab = (w * 16 + arow) * SST2 + kk4 * 16 + acol8;
        ldsm4(qfh[kk4], sQhi + ab);
        ldsm4(qfl[kk4], sQlo + ab);
    }

    // ---- qrel = Q @ tab^T -> band ----
    #pragma unroll
    for (int ntp = 0; ntp < 9; ntp++) {
        float d0[4] = {}, d1[4] = {};
        #pragma unroll
        for (int kk4 = 0; kk4 < 4; kk4++) {
            int bb = (ntp * 16 + brow) * SST2 + kk4 * 16 + bcol8;
            unsigned th4[4];
            ldsm4(th4, sTab + bb);
            mma_f16(d0, qfh[kk4], th4[0], th4[1]);
            mma_f16(d0, qfl[kk4], th4[0], th4[1]);
            mma_f16(d1, qfh[kk4], th4[2], th4[3]);
            mma_f16(d1, qfl[kk4], th4[2], th4[3]);
        }
        int c0 = ntp * 16 + tq, c1 = ntp * 16 + 8 + tq;
        if (c0 < 132) {
            prowg[c0] = d0[0]; prowg[c0 + 1] = d0[1];
            prowh[c0] = d0[2]; prowh[c0 + 1] = d0[3];
        }
        if (c1 < 132) {
            prowg[c1] = d1[0]; prowg[c1 + 1] = d1[1];
            prowh[c1] = d1[2]; prowh[c1 + 1] = d1[3];
        }
    }
    __syncthreads();

    const int qg = q0 + w * 16 + g;
    const int qh2 = qg + 8;
    const float qr0g = prowg[0], qr128g = prowg[128];
    const float qr0h = prowh[0], qr128h = prowh[128];

    auto load_kv = [&](int stg, int kt0) {
        __half* base = dsmh + 2 * FA_QAS + stg * FA_STAGE;
        {
            int idx = t;
            int r = idx >> 2, ce = (idx & 3) * 16;    // 64 rows x 64 cols, 8 halfs per cp: redo
        }
        #pragma unroll
        for (int u = 0; u < 2; u++) {
            int idx = t + 256 * u;
            int r = idx >> 3, ce = (idx & 7) * 8;
            int so = r * SST2 + ce;
            size_t gk = ((size_t)bh * SEQ + kt0 + r) * HDIM + ce;
            size_t gv = ((size_t)bh * HDIM + r) * SEQ + kt0 + ce;
            cp_async16(base + 0 * FA_KAS + so, g_kh + gk);
            cp_async16(base + 1 * FA_KAS + so, g_vth + gv);
        }
    };
    load_kv(0, 0);
    cp_commit();

    float acc[8][4] = {};
    float m_g = -1e30f, m_h = -1e30f;
    float l_g = 0.f, l_h = 0.f, lo_g = 0.f, lo_h = 0.f, hi_g = 0.f, hi_h = 0.f;

    for (int kt = 0; kt < 16; kt++) {
        int kt0 = kt * 64;
        if (kt < 15) { load_kv((kt ^ 1) & 1, kt0 + 64); cp_commit(); cp_wait1(); }
        else         { cp_wait0(); }
        __syncthreads();
        const __half* stage = dsmh + 2 * FA_QAS + (kt & 1) * FA_STAGE;
        const __half* sKhi = stage;
        const __half* sVhi = stage + FA_KAS;

        float s[8][4] = {};
        #pragma unroll
        for (int kk4 = 0; kk4 < 4; kk4++) {
            #pragma unroll
            for (int ntp = 0; ntp < 4; ntp++) {
                int bb = (ntp * 16 + brow) * SST2 + kk4 * 16 + bcol8;
                unsigned kh[4];
                ldsm4(kh, sKhi + bb);
                mma_f16(s[2 * ntp],     qfh[kk4], kh[0], kh[1]);
                mma_f16(s[2 * ntp],     qfl[kk4], kh[0], kh[1]);
                mma_f16(s[2 * ntp + 1], qfh[kk4], kh[2], kh[3]);
                mma_f16(s[2 * ntp + 1], qfl[kk4], kh[2], kh[3]);
            }
        }

        #pragma unroll
        for (int nt = 0; nt < 8; nt++) {
            int k = kt0 + nt * 8 + tq;
            float mk0 = smask[k], mk1 = smask[k + 1];
            int d0 = k - qg, d1 = k + 1 - qg;
            if (d0 > -64 && d0 < 64) {
                float sv = (s[nt][0] + prowg[d0 + 64]) * 0.125f + mk0;
                prowg[d0 + 64] = sv; s[nt][0] = sv;
            } else s[nt][0] = (s[nt][0] + (d0 <= -64 ? qr0g : qr128g)) * 0.125f + mk0;
            if (d1 > -64 && d1 < 64) {
                float sv = (s[nt][1] + prowg[d1 + 64]) * 0.125f + mk1;
                prowg[d1 + 64] = sv; s[nt][1] = sv;
            } else s[nt][1] = (s[nt][1] + (d1 <= -64 ? qr0g : qr128g)) * 0.125f + mk1;
            int e0 = k - qh2, e1 = k + 1 - qh2;
            if (e0 > -64 && e0 < 64) {
                float sv = (s[nt][2] + prowh[e0 + 64]) * 0.125f + mk0;
                prowh[e0 + 64] = sv; s[nt][2] = sv;
            } else s[nt][2] = (s[nt][2] + (e0 <= -64 ? qr0h : qr128h)) * 0.125f + mk0;
            if (e1 > -64 && e1 < 64) {
                float sv = (s[nt][3] + prowh[e1 + 64]) * 0.125f + mk1;
                prowh[e1 + 64] = sv; s[nt][3] = sv;
            } else s[nt][3] = (s[nt][3] + (e1 <= -64 ? qr0h : qr128h)) * 0.125f + mk1;
        }

        float tg = -1e30f, th = -1e30f;
        #pragma unroll
        for (int nt = 0; nt < 8; nt++) {
            tg = fmaxf(tg, fmaxf(s[nt][0], s[nt][1]));
            th = fmaxf(th, fmaxf(s[nt][2], s[nt][3]));
        }
        tg = quadmax(tg); th = quadmax(th);
        float mng = fmaxf(m_g, tg), mnh = fmaxf(m_h, th);
        float scg = __expf(m_g - mng), sch = __expf(m_h - mnh);
        if (scg < 1.0f) {
            #pragma unroll
            for (int nt = 0; nt < 8; nt++) { acc[nt][0] *= scg; acc[nt][1] *= scg; }
            l_g *= scg; lo_g *= scg; hi_g *= scg;
        }
        if (sch < 1.0f) {
            #pragma unroll
            for (int nt = 0; nt < 8; nt++) { acc[nt][2] *= sch; acc[nt][3] *= sch; }
            l_h *= sch; lo_h *= sch; hi_h *= sch;
        }
        m_g = mng; m_h = mnh;

        unsigned phi[4][4], plo[4][4];
        #pragma unroll
        for (int nt = 0; nt < 8; nt++) {
            int k = kt0 + nt * 8 + tq;
            float p0 = __expf(s[nt][0] - m_g), p1 = __expf(s[nt][1] - m_g);
            float p2 = __expf(s[nt][2] - m_h), p3 = __expf(s[nt][3] - m_h);
            l_g += p0 + p1; l_h += p2 + p3;
            int d0 = k - qg, d1 = k + 1 - qg;
            if (d0 <= -64) lo_g += p0; else if (d0 >= 64) hi_g += p0;
            if (d1 <= -64) lo_g += p1; else if (d1 >= 64) hi_g += p1;
            int e0 = k - qh2, e1 = k + 1 - qh2;
            if (e0 <= -64) lo_h += p2; else if (e0 >= 64) hi_h += p2;
            if (e1 <= -64) lo_h += p3; else if (e1 >= 64) hi_h += p3;
            int kb = nt >> 1;
            if ((nt & 1) == 0) {
                phi[kb][0] = pack2h_f16(p0, p1); phi[kb][1] = pack2h_f16(p2, p3);
                plo[kb][0] = pack2l_f16(p0, p1); plo[kb][1] = pack2l_f16(p2, p3);
            } else {
                phi[kb][2] = pack2h_f16(p0, p1); phi[kb][3] = pack2h_f16(p2, p3);
                plo[kb][2] = pack2l_f16(p0, p1); plo[kb][3] = pack2l_f16(p2, p3);
            }
        }

        #pragma unroll
        for (int kb = 0; kb < 4; kb++) {
            int kk = kb * 16;
            #pragma unroll
            for (int ntp = 0; ntp < 4; ntp++) {
                int bb = (ntp * 16 + brow) * SST2 + kk + bcol8;
                unsigned vh[4];
                ldsm4(vh, sVhi + bb);
                mma_f16(acc[2 * ntp],     phi[kb], vh[0], vh[1]);
                mma_f16(acc[2 * ntp],     plo[kb], vh[0], vh[1]);
                mma_f16(acc[2 * ntp + 1], phi[kb], vh[2], vh[3]);
                mma_f16(acc[2 * ntp + 1], plo[kb], vh[2], vh[3]);
            }
        }
        __syncthreads();
    }

    l_g = quadsum(l_g); l_h = quadsum(l_h);
    lo_g = quadsum(lo_g); lo_h = quadsum(lo_h);
    hi_g = quadsum(hi_g); hi_h = quadsum(hi_h);
    if ((lane & 3) == 0) {
        prowg[0] = lo_g; prowg[128] = hi_g;
        prowh[0] = lo_h; prowh[128] = hi_h;
    }
    {
        int c0 = (lane & 3) * 33; if (c0 == 0) c0 = 1;
        int c1 = (lane & 3) * 33 + 33; if (c1 > 128) c1 = 128;
        for (int c = c0; c < c1; c++) {
            int kg = qg + c - 64;
            int kh2 = qh2 + c - 64;
            prowg[c] = (kg >= 0 && kg < SEQ) ? __expf(prowg[c] - m_g) : 0.0f;
            prowh[c] = (kh2 >= 0 && kh2 < SEQ) ? __expf(prowh[c] - m_h) : 0.0f;
        }
    }
    __syncthreads();

    float* tabS = (float*)(dsmh + 2 * FA_QAS);
    for (int r0 = 0; r0 < VOCAB; r0 += 16) {
        __syncthreads();
        {
            int rr = t >> 4, cc = (t & 15) * 4;
            int r = r0 + rr;
            float4 tv = (r < VOCAB) ? *(const float4*)&g_tab[r * 64 + cc]
                                    : make_float4(0.f, 0.f, 0.f, 0.f);
            *(float4*)&tabS[rr * 68 + cc] = tv;
        }
        __syncthreads();
        #pragma unroll
        for (int rc = 0; rc < 16; rc++) {
            int rr2 = r0 + rc; if (rr2 > 128) rr2 = 128;
            float pg = prowg[rr2];
            float ph = prowh[rr2];
            #pragma unroll
            for (int nt = 0; nt < 8; nt++) {
                int d = nt * 8 + tq;
                float t0 = tabS[rc * 68 + d], t1 = tabS[rc * 68 + d + 1];
                acc[nt][0] += pg * t0; acc[nt][1] += pg * t1;
                acc[nt][2] += ph * t0; acc[nt][3] += ph * t1;
            }
        }
    }

    float ig = 1.0f / l_g, ih = 1.0f / l_h;
    #pragma unroll
    for (int nt = 0; nt < 8; nt++) {
        int d = nt * 8 + tq;
        *(float2*)(out + ((size_t)(b * SEQ + qg)) * HID + h * 64 + d) =
            make_float2(acc[nt][0] * ig, acc[nt][1] * ig);
        *(float2*)(out + ((size_t)(b * SEQ + qh2)) * HID + h * 64 + d) =
            make_float2(acc[nt][2] * ih, acc[nt][3] * ih);
    }
}

// ---------------- launcher ----------------
extern "C" void kernel_launch(void* const* d_in, const int* in_sizes, int n_in,
                              void* d_out, int out_size) {
    const float* hs   = (const float*)d_in[0];
    const float* mask = (const float*)d_in[1];
    const float* Wq   = (const float*)d_in[2];
    const float* bq   = (const float*)d_in[3];
    const float* Wk   = (const float*)d_in[4];
    const float* bk   = (const float*)d_in[5];
    const float* Wv   = (const float*)d_in[6];
    const float* bv   = (const float*)d_in[7];
    float* out = (float*)d_out;

    cudaFuncSetAttribute(qkv_mma_kernel,    cudaFuncAttributeMaxDynamicSharedMemorySize, QKV_SMEM);
    cudaFuncSetAttribute(attn_fused_kernel, cudaFuncAttributeMaxDynamicSharedMemorySize, FA_SMEM);

    prep_kernel<<<HS_BLKS + W_BLKS + TAB_BLKS, 256>>>(hs, Wq, Wk, Wv);
    qkv_mma_kernel<<<dim3(HID / 128, (BATCH * SEQ) / 128, 3), 256, QKV_SMEM>>>(bq, bk, bv);
    attn_fused_kernel<<<dim3(SEQ / 128, BH), 256, FA_SMEM>>>(mask, out);
}